// round 6
// baseline (speedup 1.0000x reference)
#include <cuda_runtime.h>
#include <cuda_bf16.h>

#define NN 50000
#define EE 800000
#define CC 64
#define MCC 128
#define NPAD 50048

typedef unsigned long long ull;

// ---------------- device scratch ----------------
__device__ __align__(16) float g_feat[NN * CC];
__device__ __align__(16) float g_agg[NN * MCC];
__device__ __align__(16) float g_deg[NN];
__device__ __align__(16) float g_gsum[CC];
__device__ __align__(16) float g_gctx[CC];
__device__ __align__(16) float g_misc[4];          // u0,u1,u2, tanh(res_scale)
__device__ __align__(16) float g_W1a[CC * MCC];
__device__ __align__(16) float g_W1b[CC * MCC];
__device__ __align__(16) float g_P[NPAD * MCC];
__device__ __align__(16) float g_Q[NPAD * MCC];
__device__ __align__(16) float g_ub1eff[MCC];
__device__ __align__(16) float g_zeros[MCC];
// mma.sync B fragments: [mat][ (s*16 + jg)*32 + lane ] = {bh0, bh1, bl0, bl1}
__device__ __align__(16) uint4 g_wfrag[3][4096];

// ---------------- f32x2 packed math (SIMT GEMMs) ----------------
__device__ __forceinline__ ull pack2(float lo, float hi) {
    ull r; asm("mov.b64 %0, {%1, %2};" : "=l"(r) : "f"(lo), "f"(hi)); return r;
}
__device__ __forceinline__ void fma2(ull& d, ull a, ull b) {
    asm("fma.rn.f32x2 %0, %1, %2, %0;" : "+l"(d) : "l"(a), "l"(b));
}
__device__ __forceinline__ float2 unpack2(ull v) {
    float2 f; asm("mov.b64 {%0, %1}, %2;" : "=f"(f.x), "=f"(f.y) : "l"(v)); return f;
}
__device__ __forceinline__ float gelu_exact(float x) {
    return 0.5f * x * (1.0f + erff(x * 0.7071067811865476f));
}
__device__ __forceinline__ void split2(float a, float b, unsigned& hi, unsigned& lo) {
    __nv_bfloat162 h = __floats2bfloat162_rn(a, b);
    float ra = a - __bfloat162float(h.x);
    float rb = b - __bfloat162float(h.y);
    __nv_bfloat162 l = __floats2bfloat162_rn(ra, rb);
    hi = *(unsigned*)&h;
    lo = *(unsigned*)&l;
}

#define MMA_BF16(c, a0, a1, a2, a3, b0, b1) \
    asm volatile( \
        "mma.sync.aligned.m16n8k16.row.col.f32.bf16.bf16.f32 " \
        "{%0,%1,%2,%3}, {%4,%5,%6,%7}, {%8,%9}, {%0,%1,%2,%3};" \
        : "+f"((c)[0]), "+f"((c)[1]), "+f"((c)[2]), "+f"((c)[3]) \
        : "r"(a0), "r"(a1), "r"(a2), "r"(a3), "r"(b0), "r"(b1))

// ---------------- zero scratch ----------------
__global__ void k_zero() {
    int i = blockIdx.x * blockDim.x + threadIdx.x;
    int stride = gridDim.x * blockDim.x;
    float4 z = make_float4(0.f, 0.f, 0.f, 0.f);
    for (int j = i; j < NN * MCC / 4; j += stride) ((float4*)g_agg)[j] = z;
    for (int j = i; j < NN; j += stride) g_deg[j] = 0.f;
    if (i < CC) g_gsum[i] = 0.f;
    if (i < MCC) g_zeros[i] = 0.f;
}

// ---------------- weight prep ----------------
__global__ void k_prep(const float* __restrict__ ew1) {
    int i = blockIdx.x * blockDim.x + threadIdx.x;
    int stride = gridDim.x * blockDim.x;
    for (int j = i; j < CC * MCC; j += stride) {
        float wc = ew1[2 * CC * MCC + j];
        g_W1a[j] = ew1[j] + wc;
        g_W1b[j] = ew1[CC * MCC + j] - wc;
    }
}

// mma B-fragment pack for ew2, ew3, gw1 (bf16 hi/lo split)
__global__ void k_prep_w(const float* __restrict__ ew2,
                         const float* __restrict__ ew3,
                         const float* __restrict__ gw1) {
    int m = blockIdx.y;
    const float* W = (m == 0) ? ew2 : (m == 1) ? ew3 : gw1;
    int idx = blockIdx.x * blockDim.x + threadIdx.x;
    if (idx >= 4096) return;
    int lane = idx & 31;
    int jg = (idx >> 5) & 15;
    int s = idx >> 9;
    int n = jg * 8 + (lane >> 2);
    int k = s * 16 + (lane & 3) * 2;
    float w00 = W[k * 128 + n],       w01 = W[(k + 1) * 128 + n];
    float w80 = W[(k + 8) * 128 + n], w81 = W[(k + 9) * 128 + n];
    unsigned h0, l0, h8, l8;
    split2(w00, w01, h0, l0);
    split2(w80, w81, h8, l8);
    g_wfrag[m][idx] = make_uint4(h0, h8, l0, l8);
}

// ---------------- layernorm + global column-sum partials ----------------
__global__ void k_lnorm(const float* __restrict__ h,
                        const float* __restrict__ lng,
                        const float* __restrict__ lnb) {
    __shared__ float cs[CC];
    int tid = threadIdx.x, lane = tid & 31, w = tid >> 5;
    int n = blockIdx.x * 4 + w;
    float2 v = ((const float2*)h)[n * 32 + lane];
    float s = v.x + v.y, q = v.x * v.x + v.y * v.y;
#pragma unroll
    for (int o = 16; o; o >>= 1) {
        s += __shfl_xor_sync(~0u, s, o);
        q += __shfl_xor_sync(~0u, q, o);
    }
    float mu = s * (1.f / 64.f);
    float var = q * (1.f / 64.f) - mu * mu;
    float rstd = rsqrtf(var + 1e-5f);
    float f0 = (v.x - mu) * rstd * lng[2 * lane] + lnb[2 * lane];
    float f1 = (v.y - mu) * rstd * lng[2 * lane + 1] + lnb[2 * lane + 1];
    ((float2*)g_feat)[n * 32 + lane] = make_float2(f0, f1);
    if (tid < CC) cs[tid] = 0.f;
    __syncthreads();
    atomicAdd(&cs[2 * lane], f0);
    atomicAdd(&cs[2 * lane + 1], f1);
    __syncthreads();
    if (tid < CC) atomicAdd(&g_gsum[tid], cs[tid]);
}

// ---------------- tiny global MLP + misc + effective update bias ----------------
__global__ void k_global(const float* __restrict__ fdir,
                         const float* glw1, const float* glb1,
                         const float* glw2, const float* glb2,
                         const float* glw3, const float* glb3,
                         const float* res_scale,
                         const float* ub1, const float* uw1) {
    __shared__ float a0[CC], a1[CC], a2[CC];
    int t = threadIdx.x;
    if (t < CC) a0[t] = g_gsum[t] * (1.f / (float)NN);
    __syncthreads();
    if (t < CC) {
        float acc = glb1[t];
        for (int k = 0; k < CC; k++) acc += a0[k] * glw1[k * CC + t];
        a1[t] = gelu_exact(acc);
    }
    __syncthreads();
    if (t < CC) {
        float acc = glb2[t];
        for (int k = 0; k < CC; k++) acc += a1[k] * glw2[k * CC + t];
        a2[t] = gelu_exact(acc);
    }
    __syncthreads();
    if (t < CC) {
        float acc = glb3[t];
        for (int k = 0; k < CC; k++) acc += a2[k] * glw3[k * CC + t];
        g_gctx[t] = acc;
        a0[t] = acc;
    }
    __syncthreads();
    for (int c = t; c < MCC; c += CC) {
        float acc = ub1[c];
        for (int k = 0; k < CC; k++) acc += a0[k] * uw1[(192 + k) * MCC + c];
        g_ub1eff[c] = acc;
    }
    if (t == 0) {
        float u0 = fdir[0], u1 = fdir[1], u2 = fdir[2];
        float inv = 1.f / (sqrtf(u0 * u0 + u1 * u1 + u2 * u2) + 1e-8f);
        g_misc[0] = u0 * inv; g_misc[1] = u1 * inv; g_misc[2] = u2 * inv;
        g_misc[3] = tanhf(res_scale[0]);
    }
}

// ---------------- f32x2 tiled GEMM (k_pq / k_update) ----------------
template <int NOUT, bool DOGELU>
__device__ __forceinline__ void tile_gemm(const float* __restrict__ A, int sA, int K,
                                          const float* __restrict__ W,
                                          const float* __restrict__ bias,
                                          float* __restrict__ Ws,
                                          float* __restrict__ Out, int sO, int tid) {
    constexpr int GROUPS = NOUT / 64;
    const int tx = tid & 15, ty = tid >> 4;
    ull acc[4][GROUPS][2];
#pragma unroll
    for (int r = 0; r < 4; r++)
#pragma unroll
        for (int g = 0; g < GROUPS; g++) { acc[r][g][0] = 0ULL; acc[r][g][1] = 0ULL; }

    const float* Ar0 = A + (ty * 4) * sA;
    for (int k0 = 0; k0 < K; k0 += 32) {
        int kc = K - k0; if (kc > 32) kc = 32;
        __syncthreads();
        {
            const float4* src = (const float4*)(W + k0 * NOUT);
            float4* dst = (float4*)Ws;
            int tot = kc * (NOUT / 4);
            for (int i = tid; i < tot; i += 256) dst[i] = src[i];
        }
        __syncthreads();
#pragma unroll
        for (int kq = 0; kq < 8; kq++) {
            if (kq * 4 >= kc) break;
            float4 av[4];
#pragma unroll
            for (int r = 0; r < 4; r++)
                av[r] = *(const float4*)(Ar0 + r * sA + k0 + kq * 4);
#pragma unroll
            for (int j = 0; j < 4; j++) {
                const float* wr = Ws + (kq * 4 + j) * NOUT + 4 * tx;
                ulonglong2 bq[GROUPS];
#pragma unroll
                for (int g = 0; g < GROUPS; g++)
                    bq[g] = *(const ulonglong2*)(wr + 64 * g);
#pragma unroll
                for (int r = 0; r < 4; r++) {
                    float a = ((const float*)&av[r])[j];
                    ull aa = pack2(a, a);
#pragma unroll
                    for (int g = 0; g < GROUPS; g++) {
                        fma2(acc[r][g][0], aa, bq[g].x);
                        fma2(acc[r][g][1], aa, bq[g].y);
                    }
                }
            }
        }
    }
#pragma unroll
    for (int r = 0; r < 4; r++) {
        float* orow = Out + (ty * 4 + r) * sO;
#pragma unroll
        for (int g = 0; g < GROUPS; g++) {
            int col = 64 * g + 4 * tx;
            float2 v0 = unpack2(acc[r][g][0]);
            float2 v1 = unpack2(acc[r][g][1]);
            float4 o;
            o.x = v0.x + bias[col];
            o.y = v0.y + bias[col + 1];
            o.z = v1.x + bias[col + 2];
            o.w = v1.y + bias[col + 3];
            if (DOGELU) {
                o.x = gelu_exact(o.x); o.y = gelu_exact(o.y);
                o.z = gelu_exact(o.z); o.w = gelu_exact(o.w);
            }
            *(float4*)(orow + col) = o;
        }
    }
}

// ---------------- P/Q node GEMMs ----------------
__global__ void __launch_bounds__(256, 2) k_pq() {
    __shared__ float At[64 * 68];
    __shared__ float Ws[32 * 128];
    int tid = threadIdx.x;
    int n0 = blockIdx.x * 64;
    for (int idx = tid; idx < 64 * 64; idx += 256) {
        int e = idx >> 6, c = idx & 63;
        int n = n0 + e; if (n >= NN) n = NN - 1;
        At[e * 68 + c] = g_feat[n * 64 + c];
    }
    tile_gemm<128, false>(At, 68, 64, g_W1a, g_zeros, Ws, g_P + n0 * MCC, MCC, tid);
    tile_gemm<128, false>(At, 68, 64, g_W1b, g_zeros, Ws, g_Q + n0 * MCC, MCC, tid);
}

// ---------------- edge kernel: mma.sync bf16-split, 128-edge tiles ----------------
#define ASTRIDE 272
#define SB_AH   0
#define SB_AL   34816
#define SB_GEO  69632
#define SB_GP   71680
#define SB_GATE 72704
#define SB_EB2  73216
#define SB_EB3  73728
#define SB_GB1  74240
#define SB_GW2  74752
#define SB_EB1  75264
#define SB_WD   75776
#define SB_RS   77824
#define SB_CS   78336
#define SB_EDGE_BYTES 78848

// one 128x128 GEMM pass: 16 warps, warp (r=wid&7, ch=wid>>3)
__device__ __forceinline__ void mma_pass(const char* sm, const uint4* __restrict__ Wf,
                                         float acc[8][4], int wid, int lane) {
    const int r = wid & 7, ch = wid >> 3;
    const int g = lane >> 2, t = lane & 3;
    const char* Ah = sm + SB_AH;
    const char* Al = sm + SB_AL;
    const int ro0 = (r * 16 + g) * ASTRIDE;
    const int ro1 = ro0 + 8 * ASTRIDE;
#pragma unroll
    for (int s = 0; s < 8; s++) {
        const int cb = s * 32 + 4 * t;
        unsigned ah0 = *(const unsigned*)(Ah + ro0 + cb);
        unsigned ah1 = *(const unsigned*)(Ah + ro1 + cb);
        unsigned ah2 = *(const unsigned*)(Ah + ro0 + cb + 16);
        unsigned ah3 = *(const unsigned*)(Ah + ro1 + cb + 16);
        unsigned al0 = *(const unsigned*)(Al + ro0 + cb);
        unsigned al1 = *(const unsigned*)(Al + ro1 + cb);
        unsigned al2 = *(const unsigned*)(Al + ro0 + cb + 16);
        unsigned al3 = *(const unsigned*)(Al + ro1 + cb + 16);
        const uint4* wp = Wf + (s * 16 + ch * 8) * 32 + lane;
#pragma unroll
        for (int j = 0; j < 8; j++) {
            uint4 w = __ldg(wp + j * 32);
            MMA_BF16(acc[j], ah0, ah1, ah2, ah3, w.x, w.y);
            MMA_BF16(acc[j], ah0, ah1, ah2, ah3, w.z, w.w);
            MMA_BF16(acc[j], al0, al1, al2, al3, w.x, w.y);
        }
    }
}

__global__ void __launch_bounds__(512, 1) k_edge(
    const int* __restrict__ ei, const float* __restrict__ coords,
    const float* __restrict__ ew1, const float* __restrict__ eb1,
    const float* __restrict__ eb2, const float* __restrict__ eb3,
    const float* __restrict__ gb1, const float* __restrict__ gw2,
    const float* __restrict__ gb2) {
    extern __shared__ char sm[];
    char* Ah    = sm + SB_AH;
    char* Al    = sm + SB_AL;
    float* geo  = (float*)(sm + SB_GEO);
    float* gp   = (float*)(sm + SB_GP);
    float* gateS = (float*)(sm + SB_GATE);
    float* eb2s = (float*)(sm + SB_EB2);
    float* eb3s = (float*)(sm + SB_EB3);
    float* gb1s = (float*)(sm + SB_GB1);
    float* gw2s = (float*)(sm + SB_GW2);
    float* eb1s = (float*)(sm + SB_EB1);
    float* Wd   = (float*)(sm + SB_WD);
    int* rs = (int*)(sm + SB_RS);
    int* cs = (int*)(sm + SB_CS);

    const int tid = threadIdx.x;
    const int wid = tid >> 5, lane = tid & 31;
    const int e0 = blockIdx.x * 128;

    if (tid < 128) {
        rs[tid] = ei[e0 + tid];
        cs[tid] = ei[EE + e0 + tid];
        eb2s[tid] = eb2[tid];
        eb3s[tid] = eb3[tid];
        gb1s[tid] = gb1[tid];
        gw2s[tid] = gw2[tid];
        eb1s[tid] = eb1[tid];
    }
    for (int i = tid; i < 4 * 128; i += 512) Wd[i] = ew1[192 * 128 + i];
    __syncthreads();

    if (tid < 128) {
        int e = tid, r = rs[e], c = cs[e];
        float xi0 = coords[r * 3], xi1 = coords[r * 3 + 1], xi2 = coords[r * 3 + 2];
        float xj0 = coords[c * 3], xj1 = coords[c * 3 + 1], xj2 = coords[c * 3 + 2];
        float r0 = xi0 - xj0, r1 = xi1 - xj1, r2 = xi2 - xj2;
        float u0 = g_misc[0], u1 = g_misc[1], u2 = g_misc[2];
        geo[e * 4 + 0] = r0 * r0 + r1 * r1 + r2 * r2;
        geo[e * 4 + 1] = xi0 * u0 + xi1 * u1 + xi2 * u2;
        geo[e * 4 + 2] = xj0 * u0 + xj1 * u1 + xj2 * u2;
        geo[e * 4 + 3] = r0 * u0 + r1 * u1 + r2 * u2;
    }
    __syncthreads();

    // ---- build H1 = gelu(P[row] + Q[col] + geo@Wd + eb1) -> Ah/Al ----
    for (int idx = tid; idx < 128 * 16; idx += 512) {
        int e = idx >> 4, c0 = (idx & 15) * 8;
        const float* Pr = g_P + rs[e] * MCC + c0;
        const float* Qr = g_Q + cs[e] * MCC + c0;
        float4 p0 = *(const float4*)Pr, p1 = *(const float4*)(Pr + 4);
        float4 q0 = *(const float4*)Qr, q1 = *(const float4*)(Qr + 4);
        float ge0 = geo[e * 4], ge1 = geo[e * 4 + 1], ge2 = geo[e * 4 + 2], ge3 = geo[e * 4 + 3];
        float h[8];
#pragma unroll
        for (int j = 0; j < 8; j++) {
            int c = c0 + j;
            float pq = (j < 4) ? ((const float*)&p0)[j] + ((const float*)&q0)[j]
                               : ((const float*)&p1)[j - 4] + ((const float*)&q1)[j - 4];
            float v = pq + ge0 * Wd[c] + ge1 * Wd[128 + c] + ge2 * Wd[256 + c]
                    + ge3 * Wd[384 + c] + eb1s[c];
            h[j] = gelu_exact(v);
        }
        unsigned hi[4], lo[4];
#pragma unroll
        for (int j = 0; j < 4; j++) split2(h[2 * j], h[2 * j + 1], hi[j], lo[j]);
        *(uint4*)(Ah + e * ASTRIDE + c0 * 2) = make_uint4(hi[0], hi[1], hi[2], hi[3]);
        *(uint4*)(Al + e * ASTRIDE + c0 * 2) = make_uint4(lo[0], lo[1], lo[2], lo[3]);
    }
    __syncthreads();

    const int r = wid & 7, ch = wid >> 3;
    const int g = lane >> 2, t = lane & 3;
    const int R0 = r * 16 + g, R1 = R0 + 8;

    // ---- GEMM1: H2 = gelu(H1 @ ew2 + eb2) ----
    {
        float acc[8][4];
#pragma unroll
        for (int j = 0; j < 8; j++)
#pragma unroll
            for (int q = 0; q < 4; q++) acc[j][q] = 0.f;
        mma_pass(sm, g_wfrag[0], acc, wid, lane);
        __syncthreads();
#pragma unroll
        for (int j = 0; j < 8; j++) {
            int col = ch * 64 + j * 8 + 2 * t;
            float x0 = gelu_exact(acc[j][0] + eb2s[col]);
            float x1 = gelu_exact(acc[j][1] + eb2s[col + 1]);
            float x2 = gelu_exact(acc[j][2] + eb2s[col]);
            float x3 = gelu_exact(acc[j][3] + eb2s[col + 1]);
            unsigned hi, lo;
            split2(x0, x1, hi, lo);
            *(unsigned*)(Ah + R0 * ASTRIDE + col * 2) = hi;
            *(unsigned*)(Al + R0 * ASTRIDE + col * 2) = lo;
            split2(x2, x3, hi, lo);
            *(unsigned*)(Ah + R1 * ASTRIDE + col * 2) = hi;
            *(unsigned*)(Al + R1 * ASTRIDE + col * 2) = lo;
        }
        __syncthreads();
    }

    // ---- GEMM2: hidden = H2 @ ew3 + eb3 -> split to Ah/Al ----
    {
        float acc[8][4];
#pragma unroll
        for (int j = 0; j < 8; j++)
#pragma unroll
            for (int q = 0; q < 4; q++) acc[j][q] = 0.f;
        mma_pass(sm, g_wfrag[1], acc, wid, lane);
        __syncthreads();
#pragma unroll
        for (int j = 0; j < 8; j++) {
            int col = ch * 64 + j * 8 + 2 * t;
            float x0 = acc[j][0] + eb3s[col];
            float x1 = acc[j][1] + eb3s[col + 1];
            float x2 = acc[j][2] + eb3s[col];
            float x3 = acc[j][3] + eb3s[col + 1];
            unsigned hi, lo;
            split2(x0, x1, hi, lo);
            *(unsigned*)(Ah + R0 * ASTRIDE + col * 2) = hi;
            *(unsigned*)(Al + R0 * ASTRIDE + col * 2) = lo;
            split2(x2, x3, hi, lo);
            *(unsigned*)(Ah + R1 * ASTRIDE + col * 2) = hi;
            *(unsigned*)(Al + R1 * ASTRIDE + col * 2) = lo;
        }
        __syncthreads();
    }

    // ---- GEMM3: gate hidden = hidden @ gw1 + gb1 -> gelu -> dot gw2 ----
    {
        float acc[8][4];
#pragma unroll
        for (int j = 0; j < 8; j++)
#pragma unroll
            for (int q = 0; q < 4; q++) acc[j][q] = 0.f;
        mma_pass(sm, g_wfrag[2], acc, wid, lane);
        float p0 = 0.f, p1 = 0.f;
#pragma unroll
        for (int j = 0; j < 8; j++) {
            int col = ch * 64 + j * 8 + 2 * t;
            p0 += gw2s[col] * gelu_exact(acc[j][0] + gb1s[col])
                + gw2s[col + 1] * gelu_exact(acc[j][1] + gb1s[col + 1]);
            p1 += gw2s[col] * gelu_exact(acc[j][2] + gb1s[col])
                + gw2s[col + 1] * gelu_exact(acc[j][3] + gb1s[col + 1]);
        }
        p0 += __shfl_xor_sync(~0u, p0, 1);
        p0 += __shfl_xor_sync(~0u, p0, 2);
        p1 += __shfl_xor_sync(~0u, p1, 1);
        p1 += __shfl_xor_sync(~0u, p1, 2);
        if (t == 0) {
            gp[ch * 128 + R0] = p0;
            gp[ch * 128 + R1] = p1;
        }
        __syncthreads();
        if (tid < 128) {
            float a = gp[tid] + gp[128 + tid] + gb2[0];
            gateS[tid] = 1.f / (1.f + expf(-a));
        }
        __syncthreads();
    }

    // ---- scatter msg = gate * (hi + lo), vector red.add.v4.f32 ----
    for (int idx = tid; idx < 128 * 32; idx += 512) {
        int e = idx >> 5, c = (idx & 31) * 4;
        uint2 hu = *(const uint2*)(Ah + e * ASTRIDE + c * 2);
        uint2 lu = *(const uint2*)(Al + e * ASTRIDE + c * 2);
        float2 h0 = __bfloat1622float2(*(__nv_bfloat162*)&hu.x);
        float2 h1 = __bfloat1622float2(*(__nv_bfloat162*)&hu.y);
        float2 l0 = __bfloat1622float2(*(__nv_bfloat162*)&lu.x);
        float2 l1 = __bfloat1622float2(*(__nv_bfloat162*)&lu.y);
        float gt = gateS[e];
        float v0 = gt * (h0.x + l0.x);
        float v1 = gt * (h0.y + l0.y);
        float v2 = gt * (h1.x + l1.x);
        float v3 = gt * (h1.y + l1.y);
        float* dst = g_agg + (size_t)rs[e] * MCC + c;
        asm volatile("red.global.add.v4.f32 [%0], {%1, %2, %3, %4};"
                     :: "l"(dst), "f"(v0), "f"(v1), "f"(v2), "f"(v3) : "memory");
    }
    if (tid < 128) atomicAdd(&g_deg[rs[tid]], 1.f);
}

// ---------------- node update kernel ----------------
#define SMU_UN 0
#define SMU_B1 12544
#define SMU_WS 20992
#define SMU_DG 25088
#define SMU_UPD_FLOATS 25152

__global__ void __launch_bounds__(256, 2) k_update(
    const float* uw1, const float* uw2, const float* ub2,
    const float* uw3, const float* ub3, float* __restrict__ out) {
    extern __shared__ float smf[];
    float* Un = smf + SMU_UN;
    float* B1 = smf + SMU_B1;
    float* Ws = smf + SMU_WS;
    float* dg = smf + SMU_DG;
    int tid = threadIdx.x;
    int n0 = blockIdx.x * 64;

    if (tid < 64) {
        int n = n0 + tid; if (n >= NN) n = NN - 1;
        float d = g_deg[n]; if (d < 1.f) d = 1.f;
        dg[tid] = 1.f / d;
    }
    __syncthreads();
    for (int idx = tid; idx < 64 * 64; idx += 256) {
        int e = idx >> 6, c = idx & 63;
        int n = n0 + e; if (n >= NN) n = NN - 1;
        Un[e * 196 + c] = g_feat[n * 64 + c];
    }
    for (int idx = tid; idx < 64 * 128; idx += 256) {
        int e = idx >> 7, c = idx & 127;
        int n = n0 + e; if (n >= NN) n = NN - 1;
        Un[e * 196 + 64 + c] = g_agg[n * 128 + c] * dg[e];
    }
    __syncthreads();

    tile_gemm<128, true >(Un, 196, 192, uw1, g_ub1eff, Ws, B1, 132, tid);
    tile_gemm<128, true >(B1, 132, 128, uw2, ub2, Ws, Un, 132, tid);
    tile_gemm<64,  false>(Un, 132, 128, uw3, ub3, Ws, B1, 68, tid);
    __syncthreads();

    float ts = g_misc[3];
    for (int idx = tid; idx < 64 * 64; idx += 256) {
        int e = idx >> 6, c = idx & 63;
        int n = n0 + e;
        if (n < NN) out[n * 64 + c] = ts * B1[e * 68 + c];
    }
}

// ---------------- launch ----------------
extern "C" void kernel_launch(void* const* d_in, const int* in_sizes, int n_in,
                              void* d_out, int out_size) {
    const float* coords   = (const float*)d_in[0];
    const float* h        = (const float*)d_in[1];
    const float* fdir     = (const float*)d_in[2];
    const int*   ei       = (const int*)d_in[3];
    const float* ln_g     = (const float*)d_in[4];
    const float* ln_b     = (const float*)d_in[5];
    const float* ew1      = (const float*)d_in[6];
    const float* eb1      = (const float*)d_in[7];
    const float* ew2      = (const float*)d_in[8];
    const float* eb2      = (const float*)d_in[9];
    const float* ew3      = (const float*)d_in[10];
    const float* eb3      = (const float*)d_in[11];
    const float* gw1      = (const float*)d_in[12];
    const float* gb1      = (const float*)d_in[13];
    const float* gw2      = (const float*)d_in[14];
    const float* gb2      = (const float*)d_in[15];
    const float* glw1     = (const float*)d_in[16];
    const float* glb1     = (const float*)d_in[17];
    const float* glw2     = (const float*)d_in[18];
    const float* glb2     = (const float*)d_in[19];
    const float* glw3     = (const float*)d_in[20];
    const float* glb3     = (const float*)d_in[21];
    const float* uw1      = (const float*)d_in[22];
    const float* ub1      = (const float*)d_in[23];
    const float* uw2      = (const float*)d_in[24];
    const float* ub2      = (const float*)d_in[25];
    const float* uw3      = (const float*)d_in[26];
    const float* ub3      = (const float*)d_in[27];
    const float* rscale   = (const float*)d_in[28];
    float* out = (float*)d_out;

    cudaFuncSetAttribute(k_edge, cudaFuncAttributeMaxDynamicSharedMemorySize,
                         SB_EDGE_BYTES);
    cudaFuncSetAttribute(k_update, cudaFuncAttributeMaxDynamicSharedMemorySize,
                         SMU_UPD_FLOATS * 4);

    k_zero<<<2048, 256>>>();
    k_prep<<<32, 256>>>(ew1);
    {
        dim3 gdim(16, 3);
        k_prep_w<<<gdim, 256>>>(ew2, ew3, gw1);
    }
    k_lnorm<<<NN / 4, 128>>>(h, ln_g, ln_b);
    k_global<<<1, 64>>>(fdir, glw1, glb1, glw2, glb2, glw3, glb3, rscale, ub1, uw1);
    k_pq<<<(NN + 63) / 64, 256>>>();
    k_edge<<<EE / 128, 512, SB_EDGE_BYTES>>>(ei, coords,
        ew1, eb1, eb2, eb3, gb1, gw2, gb2);
    k_update<<<(NN + 63) / 64, 256, SMU_UPD_FLOATS * 4>>>(
        uw1, uw2, ub2, uw3, ub3, out);
}

// round 8
// speedup vs baseline: 1.1259x; 1.1259x over previous
#include <cuda_runtime.h>
#include <cuda_bf16.h>

#define NN 50000
#define EE 800000
#define CC 64
#define MCC 128
#define NPAD 50048

typedef unsigned long long ull;

// ---------------- device scratch ----------------
__device__ __align__(16) float g_feat[NN * CC];
__device__ __align__(16) float g_agg[NN * MCC];
__device__ __align__(16) float g_deg[NN];
__device__ __align__(16) float g_gsum[CC];
__device__ __align__(16) float g_gctx[CC];
__device__ __align__(16) float g_misc[4];          // u0,u1,u2, tanh(res_scale)
__device__ __align__(16) float g_W1a[CC * MCC];
__device__ __align__(16) float g_W1b[CC * MCC];
__device__ __align__(16) float g_P[NPAD * MCC];
__device__ __align__(16) float g_Q[NPAD * MCC];
__device__ __align__(16) float g_ub1eff[MCC];
__device__ __align__(16) float g_zeros[MCC];
// mma.sync B fragments: [mat][ (s*16 + jg)*32 + lane ] = {bh0, bh1, bl0, bl1}
__device__ __align__(16) uint4 g_wfrag[3][4096];

// ---------------- f32x2 packed math (SIMT GEMMs) ----------------
__device__ __forceinline__ ull pack2(float lo, float hi) {
    ull r; asm("mov.b64 %0, {%1, %2};" : "=l"(r) : "f"(lo), "f"(hi)); return r;
}
__device__ __forceinline__ void fma2(ull& d, ull a, ull b) {
    asm("fma.rn.f32x2 %0, %1, %2, %0;" : "+l"(d) : "l"(a), "l"(b));
}
__device__ __forceinline__ float2 unpack2(ull v) {
    float2 f; asm("mov.b64 {%0, %1}, %2;" : "=f"(f.x), "=f"(f.y) : "l"(v)); return f;
}
__device__ __forceinline__ float gelu_exact(float x) {
    return 0.5f * x * (1.0f + erff(x * 0.7071067811865476f));
}
__device__ __forceinline__ void split2(float a, float b, unsigned& hi, unsigned& lo) {
    __nv_bfloat162 h = __floats2bfloat162_rn(a, b);
    float ra = a - __bfloat162float(h.x);
    float rb = b - __bfloat162float(h.y);
    __nv_bfloat162 l = __floats2bfloat162_rn(ra, rb);
    hi = *(unsigned*)&h;
    lo = *(unsigned*)&l;
}

#define MMA_BF16(c, a0, a1, a2, a3, b0, b1) \
    asm volatile( \
        "mma.sync.aligned.m16n8k16.row.col.f32.bf16.bf16.f32 " \
        "{%0,%1,%2,%3}, {%4,%5,%6,%7}, {%8,%9}, {%0,%1,%2,%3};" \
        : "+f"((c)[0]), "+f"((c)[1]), "+f"((c)[2]), "+f"((c)[3]) \
        : "r"(a0), "r"(a1), "r"(a2), "r"(a3), "r"(b0), "r"(b1))

// ---------------- zero scratch ----------------
__global__ void k_zero() {
    int i = blockIdx.x * blockDim.x + threadIdx.x;
    int stride = gridDim.x * blockDim.x;
    float4 z = make_float4(0.f, 0.f, 0.f, 0.f);
    for (int j = i; j < NN * MCC / 4; j += stride) ((float4*)g_agg)[j] = z;
    for (int j = i; j < NN; j += stride) g_deg[j] = 0.f;
    if (i < CC) g_gsum[i] = 0.f;
    if (i < MCC) g_zeros[i] = 0.f;
}

// ---------------- weight prep ----------------
__global__ void k_prep(const float* __restrict__ ew1) {
    int i = blockIdx.x * blockDim.x + threadIdx.x;
    int stride = gridDim.x * blockDim.x;
    for (int j = i; j < CC * MCC; j += stride) {
        float wc = ew1[2 * CC * MCC + j];
        g_W1a[j] = ew1[j] + wc;
        g_W1b[j] = ew1[CC * MCC + j] - wc;
    }
}

// mma B-fragment pack for ew2, ew3, gw1 (bf16 hi/lo split)
__global__ void k_prep_w(const float* __restrict__ ew2,
                         const float* __restrict__ ew3,
                         const float* __restrict__ gw1) {
    int m = blockIdx.y;
    const float* W = (m == 0) ? ew2 : (m == 1) ? ew3 : gw1;
    int idx = blockIdx.x * blockDim.x + threadIdx.x;
    if (idx >= 4096) return;
    int lane = idx & 31;
    int jg = (idx >> 5) & 15;
    int s = idx >> 9;
    int n = jg * 8 + (lane >> 2);
    int k = s * 16 + (lane & 3) * 2;
    float w00 = W[k * 128 + n],       w01 = W[(k + 1) * 128 + n];
    float w80 = W[(k + 8) * 128 + n], w81 = W[(k + 9) * 128 + n];
    unsigned h0, l0, h8, l8;
    split2(w00, w01, h0, l0);
    split2(w80, w81, h8, l8);
    g_wfrag[m][idx] = make_uint4(h0, h8, l0, l8);
}

// ---------------- layernorm + global column-sum partials ----------------
__global__ void k_lnorm(const float* __restrict__ h,
                        const float* __restrict__ lng,
                        const float* __restrict__ lnb) {
    __shared__ float cs[CC];
    int tid = threadIdx.x, lane = tid & 31, w = tid >> 5;
    int n = blockIdx.x * 4 + w;
    float2 v = ((const float2*)h)[n * 32 + lane];
    float s = v.x + v.y, q = v.x * v.x + v.y * v.y;
#pragma unroll
    for (int o = 16; o; o >>= 1) {
        s += __shfl_xor_sync(~0u, s, o);
        q += __shfl_xor_sync(~0u, q, o);
    }
    float mu = s * (1.f / 64.f);
    float var = q * (1.f / 64.f) - mu * mu;
    float rstd = rsqrtf(var + 1e-5f);
    float f0 = (v.x - mu) * rstd * lng[2 * lane] + lnb[2 * lane];
    float f1 = (v.y - mu) * rstd * lng[2 * lane + 1] + lnb[2 * lane + 1];
    ((float2*)g_feat)[n * 32 + lane] = make_float2(f0, f1);
    if (tid < CC) cs[tid] = 0.f;
    __syncthreads();
    atomicAdd(&cs[2 * lane], f0);
    atomicAdd(&cs[2 * lane + 1], f1);
    __syncthreads();
    if (tid < CC) atomicAdd(&g_gsum[tid], cs[tid]);
}

// ---------------- tiny global MLP + misc + effective update bias ----------------
__global__ void k_global(const float* __restrict__ fdir,
                         const float* glw1, const float* glb1,
                         const float* glw2, const float* glb2,
                         const float* glw3, const float* glb3,
                         const float* res_scale,
                         const float* ub1, const float* uw1) {
    __shared__ float a0[CC], a1[CC], a2[CC];
    int t = threadIdx.x;
    if (t < CC) a0[t] = g_gsum[t] * (1.f / (float)NN);
    __syncthreads();
    if (t < CC) {
        float acc = glb1[t];
        for (int k = 0; k < CC; k++) acc += a0[k] * glw1[k * CC + t];
        a1[t] = gelu_exact(acc);
    }
    __syncthreads();
    if (t < CC) {
        float acc = glb2[t];
        for (int k = 0; k < CC; k++) acc += a1[k] * glw2[k * CC + t];
        a2[t] = gelu_exact(acc);
    }
    __syncthreads();
    if (t < CC) {
        float acc = glb3[t];
        for (int k = 0; k < CC; k++) acc += a2[k] * glw3[k * CC + t];
        g_gctx[t] = acc;
        a0[t] = acc;
    }
    __syncthreads();
    for (int c = t; c < MCC; c += CC) {
        float acc = ub1[c];
        for (int k = 0; k < CC; k++) acc += a0[k] * uw1[(192 + k) * MCC + c];
        g_ub1eff[c] = acc;
    }
    if (t == 0) {
        float u0 = fdir[0], u1 = fdir[1], u2 = fdir[2];
        float inv = 1.f / (sqrtf(u0 * u0 + u1 * u1 + u2 * u2) + 1e-8f);
        g_misc[0] = u0 * inv; g_misc[1] = u1 * inv; g_misc[2] = u2 * inv;
        g_misc[3] = tanhf(res_scale[0]);
    }
}

// ---------------- f32x2 tiled GEMM (k_pq / k_update) ----------------
template <int NOUT, bool DOGELU>
__device__ __forceinline__ void tile_gemm(const float* __restrict__ A, int sA, int K,
                                          const float* __restrict__ W,
                                          const float* __restrict__ bias,
                                          float* __restrict__ Ws,
                                          float* __restrict__ Out, int sO, int tid) {
    constexpr int GROUPS = NOUT / 64;
    const int tx = tid & 15, ty = tid >> 4;
    ull acc[4][GROUPS][2];
#pragma unroll
    for (int r = 0; r < 4; r++)
#pragma unroll
        for (int g = 0; g < GROUPS; g++) { acc[r][g][0] = 0ULL; acc[r][g][1] = 0ULL; }

    const float* Ar0 = A + (ty * 4) * sA;
    for (int k0 = 0; k0 < K; k0 += 32) {
        int kc = K - k0; if (kc > 32) kc = 32;
        __syncthreads();
        {
            const float4* src = (const float4*)(W + k0 * NOUT);
            float4* dst = (float4*)Ws;
            int tot = kc * (NOUT / 4);
            for (int i = tid; i < tot; i += 256) dst[i] = src[i];
        }
        __syncthreads();
#pragma unroll
        for (int kq = 0; kq < 8; kq++) {
            if (kq * 4 >= kc) break;
            float4 av[4];
#pragma unroll
            for (int r = 0; r < 4; r++)
                av[r] = *(const float4*)(Ar0 + r * sA + k0 + kq * 4);
#pragma unroll
            for (int j = 0; j < 4; j++) {
                const float* wr = Ws + (kq * 4 + j) * NOUT + 4 * tx;
                ulonglong2 bq[GROUPS];
#pragma unroll
                for (int g = 0; g < GROUPS; g++)
                    bq[g] = *(const ulonglong2*)(wr + 64 * g);
#pragma unroll
                for (int r = 0; r < 4; r++) {
                    float a = ((const float*)&av[r])[j];
                    ull aa = pack2(a, a);
#pragma unroll
                    for (int g = 0; g < GROUPS; g++) {
                        fma2(acc[r][g][0], aa, bq[g].x);
                        fma2(acc[r][g][1], aa, bq[g].y);
                    }
                }
            }
        }
    }
#pragma unroll
    for (int r = 0; r < 4; r++) {
        float* orow = Out + (ty * 4 + r) * sO;
#pragma unroll
        for (int g = 0; g < GROUPS; g++) {
            int col = 64 * g + 4 * tx;
            float2 v0 = unpack2(acc[r][g][0]);
            float2 v1 = unpack2(acc[r][g][1]);
            float4 o;
            o.x = v0.x + bias[col];
            o.y = v0.y + bias[col + 1];
            o.z = v1.x + bias[col + 2];
            o.w = v1.y + bias[col + 3];
            if (DOGELU) {
                o.x = gelu_exact(o.x); o.y = gelu_exact(o.y);
                o.z = gelu_exact(o.z); o.w = gelu_exact(o.w);
            }
            *(float4*)(orow + col) = o;
        }
    }
}

// ---------------- P/Q node GEMMs ----------------
__global__ void __launch_bounds__(256, 2) k_pq() {
    __shared__ float At[64 * 68];
    __shared__ float Ws[32 * 128];
    int tid = threadIdx.x;
    int n0 = blockIdx.x * 64;
    for (int idx = tid; idx < 64 * 64; idx += 256) {
        int e = idx >> 6, c = idx & 63;
        int n = n0 + e; if (n >= NN) n = NN - 1;
        At[e * 68 + c] = g_feat[n * 64 + c];
    }
    tile_gemm<128, false>(At, 68, 64, g_W1a, g_zeros, Ws, g_P + n0 * MCC, MCC, tid);
    tile_gemm<128, false>(At, 68, 64, g_W1b, g_zeros, Ws, g_Q + n0 * MCC, MCC, tid);
}

// ---------------- edge kernel: mma.sync bf16-split, 64-edge tiles ----------------
#define ASTRIDE 272
#define SB_AH   0
#define SB_AL   17408
#define SB_GEO  34816
#define SB_GP   35840
#define SB_GATE 36352
#define SB_EB2  36608
#define SB_EB3  37120
#define SB_GB1  37632
#define SB_GW2  38144
#define SB_EB1  38656
#define SB_WD   39168
#define SB_RS   41216
#define SB_CS   41472
#define SB_EDGE_BYTES 41728

// one 64x128 GEMM pass: 8 warps, warp (r=wid&3, ch=wid>>2)
__device__ __forceinline__ void mma_pass(const char* sm, const uint4* __restrict__ Wf,
                                         float acc[8][4], int wid, int lane) {
    const int r = wid & 3, ch = wid >> 2;
    const int g = lane >> 2, t = lane & 3;
    const char* Ah = sm + SB_AH;
    const char* Al = sm + SB_AL;
    const int ro0 = (r * 16 + g) * ASTRIDE;
    const int ro1 = ro0 + 8 * ASTRIDE;
#pragma unroll
    for (int s = 0; s < 8; s++) {
        const int cb = s * 32 + 4 * t;
        unsigned ah0 = *(const unsigned*)(Ah + ro0 + cb);
        unsigned ah1 = *(const unsigned*)(Ah + ro1 + cb);
        unsigned ah2 = *(const unsigned*)(Ah + ro0 + cb + 16);
        unsigned ah3 = *(const unsigned*)(Ah + ro1 + cb + 16);
        unsigned al0 = *(const unsigned*)(Al + ro0 + cb);
        unsigned al1 = *(const unsigned*)(Al + ro1 + cb);
        unsigned al2 = *(const unsigned*)(Al + ro0 + cb + 16);
        unsigned al3 = *(const unsigned*)(Al + ro1 + cb + 16);
        const uint4* wp = Wf + (s * 16 + ch * 8) * 32 + lane;
#pragma unroll
        for (int j = 0; j < 8; j++) {
            uint4 w = __ldg(wp + j * 32);
            MMA_BF16(acc[j], ah0, ah1, ah2, ah3, w.x, w.y);
            MMA_BF16(acc[j], ah0, ah1, ah2, ah3, w.z, w.w);
            MMA_BF16(acc[j], al0, al1, al2, al3, w.x, w.y);
        }
    }
}

__global__ void __launch_bounds__(256, 2) k_edge(
    const int* __restrict__ ei, const float* __restrict__ coords,
    const float* __restrict__ ew1, const float* __restrict__ eb1,
    const float* __restrict__ eb2, const float* __restrict__ eb3,
    const float* __restrict__ gb1, const float* __restrict__ gw2,
    const float* __restrict__ gb2) {
    extern __shared__ char sm[];
    char* Ah    = sm + SB_AH;
    char* Al    = sm + SB_AL;
    float* geo  = (float*)(sm + SB_GEO);
    float* gp   = (float*)(sm + SB_GP);
    float* gateS = (float*)(sm + SB_GATE);
    float* eb2s = (float*)(sm + SB_EB2);
    float* eb3s = (float*)(sm + SB_EB3);
    float* gb1s = (float*)(sm + SB_GB1);
    float* gw2s = (float*)(sm + SB_GW2);
    float* eb1s = (float*)(sm + SB_EB1);
    float* Wd   = (float*)(sm + SB_WD);
    int* rs = (int*)(sm + SB_RS);
    int* cs = (int*)(sm + SB_CS);

    const int tid = threadIdx.x;
    const int wid = tid >> 5, lane = tid & 31;
    const int e0 = blockIdx.x * 64;

    if (tid < 64) {
        rs[tid] = ei[e0 + tid];
        cs[tid] = ei[EE + e0 + tid];
    }
    if (tid < 128) {
        eb2s[tid] = eb2[tid];
        eb3s[tid] = eb3[tid];
        gb1s[tid] = gb1[tid];
        gw2s[tid] = gw2[tid];
        eb1s[tid] = eb1[tid];
    }
    for (int i = tid; i < 4 * 128; i += 256) Wd[i] = ew1[192 * 128 + i];
    __syncthreads();

    if (tid < 64) {
        int e = tid, r = rs[e], c = cs[e];
        float xi0 = coords[r * 3], xi1 = coords[r * 3 + 1], xi2 = coords[r * 3 + 2];
        float xj0 = coords[c * 3], xj1 = coords[c * 3 + 1], xj2 = coords[c * 3 + 2];
        float r0 = xi0 - xj0, r1 = xi1 - xj1, r2 = xi2 - xj2;
        float u0 = g_misc[0], u1 = g_misc[1], u2 = g_misc[2];
        geo[e * 4 + 0] = r0 * r0 + r1 * r1 + r2 * r2;
        geo[e * 4 + 1] = xi0 * u0 + xi1 * u1 + xi2 * u2;
        geo[e * 4 + 2] = xj0 * u0 + xj1 * u1 + xj2 * u2;
        geo[e * 4 + 3] = r0 * u0 + r1 * u1 + r2 * u2;
    }
    __syncthreads();

    // ---- build H1 = gelu(P[row] + Q[col] + geo@Wd + eb1) -> Ah/Al ----
    for (int idx = tid; idx < 64 * 16; idx += 256) {
        int e = idx >> 4, c0 = (idx & 15) * 8;
        const float* Pr = g_P + rs[e] * MCC + c0;
        const float* Qr = g_Q + cs[e] * MCC + c0;
        float4 p0 = *(const float4*)Pr, p1 = *(const float4*)(Pr + 4);
        float4 q0 = *(const float4*)Qr, q1 = *(const float4*)(Qr + 4);
        float ge0 = geo[e * 4], ge1 = geo[e * 4 + 1], ge2 = geo[e * 4 + 2], ge3 = geo[e * 4 + 3];
        float h[8];
#pragma unroll
        for (int j = 0; j < 8; j++) {
            int c = c0 + j;
            float pq = (j < 4) ? ((const float*)&p0)[j] + ((const float*)&q0)[j]
                               : ((const float*)&p1)[j - 4] + ((const float*)&q1)[j - 4];
            float v = pq + ge0 * Wd[c] + ge1 * Wd[128 + c] + ge2 * Wd[256 + c]
                    + ge3 * Wd[384 + c] + eb1s[c];
            h[j] = gelu_exact(v);
        }
        unsigned hi[4], lo[4];
#pragma unroll
        for (int j = 0; j < 4; j++) split2(h[2 * j], h[2 * j + 1], hi[j], lo[j]);
        *(uint4*)(Ah + e * ASTRIDE + c0 * 2) = make_uint4(hi[0], hi[1], hi[2], hi[3]);
        *(uint4*)(Al + e * ASTRIDE + c0 * 2) = make_uint4(lo[0], lo[1], lo[2], lo[3]);
    }
    __syncthreads();

    const int r = wid & 3, ch = wid >> 2;
    const int g = lane >> 2, t = lane & 3;
    const int R0 = r * 16 + g, R1 = R0 + 8;

    // ---- GEMM1: H2 = gelu(H1 @ ew2 + eb2) ----
    {
        float acc[8][4];
#pragma unroll
        for (int j = 0; j < 8; j++)
#pragma unroll
            for (int q = 0; q < 4; q++) acc[j][q] = 0.f;
        mma_pass(sm, g_wfrag[0], acc, wid, lane);
        __syncthreads();
#pragma unroll
        for (int j = 0; j < 8; j++) {
            int col = ch * 64 + j * 8 + 2 * t;
            float x0 = gelu_exact(acc[j][0] + eb2s[col]);
            float x1 = gelu_exact(acc[j][1] + eb2s[col + 1]);
            float x2 = gelu_exact(acc[j][2] + eb2s[col]);
            float x3 = gelu_exact(acc[j][3] + eb2s[col + 1]);
            unsigned hi, lo;
            split2(x0, x1, hi, lo);
            *(unsigned*)(Ah + R0 * ASTRIDE + col * 2) = hi;
            *(unsigned*)(Al + R0 * ASTRIDE + col * 2) = lo;
            split2(x2, x3, hi, lo);
            *(unsigned*)(Ah + R1 * ASTRIDE + col * 2) = hi;
            *(unsigned*)(Al + R1 * ASTRIDE + col * 2) = lo;
        }
        __syncthreads();
    }

    // ---- GEMM2: hidden = H2 @ ew3 + eb3 -> split to Ah/Al ----
    {
        float acc[8][4];
#pragma unroll
        for (int j = 0; j < 8; j++)
#pragma unroll
            for (int q = 0; q < 4; q++) acc[j][q] = 0.f;
        mma_pass(sm, g_wfrag[1], acc, wid, lane);
        __syncthreads();
#pragma unroll
        for (int j = 0; j < 8; j++) {
            int col = ch * 64 + j * 8 + 2 * t;
            float x0 = acc[j][0] + eb3s[col];
            float x1 = acc[j][1] + eb3s[col + 1];
            float x2 = acc[j][2] + eb3s[col];
            float x3 = acc[j][3] + eb3s[col + 1];
            unsigned hi, lo;
            split2(x0, x1, hi, lo);
            *(unsigned*)(Ah + R0 * ASTRIDE + col * 2) = hi;
            *(unsigned*)(Al + R0 * ASTRIDE + col * 2) = lo;
            split2(x2, x3, hi, lo);
            *(unsigned*)(Ah + R1 * ASTRIDE + col * 2) = hi;
            *(unsigned*)(Al + R1 * ASTRIDE + col * 2) = lo;
        }
        __syncthreads();
    }

    // ---- GEMM3: gate hidden = hidden @ gw1 + gb1 -> gelu -> dot gw2 ----
    {
        float acc[8][4];
#pragma unroll
        for (int j = 0; j < 8; j++)
#pragma unroll
            for (int q = 0; q < 4; q++) acc[j][q] = 0.f;
        mma_pass(sm, g_wfrag[2], acc, wid, lane);
        float p0 = 0.f, p1 = 0.f;
#pragma unroll
        for (int j = 0; j < 8; j++) {
            int col = ch * 64 + j * 8 + 2 * t;
            p0 += gw2s[col] * gelu_exact(acc[j][0] + gb1s[col])
                + gw2s[col + 1] * gelu_exact(acc[j][1] + gb1s[col + 1]);
            p1 += gw2s[col] * gelu_exact(acc[j][2] + gb1s[col])
                + gw2s[col + 1] * gelu_exact(acc[j][3] + gb1s[col + 1]);
        }
        p0 += __shfl_xor_sync(~0u, p0, 1);
        p0 += __shfl_xor_sync(~0u, p0, 2);
        p1 += __shfl_xor_sync(~0u, p1, 1);
        p1 += __shfl_xor_sync(~0u, p1, 2);
        if (t == 0) {
            gp[ch * 64 + R0] = p0;
            gp[ch * 64 + R1] = p1;
        }
        __syncthreads();
        if (tid < 64) {
            float a = gp[tid] + gp[64 + tid] + gb2[0];
            gateS[tid] = 1.f / (1.f + expf(-a));
        }
        __syncthreads();
    }

    // ---- scatter msg = gate * (hi + lo), vector red.add.v4.f32 ----
    for (int idx = tid; idx < 64 * 32; idx += 256) {
        int e = idx >> 5, c = (idx & 31) * 4;
        uint2 hu = *(const uint2*)(Ah + e * ASTRIDE + c * 2);
        uint2 lu = *(const uint2*)(Al + e * ASTRIDE + c * 2);
        float2 h0 = __bfloat1622float2(*(__nv_bfloat162*)&hu.x);
        float2 h1 = __bfloat1622float2(*(__nv_bfloat162*)&hu.y);
        float2 l0 = __bfloat1622float2(*(__nv_bfloat162*)&lu.x);
        float2 l1 = __bfloat1622float2(*(__nv_bfloat162*)&lu.y);
        float gt = gateS[e];
        float v0 = gt * (h0.x + l0.x);
        float v1 = gt * (h0.y + l0.y);
        float v2 = gt * (h1.x + l1.x);
        float v3 = gt * (h1.y + l1.y);
        float* dst = g_agg + (size_t)rs[e] * MCC + c;
        asm volatile("red.global.add.v4.f32 [%0], {%1, %2, %3, %4};"
                     :: "l"(dst), "f"(v0), "f"(v1), "f"(v2), "f"(v3) : "memory");
    }
    if (tid < 64) atomicAdd(&g_deg[rs[tid]], 1.f);
}

// ---------------- node update kernel ----------------
#define SMU_UN 0
#define SMU_B1 12544
#define SMU_WS 20992
#define SMU_DG 25088
#define SMU_UPD_FLOATS 25152

__global__ void __launch_bounds__(256, 2) k_update(
    const float* uw1, const float* uw2, const float* ub2,
    const float* uw3, const float* ub3, float* __restrict__ out) {
    extern __shared__ float smf[];
    float* Un = smf + SMU_UN;
    float* B1 = smf + SMU_B1;
    float* Ws = smf + SMU_WS;
    float* dg = smf + SMU_DG;
    int tid = threadIdx.x;
    int n0 = blockIdx.x * 64;

    if (tid < 64) {
        int n = n0 + tid; if (n >= NN) n = NN - 1;
        float d = g_deg[n]; if (d < 1.f) d = 1.f;
        dg[tid] = 1.f / d;
    }
    __syncthreads();
    for (int idx = tid; idx < 64 * 64; idx += 256) {
        int e = idx >> 6, c = idx & 63;
        int n = n0 + e; if (n >= NN) n = NN - 1;
        Un[e * 196 + c] = g_feat[n * 64 + c];
    }
    for (int idx = tid; idx < 64 * 128; idx += 256) {
        int e = idx >> 7, c = idx & 127;
        int n = n0 + e; if (n >= NN) n = NN - 1;
        Un[e * 196 + 64 + c] = g_agg[n * 128 + c] * dg[e];
    }
    __syncthreads();

    tile_gemm<128, true >(Un, 196, 192, uw1, g_ub1eff, Ws, B1, 132, tid);
    tile_gemm<128, true >(B1, 132, 128, uw2, ub2, Ws, Un, 132, tid);
    tile_gemm<64,  false>(Un, 132, 128, uw3, ub3, Ws, B1, 68, tid);
    __syncthreads();

    float ts = g_misc[3];
    for (int idx = tid; idx < 64 * 64; idx += 256) {
        int e = idx >> 6, c = idx & 63;
        int n = n0 + e;
        if (n < NN) out[n * 64 + c] = ts * B1[e * 68 + c];
    }
}

// ---------------- launch ----------------
extern "C" void kernel_launch(void* const* d_in, const int* in_sizes, int n_in,
                              void* d_out, int out_size) {
    const float* coords   = (const float*)d_in[0];
    const float* h        = (const float*)d_in[1];
    const float* fdir     = (const float*)d_in[2];
    const int*   ei       = (const int*)d_in[3];
    const float* ln_g     = (const float*)d_in[4];
    const float* ln_b     = (const float*)d_in[5];
    const float* ew1      = (const float*)d_in[6];
    const float* eb1      = (const float*)d_in[7];
    const float* ew2      = (const float*)d_in[8];
    const float* eb2      = (const float*)d_in[9];
    const float* ew3      = (const float*)d_in[10];
    const float* eb3      = (const float*)d_in[11];
    const float* gw1      = (const float*)d_in[12];
    const float* gb1      = (const float*)d_in[13];
    const float* gw2      = (const float*)d_in[14];
    const float* gb2      = (const float*)d_in[15];
    const float* glw1     = (const float*)d_in[16];
    const float* glb1     = (const float*)d_in[17];
    const float* glw2     = (const float*)d_in[18];
    const float* glb2     = (const float*)d_in[19];
    const float* glw3     = (const float*)d_in[20];
    const float* glb3     = (const float*)d_in[21];
    const float* uw1      = (const float*)d_in[22];
    const float* ub1      = (const float*)d_in[23];
    const float* uw2      = (const float*)d_in[24];
    const float* ub2      = (const float*)d_in[25];
    const float* uw3      = (const float*)d_in[26];
    const float* ub3      = (const float*)d_in[27];
    const float* rscale   = (const float*)d_in[28];
    float* out = (float*)d_out;

    cudaFuncSetAttribute(k_edge, cudaFuncAttributeMaxDynamicSharedMemorySize,
                         SB_EDGE_BYTES);
    cudaFuncSetAttribute(k_update, cudaFuncAttributeMaxDynamicSharedMemorySize,
                         SMU_UPD_FLOATS * 4);

    k_zero<<<2048, 256>>>();
    k_prep<<<32, 256>>>(ew1);
    {
        dim3 gdim(16, 3);
        k_prep_w<<<gdim, 256>>>(ew2, ew3, gw1);
    }
    k_lnorm<<<NN / 4, 128>>>(h, ln_g, ln_b);
    k_global<<<1, 64>>>(fdir, glw1, glb1, glw2, glb2, glw3, glb3, rscale, ub1, uw1);
    k_pq<<<(NN + 63) / 64, 256>>>();
    k_edge<<<EE / 64, 256, SB_EDGE_BYTES>>>(ei, coords,
        ew1, eb1, eb2, eb3, gb1, gw2, gb2);
    k_update<<<(NN + 63) / 64, 256, SMU_UPD_FLOATS * 4>>>(
        uw1, uw2, ub2, uw3, ub3, out);
}

// round 10
// speedup vs baseline: 1.2717x; 1.1295x over previous
#include <cuda_runtime.h>
#include <cuda_bf16.h>

#define NN 50000
#define EE 800000
#define CC 64
#define MCC 128
#define NPAD 50048

typedef unsigned long long ull;

// ---------------- device scratch ----------------
__device__ __align__(16) float g_feat[NN * CC];
__device__ __align__(16) float g_agg[NN * MCC];
__device__ __align__(16) float g_deg[NN];
__device__ __align__(16) float g_gsum[CC];
__device__ __align__(16) float g_gctx[CC];
__device__ __align__(16) float g_misc[4];          // u0,u1,u2, tanh(res_scale)
__device__ __align__(16) float g_W1a[CC * MCC];
__device__ __align__(16) float g_W1b[CC * MCC];
__device__ __align__(16) float g_P[NPAD * MCC];
__device__ __align__(16) float g_Q[NPAD * MCC];
__device__ __align__(16) float g_ub1eff[MCC];
__device__ __align__(16) float g_zeros[MCC];
// mma.sync B fragments: [mat][ (s*16 + jg)*32 + lane ] = {bh0, bh1, bl0, bl1}
__device__ __align__(16) uint4 g_wfrag[3][4096];
// update-MLP weight fragments: uw1 (K=192,N=128), uw2 (128,128), uw3 (128,64)
__device__ __align__(16) uint4 g_wfu1[6144];
__device__ __align__(16) uint4 g_wfu2[4096];
__device__ __align__(16) uint4 g_wfu3[2048];

// ---------------- f32x2 packed math (SIMT GEMMs) ----------------
__device__ __forceinline__ ull pack2(float lo, float hi) {
    ull r; asm("mov.b64 %0, {%1, %2};" : "=l"(r) : "f"(lo), "f"(hi)); return r;
}
__device__ __forceinline__ void fma2(ull& d, ull a, ull b) {
    asm("fma.rn.f32x2 %0, %1, %2, %0;" : "+l"(d) : "l"(a), "l"(b));
}
__device__ __forceinline__ float2 unpack2(ull v) {
    float2 f; asm("mov.b64 {%0, %1}, %2;" : "=f"(f.x), "=f"(f.y) : "l"(v)); return f;
}
__device__ __forceinline__ float gelu_exact(float x) {
    return 0.5f * x * (1.0f + erff(x * 0.7071067811865476f));
}
__device__ __forceinline__ void split2(float a, float b, unsigned& hi, unsigned& lo) {
    __nv_bfloat162 h = __floats2bfloat162_rn(a, b);
    float ra = a - __bfloat162float(h.x);
    float rb = b - __bfloat162float(h.y);
    __nv_bfloat162 l = __floats2bfloat162_rn(ra, rb);
    hi = *(unsigned*)&h;
    lo = *(unsigned*)&l;
}

#define MMA_BF16(c, a0, a1, a2, a3, b0, b1) \
    asm volatile( \
        "mma.sync.aligned.m16n8k16.row.col.f32.bf16.bf16.f32 " \
        "{%0,%1,%2,%3}, {%4,%5,%6,%7}, {%8,%9}, {%0,%1,%2,%3};" \
        : "+f"((c)[0]), "+f"((c)[1]), "+f"((c)[2]), "+f"((c)[3]) \
        : "r"(a0), "r"(a1), "r"(a2), "r"(a3), "r"(b0), "r"(b1))

// ---------------- zero scratch ----------------
__global__ void k_zero() {
    int i = blockIdx.x * blockDim.x + threadIdx.x;
    int stride = gridDim.x * blockDim.x;
    float4 z = make_float4(0.f, 0.f, 0.f, 0.f);
    for (int j = i; j < NN * MCC / 4; j += stride) ((float4*)g_agg)[j] = z;
    for (int j = i; j < NN; j += stride) g_deg[j] = 0.f;
    if (i < CC) g_gsum[i] = 0.f;
    if (i < MCC) g_zeros[i] = 0.f;
}

// ---------------- weight prep ----------------
__global__ void k_prep(const float* __restrict__ ew1) {
    int i = blockIdx.x * blockDim.x + threadIdx.x;
    int stride = gridDim.x * blockDim.x;
    for (int j = i; j < CC * MCC; j += stride) {
        float wc = ew1[2 * CC * MCC + j];
        g_W1a[j] = ew1[j] + wc;
        g_W1b[j] = ew1[CC * MCC + j] - wc;
    }
}

// mma B-fragment pack for ew2, ew3, gw1 (bf16 hi/lo split)
__global__ void k_prep_w(const float* __restrict__ ew2,
                         const float* __restrict__ ew3,
                         const float* __restrict__ gw1) {
    int m = blockIdx.y;
    const float* W = (m == 0) ? ew2 : (m == 1) ? ew3 : gw1;
    int idx = blockIdx.x * blockDim.x + threadIdx.x;
    if (idx >= 4096) return;
    int lane = idx & 31;
    int jg = (idx >> 5) & 15;
    int s = idx >> 9;
    int n = jg * 8 + (lane >> 2);
    int k = s * 16 + (lane & 3) * 2;
    float w00 = W[k * 128 + n],       w01 = W[(k + 1) * 128 + n];
    float w80 = W[(k + 8) * 128 + n], w81 = W[(k + 9) * 128 + n];
    unsigned h0, l0, h8, l8;
    split2(w00, w01, h0, l0);
    split2(w80, w81, h8, l8);
    g_wfrag[m][idx] = make_uint4(h0, h8, l0, l8);
}

// fragment pack for update weights uw1/uw2/uw3
__global__ void k_prep_wu(const float* __restrict__ uw1,
                          const float* __restrict__ uw2,
                          const float* __restrict__ uw3) {
    int gidx = blockIdx.x * blockDim.x + threadIdx.x;
    if (gidx >= 12288) return;
    const float* W; uint4* dst; int idx, ldW, jgTot;
    if (gidx < 6144)       { W = uw1; dst = g_wfu1; idx = gidx;          ldW = 128; jgTot = 16; }
    else if (gidx < 10240) { W = uw2; dst = g_wfu2; idx = gidx - 6144;   ldW = 128; jgTot = 16; }
    else                   { W = uw3; dst = g_wfu3; idx = gidx - 10240;  ldW = 64;  jgTot = 8; }
    int lane = idx & 31;
    int jg = (idx >> 5) % jgTot;
    int s  = (idx >> 5) / jgTot;
    int n = jg * 8 + (lane >> 2);
    int k = s * 16 + (lane & 3) * 2;
    float w00 = W[k * ldW + n],       w01 = W[(k + 1) * ldW + n];
    float w80 = W[(k + 8) * ldW + n], w81 = W[(k + 9) * ldW + n];
    unsigned h0, l0, h8, l8;
    split2(w00, w01, h0, l0);
    split2(w80, w81, h8, l8);
    dst[idx] = make_uint4(h0, h8, l0, l8);
}

// ---------------- layernorm (2 rows/warp ILP) + global column-sum partials ----------------
__global__ void k_lnorm(const float* __restrict__ h,
                        const float* __restrict__ lng,
                        const float* __restrict__ lnb) {
    __shared__ float cs[CC];
    int tid = threadIdx.x, lane = tid & 31, w = tid >> 5;
    int nA = blockIdx.x * 8 + w * 2, nB = nA + 1;
    float2 va = ((const float2*)h)[nA * 32 + lane];
    float2 vb = ((const float2*)h)[nB * 32 + lane];
    float sa = va.x + va.y, qa = va.x * va.x + va.y * va.y;
    float sb = vb.x + vb.y, qb = vb.x * vb.x + vb.y * vb.y;
#pragma unroll
    for (int o = 16; o; o >>= 1) {
        sa += __shfl_xor_sync(~0u, sa, o);
        qa += __shfl_xor_sync(~0u, qa, o);
        sb += __shfl_xor_sync(~0u, sb, o);
        qb += __shfl_xor_sync(~0u, qb, o);
    }
    float g0 = lng[2 * lane], g1 = lng[2 * lane + 1];
    float b0 = lnb[2 * lane], b1 = lnb[2 * lane + 1];
    float muA = sa * (1.f / 64.f);
    float rsA = rsqrtf(qa * (1.f / 64.f) - muA * muA + 1e-5f);
    float muB = sb * (1.f / 64.f);
    float rsB = rsqrtf(qb * (1.f / 64.f) - muB * muB + 1e-5f);
    float f0a = (va.x - muA) * rsA * g0 + b0;
    float f1a = (va.y - muA) * rsA * g1 + b1;
    float f0b = (vb.x - muB) * rsB * g0 + b0;
    float f1b = (vb.y - muB) * rsB * g1 + b1;
    ((float2*)g_feat)[nA * 32 + lane] = make_float2(f0a, f1a);
    ((float2*)g_feat)[nB * 32 + lane] = make_float2(f0b, f1b);
    if (tid < CC) cs[tid] = 0.f;
    __syncthreads();
    atomicAdd(&cs[2 * lane], f0a + f0b);
    atomicAdd(&cs[2 * lane + 1], f1a + f1b);
    __syncthreads();
    if (tid < CC) atomicAdd(&g_gsum[tid], cs[tid]);
}

// ---------------- tiny global MLP + misc + effective update bias ----------------
__global__ void k_global(const float* __restrict__ fdir,
                         const float* glw1, const float* glb1,
                         const float* glw2, const float* glb2,
                         const float* glw3, const float* glb3,
                         const float* res_scale,
                         const float* ub1, const float* uw1) {
    __shared__ float a0[CC], a1[CC], a2[CC];
    int t = threadIdx.x;
    if (t < CC) a0[t] = g_gsum[t] * (1.f / (float)NN);
    __syncthreads();
    if (t < CC) {
        float acc = glb1[t];
        for (int k = 0; k < CC; k++) acc += a0[k] * glw1[k * CC + t];
        a1[t] = gelu_exact(acc);
    }
    __syncthreads();
    if (t < CC) {
        float acc = glb2[t];
        for (int k = 0; k < CC; k++) acc += a1[k] * glw2[k * CC + t];
        a2[t] = gelu_exact(acc);
    }
    __syncthreads();
    if (t < CC) {
        float acc = glb3[t];
        for (int k = 0; k < CC; k++) acc += a2[k] * glw3[k * CC + t];
        g_gctx[t] = acc;
        a0[t] = acc;
    }
    __syncthreads();
    for (int c = t; c < MCC; c += CC) {
        float acc = ub1[c];
        for (int k = 0; k < CC; k++) acc += a0[k] * uw1[(192 + k) * MCC + c];
        g_ub1eff[c] = acc;
    }
    if (t == 0) {
        float u0 = fdir[0], u1 = fdir[1], u2 = fdir[2];
        float inv = 1.f / (sqrtf(u0 * u0 + u1 * u1 + u2 * u2) + 1e-8f);
        g_misc[0] = u0 * inv; g_misc[1] = u1 * inv; g_misc[2] = u2 * inv;
        g_misc[3] = tanhf(res_scale[0]);
    }
}

// ---------------- f32x2 tiled GEMM (k_pq) ----------------
template <int NOUT, bool DOGELU>
__device__ __forceinline__ void tile_gemm(const float* __restrict__ A, int sA, int K,
                                          const float* __restrict__ W,
                                          const float* __restrict__ bias,
                                          float* __restrict__ Ws,
                                          float* __restrict__ Out, int sO, int tid) {
    constexpr int GROUPS = NOUT / 64;
    const int tx = tid & 15, ty = tid >> 4;
    ull acc[4][GROUPS][2];
#pragma unroll
    for (int r = 0; r < 4; r++)
#pragma unroll
        for (int g = 0; g < GROUPS; g++) { acc[r][g][0] = 0ULL; acc[r][g][1] = 0ULL; }

    const float* Ar0 = A + (ty * 4) * sA;
    for (int k0 = 0; k0 < K; k0 += 32) {
        int kc = K - k0; if (kc > 32) kc = 32;
        __syncthreads();
        {
            const float4* src = (const float4*)(W + k0 * NOUT);
            float4* dst = (float4*)Ws;
            int tot = kc * (NOUT / 4);
            for (int i = tid; i < tot; i += 256) dst[i] = src[i];
        }
        __syncthreads();
#pragma unroll
        for (int kq = 0; kq < 8; kq++) {
            if (kq * 4 >= kc) break;
            float4 av[4];
#pragma unroll
            for (int r = 0; r < 4; r++)
                av[r] = *(const float4*)(Ar0 + r * sA + k0 + kq * 4);
#pragma unroll
            for (int j = 0; j < 4; j++) {
                const float* wr = Ws + (kq * 4 + j) * NOUT + 4 * tx;
                ulonglong2 bq[GROUPS];
#pragma unroll
                for (int g = 0; g < GROUPS; g++)
                    bq[g] = *(const ulonglong2*)(wr + 64 * g);
#pragma unroll
                for (int r = 0; r < 4; r++) {
                    float a = ((const float*)&av[r])[j];
                    ull aa = pack2(a, a);
#pragma unroll
                    for (int g = 0; g < GROUPS; g++) {
                        fma2(acc[r][g][0], aa, bq[g].x);
                        fma2(acc[r][g][1], aa, bq[g].y);
                    }
                }
            }
        }
    }
#pragma unroll
    for (int r = 0; r < 4; r++) {
        float* orow = Out + (ty * 4 + r) * sO;
#pragma unroll
        for (int g = 0; g < GROUPS; g++) {
            int col = 64 * g + 4 * tx;
            float2 v0 = unpack2(acc[r][g][0]);
            float2 v1 = unpack2(acc[r][g][1]);
            float4 o;
            o.x = v0.x + bias[col];
            o.y = v0.y + bias[col + 1];
            o.z = v1.x + bias[col + 2];
            o.w = v1.y + bias[col + 3];
            if (DOGELU) {
                o.x = gelu_exact(o.x); o.y = gelu_exact(o.y);
                o.z = gelu_exact(o.z); o.w = gelu_exact(o.w);
            }
            *(float4*)(orow + col) = o;
        }
    }
}

// ---------------- P/Q node GEMMs ----------------
__global__ void __launch_bounds__(256, 2) k_pq() {
    __shared__ float At[64 * 68];
    __shared__ float Ws[32 * 128];
    int tid = threadIdx.x;
    int n0 = blockIdx.x * 64;
    for (int idx = tid; idx < 64 * 64; idx += 256) {
        int e = idx >> 6, c = idx & 63;
        int n = n0 + e; if (n >= NN) n = NN - 1;
        At[e * 68 + c] = g_feat[n * 64 + c];
    }
    tile_gemm<128, false>(At, 68, 64, g_W1a, g_zeros, Ws, g_P + n0 * MCC, MCC, tid);
    tile_gemm<128, false>(At, 68, 64, g_W1b, g_zeros, Ws, g_Q + n0 * MCC, MCC, tid);
}

// ---------------- generic mma pass (64 rows, variable K / N) ----------------
// SS = K/16 s-steps; JGT = N/8 fragment groups total (split over 2 warp-halves).
template <int SS, int JGT>
__device__ __forceinline__ void mma_passg(const char* Ah, const char* Al, int ast,
                                          const uint4* __restrict__ Wf,
                                          float acc[][4], int wid, int lane) {
    const int r = wid & 3, ch = wid >> 2;
    const int g = lane >> 2, t = lane & 3;
    const int ro0 = (r * 16 + g) * ast;
    const int ro1 = ro0 + 8 * ast;
    constexpr int JC = JGT / 2;
#pragma unroll
    for (int s = 0; s < SS; s++) {
        const int cb = s * 32 + 4 * t;
        unsigned ah0 = *(const unsigned*)(Ah + ro0 + cb);
        unsigned ah1 = *(const unsigned*)(Ah + ro1 + cb);
        unsigned ah2 = *(const unsigned*)(Ah + ro0 + cb + 16);
        unsigned ah3 = *(const unsigned*)(Ah + ro1 + cb + 16);
        unsigned al0 = *(const unsigned*)(Al + ro0 + cb);
        unsigned al1 = *(const unsigned*)(Al + ro1 + cb);
        unsigned al2 = *(const unsigned*)(Al + ro0 + cb + 16);
        unsigned al3 = *(const unsigned*)(Al + ro1 + cb + 16);
        const uint4* wp = Wf + (s * JGT + ch * JC) * 32 + lane;
#pragma unroll
        for (int j = 0; j < JC; j++) {
            uint4 w = __ldg(wp + j * 32);
            MMA_BF16(acc[j], ah0, ah1, ah2, ah3, w.x, w.y);
            MMA_BF16(acc[j], ah0, ah1, ah2, ah3, w.z, w.w);
            MMA_BF16(acc[j], al0, al1, al2, al3, w.x, w.y);
        }
    }
}

// ---------------- edge kernel: mma.sync bf16-split, 64-edge tiles ----------------
#define ASTRIDE 272
#define SB_AH   0
#define SB_AL   17408
#define SB_GEO  34816
#define SB_GP   35840
#define SB_GATE 36352
#define SB_EB2  36608
#define SB_EB3  37120
#define SB_GB1  37632
#define SB_GW2  38144
#define SB_EB1  38656
#define SB_WD   39168
#define SB_RS   41216
#define SB_CS   41472
#define SB_EDGE_BYTES 41728

__global__ void __launch_bounds__(256, 2) k_edge(
    const int* __restrict__ ei, const float* __restrict__ coords,
    const float* __restrict__ ew1, const float* __restrict__ eb1,
    const float* __restrict__ eb2, const float* __restrict__ eb3,
    const float* __restrict__ gb1, const float* __restrict__ gw2,
    const float* __restrict__ gb2) {
    extern __shared__ char sm[];
    char* Ah    = sm + SB_AH;
    char* Al    = sm + SB_AL;
    float* geo  = (float*)(sm + SB_GEO);
    float* gp   = (float*)(sm + SB_GP);
    float* gateS = (float*)(sm + SB_GATE);
    float* eb2s = (float*)(sm + SB_EB2);
    float* eb3s = (float*)(sm + SB_EB3);
    float* gb1s = (float*)(sm + SB_GB1);
    float* gw2s = (float*)(sm + SB_GW2);
    float* eb1s = (float*)(sm + SB_EB1);
    float* Wd   = (float*)(sm + SB_WD);
    int* rs = (int*)(sm + SB_RS);
    int* cs = (int*)(sm + SB_CS);

    const int tid = threadIdx.x;
    const int wid = tid >> 5, lane = tid & 31;
    const int e0 = blockIdx.x * 64;

    if (tid < 64) {
        rs[tid] = ei[e0 + tid];
        cs[tid] = ei[EE + e0 + tid];
    }
    if (tid < 128) {
        eb2s[tid] = eb2[tid];
        eb3s[tid] = eb3[tid];
        gb1s[tid] = gb1[tid];
        gw2s[tid] = gw2[tid];
        eb1s[tid] = eb1[tid];
    }
    for (int i = tid; i < 4 * 128; i += 256) Wd[i] = ew1[192 * 128 + i];
    __syncthreads();

    if (tid < 64) {
        int e = tid, r = rs[e], c = cs[e];
        float xi0 = coords[r * 3], xi1 = coords[r * 3 + 1], xi2 = coords[r * 3 + 2];
        float xj0 = coords[c * 3], xj1 = coords[c * 3 + 1], xj2 = coords[c * 3 + 2];
        float r0 = xi0 - xj0, r1 = xi1 - xj1, r2 = xi2 - xj2;
        float u0 = g_misc[0], u1 = g_misc[1], u2 = g_misc[2];
        geo[e * 4 + 0] = r0 * r0 + r1 * r1 + r2 * r2;
        geo[e * 4 + 1] = xi0 * u0 + xi1 * u1 + xi2 * u2;
        geo[e * 4 + 2] = xj0 * u0 + xj1 * u1 + xj2 * u2;
        geo[e * 4 + 3] = r0 * u0 + r1 * u1 + r2 * u2;
    }
    __syncthreads();

    // ---- build H1 = gelu(P[row] + Q[col] + geo@Wd + eb1) -> Ah/Al ----
    for (int idx = tid; idx < 64 * 16; idx += 256) {
        int e = idx >> 4, c0 = (idx & 15) * 8;
        const float* Pr = g_P + rs[e] * MCC + c0;
        const float* Qr = g_Q + cs[e] * MCC + c0;
        float4 p0 = *(const float4*)Pr, p1 = *(const float4*)(Pr + 4);
        float4 q0 = *(const float4*)Qr, q1 = *(const float4*)(Qr + 4);
        float ge0 = geo[e * 4], ge1 = geo[e * 4 + 1], ge2 = geo[e * 4 + 2], ge3 = geo[e * 4 + 3];
        float h[8];
#pragma unroll
        for (int j = 0; j < 8; j++) {
            int c = c0 + j;
            float pq = (j < 4) ? ((const float*)&p0)[j] + ((const float*)&q0)[j]
                               : ((const float*)&p1)[j - 4] + ((const float*)&q1)[j - 4];
            float v = pq + ge0 * Wd[c] + ge1 * Wd[128 + c] + ge2 * Wd[256 + c]
                    + ge3 * Wd[384 + c] + eb1s[c];
            h[j] = gelu_exact(v);
        }
        unsigned hi[4], lo[4];
#pragma unroll
        for (int j = 0; j < 4; j++) split2(h[2 * j], h[2 * j + 1], hi[j], lo[j]);
        *(uint4*)(Ah + e * ASTRIDE + c0 * 2) = make_uint4(hi[0], hi[1], hi[2], hi[3]);
        *(uint4*)(Al + e * ASTRIDE + c0 * 2) = make_uint4(lo[0], lo[1], lo[2], lo[3]);
    }
    __syncthreads();

    const int r = wid & 3, ch = wid >> 2;
    const int g = lane >> 2, t = lane & 3;
    const int R0 = r * 16 + g, R1 = R0 + 8;

    // ---- GEMM1: H2 = gelu(H1 @ ew2 + eb2) ----
    {
        float acc[8][4];
#pragma unroll
        for (int j = 0; j < 8; j++)
#pragma unroll
            for (int q = 0; q < 4; q++) acc[j][q] = 0.f;
        mma_passg<8, 16>(Ah, Al, ASTRIDE, g_wfrag[0], acc, wid, lane);
        __syncthreads();
#pragma unroll
        for (int j = 0; j < 8; j++) {
            int col = ch * 64 + j * 8 + 2 * t;
            float x0 = gelu_exact(acc[j][0] + eb2s[col]);
            float x1 = gelu_exact(acc[j][1] + eb2s[col + 1]);
            float x2 = gelu_exact(acc[j][2] + eb2s[col]);
            float x3 = gelu_exact(acc[j][3] + eb2s[col + 1]);
            unsigned hi, lo;
            split2(x0, x1, hi, lo);
            *(unsigned*)(Ah + R0 * ASTRIDE + col * 2) = hi;
            *(unsigned*)(Al + R0 * ASTRIDE + col * 2) = lo;
            split2(x2, x3, hi, lo);
            *(unsigned*)(Ah + R1 * ASTRIDE + col * 2) = hi;
            *(unsigned*)(Al + R1 * ASTRIDE + col * 2) = lo;
        }
        __syncthreads();
    }

    // ---- GEMM2: hidden = H2 @ ew3 + eb3 -> split to Ah/Al ----
    {
        float acc[8][4];
#pragma unroll
        for (int j = 0; j < 8; j++)
#pragma unroll
            for (int q = 0; q < 4; q++) acc[j][q] = 0.f;
        mma_passg<8, 16>(Ah, Al, ASTRIDE, g_wfrag[1], acc, wid, lane);
        __syncthreads();
#pragma unroll
        for (int j = 0; j < 8; j++) {
            int col = ch * 64 + j * 8 + 2 * t;
            float x0 = acc[j][0] + eb3s[col];
            float x1 = acc[j][1] + eb3s[col + 1];
            float x2 = acc[j][2] + eb3s[col];
            float x3 = acc[j][3] + eb3s[col + 1];
            unsigned hi, lo;
            split2(x0, x1, hi, lo);
            *(unsigned*)(Ah + R0 * ASTRIDE + col * 2) = hi;
            *(unsigned*)(Al + R0 * ASTRIDE + col * 2) = lo;
            split2(x2, x3, hi, lo);
            *(unsigned*)(Ah + R1 * ASTRIDE + col * 2) = hi;
            *(unsigned*)(Al + R1 * ASTRIDE + col * 2) = lo;
        }
        __syncthreads();
    }

    // ---- GEMM3: gate hidden = hidden @ gw1 + gb1 -> gelu -> dot gw2 ----
    {
        float acc[8][4];
#pragma unroll
        for (int j = 0; j < 8; j++)
#pragma unroll
            for (int q = 0; q < 4; q++) acc[j][q] = 0.f;
        mma_passg<8, 16>(Ah, Al, ASTRIDE, g_wfrag[2], acc, wid, lane);
        float p0 = 0.f, p1 = 0.f;
#pragma unroll
        for (int j = 0; j < 8; j++) {
            int col = ch * 64 + j * 8 + 2 * t;
            p0 += gw2s[col] * gelu_exact(acc[j][0] + gb1s[col])
                + gw2s[col + 1] * gelu_exact(acc[j][1] + gb1s[col + 1]);
            p1 += gw2s[col] * gelu_exact(acc[j][2] + gb1s[col])
                + gw2s[col + 1] * gelu_exact(acc[j][3] + gb1s[col + 1]);
        }
        p0 += __shfl_xor_sync(~0u, p0, 1);
        p0 += __shfl_xor_sync(~0u, p0, 2);
        p1 += __shfl_xor_sync(~0u, p1, 1);
        p1 += __shfl_xor_sync(~0u, p1, 2);
        if (t == 0) {
            gp[ch * 64 + R0] = p0;
            gp[ch * 64 + R1] = p1;
        }
        __syncthreads();
        if (tid < 64) {
            float a = gp[tid] + gp[64 + tid] + gb2[0];
            gateS[tid] = 1.f / (1.f + expf(-a));
        }
        __syncthreads();
    }

    // ---- scatter msg = gate * (hi + lo), vector red.add.v4.f32 ----
    for (int idx = tid; idx < 64 * 32; idx += 256) {
        int e = idx >> 5, c = (idx & 31) * 4;
        uint2 hu = *(const uint2*)(Ah + e * ASTRIDE + c * 2);
        uint2 lu = *(const uint2*)(Al + e * ASTRIDE + c * 2);
        float2 h0 = __bfloat1622float2(*(__nv_bfloat162*)&hu.x);
        float2 h1 = __bfloat1622float2(*(__nv_bfloat162*)&hu.y);
        float2 l0 = __bfloat1622float2(*(__nv_bfloat162*)&lu.x);
        float2 l1 = __bfloat1622float2(*(__nv_bfloat162*)&lu.y);
        float gt = gateS[e];
        float v0 = gt * (h0.x + l0.x);
        float v1 = gt * (h0.y + l0.y);
        float v2 = gt * (h1.x + l1.x);
        float v3 = gt * (h1.y + l1.y);
        float* dst = g_agg + (size_t)rs[e] * MCC + c;
        asm volatile("red.global.add.v4.f32 [%0], {%1, %2, %3, %4};"
                     :: "l"(dst), "f"(v0), "f"(v1), "f"(v2), "f"(v3) : "memory");
    }
    if (tid < 64) atomicAdd(&g_deg[rs[tid]], 1.f);
}

// ---------------- node update kernel: mma.sync bf16-split ----------------
// input K=192 rows stride 400B; intermediate K=128 stride 272B
#define USTRIDE 400
#define SU_UH   0
#define SU_UL   25600
#define SU_BH   51200
#define SU_BL   68608
#define SU_B1   86016
#define SU_B2   86528
#define SU_B3   87040
#define SU_DG   87296
#define SU_BYTES 87552

__global__ void __launch_bounds__(256, 2) k_update(
    const float* __restrict__ ub2, const float* __restrict__ ub3,
    float* __restrict__ out) {
    extern __shared__ char smu[];
    char* UH = smu + SU_UH;
    char* UL = smu + SU_UL;
    char* BH = smu + SU_BH;
    char* BL = smu + SU_BL;
    float* b1s = (float*)(smu + SU_B1);
    float* b2s = (float*)(smu + SU_B2);
    float* b3s = (float*)(smu + SU_B3);
    float* dg  = (float*)(smu + SU_DG);
    const int tid = threadIdx.x;
    const int wid = tid >> 5, lane = tid & 31;
    const int n0 = blockIdx.x * 64;

    if (tid < 128) { b1s[tid] = g_ub1eff[tid]; b2s[tid] = ub2[tid]; }
    if (tid < 64) {
        b3s[tid] = ub3[tid];
        int n = n0 + tid; if (n >= NN) n = NN - 1;
        float d = g_deg[n]; if (d < 1.f) d = 1.f;
        dg[tid] = 1.f / d;
    }
    __syncthreads();

    // build input: cols 0..63 feat, 64..191 agg/deg -> bf16 hi/lo
    for (int idx = tid; idx < 64 * 8; idx += 256) {
        int e = idx >> 3, c0 = (idx & 7) * 8;
        int n = n0 + e; if (n >= NN) n = NN - 1;
        const float* fr = g_feat + n * 64 + c0;
        unsigned hi[4], lo[4];
#pragma unroll
        for (int j = 0; j < 4; j++) split2(fr[2 * j], fr[2 * j + 1], hi[j], lo[j]);
        *(uint4*)(UH + e * USTRIDE + c0 * 2) = make_uint4(hi[0], hi[1], hi[2], hi[3]);
        *(uint4*)(UL + e * USTRIDE + c0 * 2) = make_uint4(lo[0], lo[1], lo[2], lo[3]);
    }
    for (int idx = tid; idx < 64 * 16; idx += 256) {
        int e = idx >> 4, cc = (idx & 15) * 8;
        int n = n0 + e; if (n >= NN) n = NN - 1;
        const float* ar = g_agg + (size_t)n * 128 + cc;
        float sc = dg[e];
        unsigned hi[4], lo[4];
#pragma unroll
        for (int j = 0; j < 4; j++)
            split2(ar[2 * j] * sc, ar[2 * j + 1] * sc, hi[j], lo[j]);
        int boff = (64 + cc) * 2;
        *(uint4*)(UH + e * USTRIDE + boff) = make_uint4(hi[0], hi[1], hi[2], hi[3]);
        *(uint4*)(UL + e * USTRIDE + boff) = make_uint4(lo[0], lo[1], lo[2], lo[3]);
    }
    __syncthreads();

    const int r = wid & 3, ch = wid >> 2;
    const int g = lane >> 2, t = lane & 3;
    const int R0 = r * 16 + g, R1 = R0 + 8;

    // ---- GEMM1: h1 = gelu(U @ uw1 + ub1eff) -> BH/BL ----
    {
        float acc[8][4];
#pragma unroll
        for (int j = 0; j < 8; j++)
#pragma unroll
            for (int q = 0; q < 4; q++) acc[j][q] = 0.f;
        mma_passg<12, 16>(UH, UL, USTRIDE, g_wfu1, acc, wid, lane);
#pragma unroll
        for (int j = 0; j < 8; j++) {
            int col = ch * 64 + j * 8 + 2 * t;
            float x0 = gelu_exact(acc[j][0] + b1s[col]);
            float x1 = gelu_exact(acc[j][1] + b1s[col + 1]);
            float x2 = gelu_exact(acc[j][2] + b1s[col]);
            float x3 = gelu_exact(acc[j][3] + b1s[col + 1]);
            unsigned hi, lo;
            split2(x0, x1, hi, lo);
            *(unsigned*)(BH + R0 * ASTRIDE + col * 2) = hi;
            *(unsigned*)(BL + R0 * ASTRIDE + col * 2) = lo;
            split2(x2, x3, hi, lo);
            *(unsigned*)(BH + R1 * ASTRIDE + col * 2) = hi;
            *(unsigned*)(BL + R1 * ASTRIDE + col * 2) = lo;
        }
        __syncthreads();
    }

    // ---- GEMM2: h2 = gelu(h1 @ uw2 + ub2) -> UH/UL (cols 0..127) ----
    {
        float acc[8][4];
#pragma unroll
        for (int j = 0; j < 8; j++)
#pragma unroll
            for (int q = 0; q < 4; q++) acc[j][q] = 0.f;
        mma_passg<8, 16>(BH, BL, ASTRIDE, g_wfu2, acc, wid, lane);
        __syncthreads();
#pragma unroll
        for (int j = 0; j < 8; j++) {
            int col = ch * 64 + j * 8 + 2 * t;
            float x0 = gelu_exact(acc[j][0] + b2s[col]);
            float x1 = gelu_exact(acc[j][1] + b2s[col + 1]);
            float x2 = gelu_exact(acc[j][2] + b2s[col]);
            float x3 = gelu_exact(acc[j][3] + b2s[col + 1]);
            unsigned hi, lo;
            split2(x0, x1, hi, lo);
            *(unsigned*)(UH + R0 * USTRIDE + col * 2) = hi;
            *(unsigned*)(UL + R0 * USTRIDE + col * 2) = lo;
            split2(x2, x3, hi, lo);
            *(unsigned*)(UH + R1 * USTRIDE + col * 2) = hi;
            *(unsigned*)(UL + R1 * USTRIDE + col * 2) = lo;
        }
        __syncthreads();
    }

    // ---- GEMM3: dh = h2 @ uw3 + ub3 -> out (direct from accumulators) ----
    {
        float acc[4][4];
#pragma unroll
        for (int j = 0; j < 4; j++)
#pragma unroll
            for (int q = 0; q < 4; q++) acc[j][q] = 0.f;
        mma_passg<8, 8>(UH, UL, USTRIDE, g_wfu3, acc, wid, lane);
        float ts = g_misc[3];
        int nA = n0 + R0, nB = n0 + R1;
#pragma unroll
        for (int j = 0; j < 4; j++) {
            int col = ch * 32 + j * 8 + 2 * t;
            if (nA < NN) {
                float2 v = make_float2(ts * (acc[j][0] + b3s[col]),
                                       ts * (acc[j][1] + b3s[col + 1]));
                *(float2*)(out + nA * 64 + col) = v;
            }
            if (nB < NN) {
                float2 v = make_float2(ts * (acc[j][2] + b3s[col]),
                                       ts * (acc[j][3] + b3s[col + 1]));
                *(float2*)(out + nB * 64 + col) = v;
            }
        }
    }
}

// ---------------- launch ----------------
extern "C" void kernel_launch(void* const* d_in, const int* in_sizes, int n_in,
                              void* d_out, int out_size) {
    const float* coords   = (const float*)d_in[0];
    const float* h        = (const float*)d_in[1];
    const float* fdir     = (const float*)d_in[2];
    const int*   ei       = (const int*)d_in[3];
    const float* ln_g     = (const float*)d_in[4];
    const float* ln_b     = (const float*)d_in[5];
    const float* ew1      = (const float*)d_in[6];
    const float* eb1      = (const float*)d_in[7];
    const float* ew2      = (const float*)d_in[8];
    const float* eb2      = (const float*)d_in[9];
    const float* ew3      = (const float*)d_in[10];
    const float* eb3      = (const float*)d_in[11];
    const float* gw1      = (const float*)d_in[12];
    const float* gb1      = (const float*)d_in[13];
    const float* gw2      = (const float*)d_in[14];
    const float* gb2      = (const float*)d_in[15];
    const float* glw1     = (const float*)d_in[16];
    const float* glb1     = (const float*)d_in[17];
    const float* glw2     = (const float*)d_in[18];
    const float* glb2     = (const float*)d_in[19];
    const float* glw3     = (const float*)d_in[20];
    const float* glb3     = (const float*)d_in[21];
    const float* uw1      = (const float*)d_in[22];
    const float* ub1      = (const float*)d_in[23];
    const float* uw2      = (const float*)d_in[24];
    const float* ub2      = (const float*)d_in[25];
    const float* uw3      = (const float*)d_in[26];
    const float* ub3      = (const float*)d_in[27];
    const float* rscale   = (const float*)d_in[28];
    float* out = (float*)d_out;

    cudaFuncSetAttribute(k_edge, cudaFuncAttributeMaxDynamicSharedMemorySize,
                         SB_EDGE_BYTES);
    cudaFuncSetAttribute(k_update, cudaFuncAttributeMaxDynamicSharedMemorySize,
                         SU_BYTES);

    k_zero<<<2048, 256>>>();
    k_prep<<<32, 256>>>(ew1);
    {
        dim3 gdim(16, 3);
        k_prep_w<<<gdim, 256>>>(ew2, ew3, gw1);
    }
    k_prep_wu<<<48, 256>>>(uw1, uw2, uw3);
    k_lnorm<<<NN / 8, 128>>>(h, ln_g, ln_b);
    k_global<<<1, 64>>>(fdir, glw1, glb1, glw2, glb2, glw3, glb3, rscale, ub1, uw1);
    k_pq<<<(NN + 63) / 64, 256>>>();
    k_edge<<<EE / 64, 256, SB_EDGE_BYTES>>>(ei, coords,
        ew1, eb1, eb2, eb3, gb1, gw2, gb2);
    k_update<<<(NN + 63) / 64, 256, SU_BYTES>>>(ub2, ub3, out);
}

// round 11
// speedup vs baseline: 1.3569x; 1.0670x over previous
#include <cuda_runtime.h>
#include <cuda_bf16.h>

#define NN 50000
#define EE 800000
#define CC 64
#define MCC 128
#define NPAD 50048

typedef unsigned long long ull;

// ---------------- device scratch ----------------
__device__ __align__(16) float g_feat[NN * CC];
__device__ __align__(16) float g_agg[NN * MCC];
__device__ __align__(16) float g_deg[NN];
__device__ __align__(16) float g_gsum[CC];
__device__ __align__(16) float g_gctx[CC];
__device__ __align__(16) float g_misc[4];          // u0,u1,u2, tanh(res_scale)
__device__ __align__(16) float g_W1a[CC * MCC];
__device__ __align__(16) float g_W1b[CC * MCC];
__device__ __align__(16) float g_P[NPAD * MCC];
__device__ __align__(16) float g_Q[NPAD * MCC];
__device__ __align__(16) float g_ub1eff[MCC];
// mma.sync B fragments: [mat][ (s*16 + jg)*32 + lane ] = {bh0, bh1, bl0, bl1}
__device__ __align__(16) uint4 g_wfrag[3][4096];
// update-MLP weight fragments: uw1 (K=192,N=128), uw2 (128,128), uw3 (128,64)
__device__ __align__(16) uint4 g_wfu1[6144];
__device__ __align__(16) uint4 g_wfu2[4096];
__device__ __align__(16) uint4 g_wfu3[2048];
// P/Q weight fragments: W1a, W1b (K=64, N=128) -> 2048 each
__device__ __align__(16) uint4 g_wfpq[2][2048];

// ---------------- helpers ----------------
__device__ __forceinline__ float gelu_exact(float x) {
    return 0.5f * x * (1.0f + erff(x * 0.7071067811865476f));
}
__device__ __forceinline__ void split2(float a, float b, unsigned& hi, unsigned& lo) {
    __nv_bfloat162 h = __floats2bfloat162_rn(a, b);
    float ra = a - __bfloat162float(h.x);
    float rb = b - __bfloat162float(h.y);
    __nv_bfloat162 l = __floats2bfloat162_rn(ra, rb);
    hi = *(unsigned*)&h;
    lo = *(unsigned*)&l;
}

#define MMA_BF16(c, a0, a1, a2, a3, b0, b1) \
    asm volatile( \
        "mma.sync.aligned.m16n8k16.row.col.f32.bf16.bf16.f32 " \
        "{%0,%1,%2,%3}, {%4,%5,%6,%7}, {%8,%9}, {%0,%1,%2,%3};" \
        : "+f"((c)[0]), "+f"((c)[1]), "+f"((c)[2]), "+f"((c)[3]) \
        : "r"(a0), "r"(a1), "r"(a2), "r"(a3), "r"(b0), "r"(b1))

// ---------------- zero scratch ----------------
__global__ void k_zero() {
    int i = blockIdx.x * blockDim.x + threadIdx.x;
    int stride = gridDim.x * blockDim.x;
    float4 z = make_float4(0.f, 0.f, 0.f, 0.f);
    for (int j = i; j < NN * MCC / 4; j += stride) ((float4*)g_agg)[j] = z;
    for (int j = i; j < NN; j += stride) g_deg[j] = 0.f;
    if (i < CC) g_gsum[i] = 0.f;
}

// ---------------- weight prep ----------------
__global__ void k_prep(const float* __restrict__ ew1) {
    int i = blockIdx.x * blockDim.x + threadIdx.x;
    int stride = gridDim.x * blockDim.x;
    for (int j = i; j < CC * MCC; j += stride) {
        float wc = ew1[2 * CC * MCC + j];
        g_W1a[j] = ew1[j] + wc;
        g_W1b[j] = ew1[CC * MCC + j] - wc;
    }
}

// mma B-fragment pack for ew2, ew3, gw1 (bf16 hi/lo split)
__global__ void k_prep_w(const float* __restrict__ ew2,
                         const float* __restrict__ ew3,
                         const float* __restrict__ gw1) {
    int m = blockIdx.y;
    const float* W = (m == 0) ? ew2 : (m == 1) ? ew3 : gw1;
    int idx = blockIdx.x * blockDim.x + threadIdx.x;
    if (idx >= 4096) return;
    int lane = idx & 31;
    int jg = (idx >> 5) & 15;
    int s = idx >> 9;
    int n = jg * 8 + (lane >> 2);
    int k = s * 16 + (lane & 3) * 2;
    float w00 = W[k * 128 + n],       w01 = W[(k + 1) * 128 + n];
    float w80 = W[(k + 8) * 128 + n], w81 = W[(k + 9) * 128 + n];
    unsigned h0, l0, h8, l8;
    split2(w00, w01, h0, l0);
    split2(w80, w81, h8, l8);
    g_wfrag[m][idx] = make_uint4(h0, h8, l0, l8);
}

// fragment pack for update weights uw1/uw2/uw3
__global__ void k_prep_wu(const float* __restrict__ uw1,
                          const float* __restrict__ uw2,
                          const float* __restrict__ uw3) {
    int gidx = blockIdx.x * blockDim.x + threadIdx.x;
    if (gidx >= 12288) return;
    const float* W; uint4* dst; int idx, ldW, jgTot;
    if (gidx < 6144)       { W = uw1; dst = g_wfu1; idx = gidx;          ldW = 128; jgTot = 16; }
    else if (gidx < 10240) { W = uw2; dst = g_wfu2; idx = gidx - 6144;   ldW = 128; jgTot = 16; }
    else                   { W = uw3; dst = g_wfu3; idx = gidx - 10240;  ldW = 64;  jgTot = 8; }
    int lane = idx & 31;
    int jg = (idx >> 5) % jgTot;
    int s  = (idx >> 5) / jgTot;
    int n = jg * 8 + (lane >> 2);
    int k = s * 16 + (lane & 3) * 2;
    float w00 = W[k * ldW + n],       w01 = W[(k + 1) * ldW + n];
    float w80 = W[(k + 8) * ldW + n], w81 = W[(k + 9) * ldW + n];
    unsigned h0, l0, h8, l8;
    split2(w00, w01, h0, l0);
    split2(w80, w81, h8, l8);
    dst[idx] = make_uint4(h0, h8, l0, l8);
}

// fragment pack for P/Q weights (device-resident g_W1a/g_W1b, K=64, N=128)
__global__ void k_prep_wpq() {
    int gidx = blockIdx.x * blockDim.x + threadIdx.x;
    if (gidx >= 4096) return;
    int m = gidx >> 11;
    int idx = gidx & 2047;
    const float* W = m ? g_W1b : g_W1a;
    int lane = idx & 31;
    int jg = (idx >> 5) & 15;
    int s = idx >> 9;                 // 0..3  (K=64)
    int n = jg * 8 + (lane >> 2);
    int k = s * 16 + (lane & 3) * 2;
    float w00 = W[k * 128 + n],       w01 = W[(k + 1) * 128 + n];
    float w80 = W[(k + 8) * 128 + n], w81 = W[(k + 9) * 128 + n];
    unsigned h0, l0, h8, l8;
    split2(w00, w01, h0, l0);
    split2(w80, w81, h8, l8);
    g_wfpq[m][idx] = make_uint4(h0, h8, l0, l8);
}

// ---------------- layernorm (2 rows/warp ILP) + global column-sum partials ----------------
__global__ void k_lnorm(const float* __restrict__ h,
                        const float* __restrict__ lng,
                        const float* __restrict__ lnb) {
    __shared__ float cs[CC];
    int tid = threadIdx.x, lane = tid & 31, w = tid >> 5;
    int nA = blockIdx.x * 8 + w * 2, nB = nA + 1;
    float2 va = ((const float2*)h)[nA * 32 + lane];
    float2 vb = ((const float2*)h)[nB * 32 + lane];
    float sa = va.x + va.y, qa = va.x * va.x + va.y * va.y;
    float sb = vb.x + vb.y, qb = vb.x * vb.x + vb.y * vb.y;
#pragma unroll
    for (int o = 16; o; o >>= 1) {
        sa += __shfl_xor_sync(~0u, sa, o);
        qa += __shfl_xor_sync(~0u, qa, o);
        sb += __shfl_xor_sync(~0u, sb, o);
        qb += __shfl_xor_sync(~0u, qb, o);
    }
    float g0 = lng[2 * lane], g1 = lng[2 * lane + 1];
    float b0 = lnb[2 * lane], b1 = lnb[2 * lane + 1];
    float muA = sa * (1.f / 64.f);
    float rsA = rsqrtf(qa * (1.f / 64.f) - muA * muA + 1e-5f);
    float muB = sb * (1.f / 64.f);
    float rsB = rsqrtf(qb * (1.f / 64.f) - muB * muB + 1e-5f);
    float f0a = (va.x - muA) * rsA * g0 + b0;
    float f1a = (va.y - muA) * rsA * g1 + b1;
    float f0b = (vb.x - muB) * rsB * g0 + b0;
    float f1b = (vb.y - muB) * rsB * g1 + b1;
    ((float2*)g_feat)[nA * 32 + lane] = make_float2(f0a, f1a);
    ((float2*)g_feat)[nB * 32 + lane] = make_float2(f0b, f1b);
    if (tid < CC) cs[tid] = 0.f;
    __syncthreads();
    atomicAdd(&cs[2 * lane], f0a + f0b);
    atomicAdd(&cs[2 * lane + 1], f1a + f1b);
    __syncthreads();
    if (tid < CC) atomicAdd(&g_gsum[tid], cs[tid]);
}

// ---------------- tiny global MLP + misc + effective update bias ----------------
__global__ void k_global(const float* __restrict__ fdir,
                         const float* glw1, const float* glb1,
                         const float* glw2, const float* glb2,
                         const float* glw3, const float* glb3,
                         const float* res_scale,
                         const float* ub1, const float* uw1) {
    __shared__ float a0[CC], a1[CC], a2[CC];
    int t = threadIdx.x;
    if (t < CC) a0[t] = g_gsum[t] * (1.f / (float)NN);
    __syncthreads();
    if (t < CC) {
        float acc = glb1[t];
        for (int k = 0; k < CC; k++) acc += a0[k] * glw1[k * CC + t];
        a1[t] = gelu_exact(acc);
    }
    __syncthreads();
    if (t < CC) {
        float acc = glb2[t];
        for (int k = 0; k < CC; k++) acc += a1[k] * glw2[k * CC + t];
        a2[t] = gelu_exact(acc);
    }
    __syncthreads();
    if (t < CC) {
        float acc = glb3[t];
        for (int k = 0; k < CC; k++) acc += a2[k] * glw3[k * CC + t];
        g_gctx[t] = acc;
        a0[t] = acc;
    }
    __syncthreads();
    for (int c = t; c < MCC; c += CC) {
        float acc = ub1[c];
        for (int k = 0; k < CC; k++) acc += a0[k] * uw1[(192 + k) * MCC + c];
        g_ub1eff[c] = acc;
    }
    if (t == 0) {
        float u0 = fdir[0], u1 = fdir[1], u2 = fdir[2];
        float inv = 1.f / (sqrtf(u0 * u0 + u1 * u1 + u2 * u2) + 1e-8f);
        g_misc[0] = u0 * inv; g_misc[1] = u1 * inv; g_misc[2] = u2 * inv;
        g_misc[3] = tanhf(res_scale[0]);
    }
}

// ---------------- generic mma pass (64 rows, variable K / N) ----------------
// SS = K/16 s-steps; JGT = N/8 fragment groups total (split over 2 warp-halves).
template <int SS, int JGT>
__device__ __forceinline__ void mma_passg(const char* Ah, const char* Al, int ast,
                                          const uint4* __restrict__ Wf,
                                          float acc[][4], int wid, int lane) {
    const int r = wid & 3, ch = wid >> 2;
    const int g = lane >> 2, t = lane & 3;
    const int ro0 = (r * 16 + g) * ast;
    const int ro1 = ro0 + 8 * ast;
    constexpr int JC = JGT / 2;
#pragma unroll
    for (int s = 0; s < SS; s++) {
        const int cb = s * 32 + 4 * t;
        unsigned ah0 = *(const unsigned*)(Ah + ro0 + cb);
        unsigned ah1 = *(const unsigned*)(Ah + ro1 + cb);
        unsigned ah2 = *(const unsigned*)(Ah + ro0 + cb + 16);
        unsigned ah3 = *(const unsigned*)(Ah + ro1 + cb + 16);
        unsigned al0 = *(const unsigned*)(Al + ro0 + cb);
        unsigned al1 = *(const unsigned*)(Al + ro1 + cb);
        unsigned al2 = *(const unsigned*)(Al + ro0 + cb + 16);
        unsigned al3 = *(const unsigned*)(Al + ro1 + cb + 16);
        const uint4* wp = Wf + (s * JGT + ch * JC) * 32 + lane;
#pragma unroll
        for (int j = 0; j < JC; j++) {
            uint4 w = __ldg(wp + j * 32);
            MMA_BF16(acc[j], ah0, ah1, ah2, ah3, w.x, w.y);
            MMA_BF16(acc[j], ah0, ah1, ah2, ah3, w.z, w.w);
            MMA_BF16(acc[j], al0, al1, al2, al3, w.x, w.y);
        }
    }
}

// ---------------- P/Q node GEMMs via mma.sync ----------------
#define PSTRIDE 144

__global__ void __launch_bounds__(256) k_pq() {
    __shared__ __align__(16) char PH[64 * PSTRIDE];
    __shared__ __align__(16) char PL[64 * PSTRIDE];
    const int tid = threadIdx.x;
    const int wid = tid >> 5, lane = tid & 31;
    const int n0 = blockIdx.x * 64;

    // build split feat (K=64)
    for (int idx = tid; idx < 64 * 8; idx += 256) {
        int e = idx >> 3, c0 = (idx & 7) * 8;
        int n = n0 + e; if (n >= NN) n = NN - 1;
        const float* fr = g_feat + n * 64 + c0;
        unsigned hi[4], lo[4];
#pragma unroll
        for (int j = 0; j < 4; j++) split2(fr[2 * j], fr[2 * j + 1], hi[j], lo[j]);
        *(uint4*)(PH + e * PSTRIDE + c0 * 2) = make_uint4(hi[0], hi[1], hi[2], hi[3]);
        *(uint4*)(PL + e * PSTRIDE + c0 * 2) = make_uint4(lo[0], lo[1], lo[2], lo[3]);
    }
    __syncthreads();

    const int r = wid & 3, ch = wid >> 2;
    const int g = lane >> 2, t = lane & 3;
    const int R0 = r * 16 + g, R1 = R0 + 8;
    const int nA = n0 + R0, nB = n0 + R1;   // < NPAD always

    // P = feat @ W1a
    {
        float acc[8][4];
#pragma unroll
        for (int j = 0; j < 8; j++)
#pragma unroll
            for (int q = 0; q < 4; q++) acc[j][q] = 0.f;
        mma_passg<4, 16>(PH, PL, PSTRIDE, g_wfpq[0], acc, wid, lane);
#pragma unroll
        for (int j = 0; j < 8; j++) {
            int col = ch * 64 + j * 8 + 2 * t;
            *(float2*)(g_P + (size_t)nA * MCC + col) = make_float2(acc[j][0], acc[j][1]);
            *(float2*)(g_P + (size_t)nB * MCC + col) = make_float2(acc[j][2], acc[j][3]);
        }
    }
    // Q = feat @ W1b
    {
        float acc[8][4];
#pragma unroll
        for (int j = 0; j < 8; j++)
#pragma unroll
            for (int q = 0; q < 4; q++) acc[j][q] = 0.f;
        mma_passg<4, 16>(PH, PL, PSTRIDE, g_wfpq[1], acc, wid, lane);
#pragma unroll
        for (int j = 0; j < 8; j++) {
            int col = ch * 64 + j * 8 + 2 * t;
            *(float2*)(g_Q + (size_t)nA * MCC + col) = make_float2(acc[j][0], acc[j][1]);
            *(float2*)(g_Q + (size_t)nB * MCC + col) = make_float2(acc[j][2], acc[j][3]);
        }
    }
}

// ---------------- edge kernel: mma.sync bf16-split, 64-edge tiles ----------------
#define ASTRIDE 272
#define SB_AH   0
#define SB_AL   17408
#define SB_GEO  34816
#define SB_GP   35840
#define SB_GATE 36352
#define SB_EB2  36608
#define SB_EB3  37120
#define SB_GB1  37632
#define SB_GW2  38144
#define SB_EB1  38656
#define SB_WD   39168
#define SB_RS   41216
#define SB_CS   41472
#define SB_EDGE_BYTES 41728

__global__ void __launch_bounds__(256, 3) k_edge(
    const int* __restrict__ ei, const float* __restrict__ coords,
    const float* __restrict__ ew1, const float* __restrict__ eb1,
    const float* __restrict__ eb2, const float* __restrict__ eb3,
    const float* __restrict__ gb1, const float* __restrict__ gw2,
    const float* __restrict__ gb2) {
    extern __shared__ char sm[];
    char* Ah    = sm + SB_AH;
    char* Al    = sm + SB_AL;
    float* geo  = (float*)(sm + SB_GEO);
    float* gp   = (float*)(sm + SB_GP);
    float* gateS = (float*)(sm + SB_GATE);
    float* eb2s = (float*)(sm + SB_EB2);
    float* eb3s = (float*)(sm + SB_EB3);
    float* gb1s = (float*)(sm + SB_GB1);
    float* gw2s = (float*)(sm + SB_GW2);
    float* eb1s = (float*)(sm + SB_EB1);
    float* Wd   = (float*)(sm + SB_WD);
    int* rs = (int*)(sm + SB_RS);
    int* cs = (int*)(sm + SB_CS);

    const int tid = threadIdx.x;
    const int wid = tid >> 5, lane = tid & 31;
    const int e0 = blockIdx.x * 64;

    if (tid < 64) {
        rs[tid] = ei[e0 + tid];
        cs[tid] = ei[EE + e0 + tid];
    }
    if (tid < 128) {
        eb2s[tid] = eb2[tid];
        eb3s[tid] = eb3[tid];
        gb1s[tid] = gb1[tid];
        gw2s[tid] = gw2[tid];
        eb1s[tid] = eb1[tid];
    }
    for (int i = tid; i < 4 * 128; i += 256) Wd[i] = ew1[192 * 128 + i];
    __syncthreads();

    if (tid < 64) {
        int e = tid, r = rs[e], c = cs[e];
        float xi0 = coords[r * 3], xi1 = coords[r * 3 + 1], xi2 = coords[r * 3 + 2];
        float xj0 = coords[c * 3], xj1 = coords[c * 3 + 1], xj2 = coords[c * 3 + 2];
        float r0 = xi0 - xj0, r1 = xi1 - xj1, r2 = xi2 - xj2;
        float u0 = g_misc[0], u1 = g_misc[1], u2 = g_misc[2];
        geo[e * 4 + 0] = r0 * r0 + r1 * r1 + r2 * r2;
        geo[e * 4 + 1] = xi0 * u0 + xi1 * u1 + xi2 * u2;
        geo[e * 4 + 2] = xj0 * u0 + xj1 * u1 + xj2 * u2;
        geo[e * 4 + 3] = r0 * u0 + r1 * u1 + r2 * u2;
    }
    __syncthreads();

    // ---- build H1 = gelu(P[row] + Q[col] + geo@Wd + eb1) -> Ah/Al ----
    for (int idx = tid; idx < 64 * 16; idx += 256) {
        int e = idx >> 4, c0 = (idx & 15) * 8;
        const float* Pr = g_P + rs[e] * MCC + c0;
        const float* Qr = g_Q + cs[e] * MCC + c0;
        float4 p0 = *(const float4*)Pr, p1 = *(const float4*)(Pr + 4);
        float4 q0 = *(const float4*)Qr, q1 = *(const float4*)(Qr + 4);
        float ge0 = geo[e * 4], ge1 = geo[e * 4 + 1], ge2 = geo[e * 4 + 2], ge3 = geo[e * 4 + 3];
        float h[8];
#pragma unroll
        for (int j = 0; j < 8; j++) {
            int c = c0 + j;
            float pq = (j < 4) ? ((const float*)&p0)[j] + ((const float*)&q0)[j]
                               : ((const float*)&p1)[j - 4] + ((const float*)&q1)[j - 4];
            float v = pq + ge0 * Wd[c] + ge1 * Wd[128 + c] + ge2 * Wd[256 + c]
                    + ge3 * Wd[384 + c] + eb1s[c];
            h[j] = gelu_exact(v);
        }
        unsigned hi[4], lo[4];
#pragma unroll
        for (int j = 0; j < 4; j++) split2(h[2 * j], h[2 * j + 1], hi[j], lo[j]);
        *(uint4*)(Ah + e * ASTRIDE + c0 * 2) = make_uint4(hi[0], hi[1], hi[2], hi[3]);
        *(uint4*)(Al + e * ASTRIDE + c0 * 2) = make_uint4(lo[0], lo[1], lo[2], lo[3]);
    }
    __syncthreads();

    const int r = wid & 3, ch = wid >> 2;
    const int g = lane >> 2, t = lane & 3;
    const int R0 = r * 16 + g, R1 = R0 + 8;

    // ---- GEMM1: H2 = gelu(H1 @ ew2 + eb2) ----
    {
        float acc[8][4];
#pragma unroll
        for (int j = 0; j < 8; j++)
#pragma unroll
            for (int q = 0; q < 4; q++) acc[j][q] = 0.f;
        mma_passg<8, 16>(Ah, Al, ASTRIDE, g_wfrag[0], acc, wid, lane);
        __syncthreads();
#pragma unroll
        for (int j = 0; j < 8; j++) {
            int col = ch * 64 + j * 8 + 2 * t;
            float x0 = gelu_exact(acc[j][0] + eb2s[col]);
            float x1 = gelu_exact(acc[j][1] + eb2s[col + 1]);
            float x2 = gelu_exact(acc[j][2] + eb2s[col]);
            float x3 = gelu_exact(acc[j][3] + eb2s[col + 1]);
            unsigned hi, lo;
            split2(x0, x1, hi, lo);
            *(unsigned*)(Ah + R0 * ASTRIDE + col * 2) = hi;
            *(unsigned*)(Al + R0 * ASTRIDE + col * 2) = lo;
            split2(x2, x3, hi, lo);
            *(unsigned*)(Ah + R1 * ASTRIDE + col * 2) = hi;
            *(unsigned*)(Al + R1 * ASTRIDE + col * 2) = lo;
        }
        __syncthreads();
    }

    // ---- GEMM2: hidden = H2 @ ew3 + eb3 -> split to Ah/Al ----
    {
        float acc[8][4];
#pragma unroll
        for (int j = 0; j < 8; j++)
#pragma unroll
            for (int q = 0; q < 4; q++) acc[j][q] = 0.f;
        mma_passg<8, 16>(Ah, Al, ASTRIDE, g_wfrag[1], acc, wid, lane);
        __syncthreads();
#pragma unroll
        for (int j = 0; j < 8; j++) {
            int col = ch * 64 + j * 8 + 2 * t;
            float x0 = acc[j][0] + eb3s[col];
            float x1 = acc[j][1] + eb3s[col + 1];
            float x2 = acc[j][2] + eb3s[col];
            float x3 = acc[j][3] + eb3s[col + 1];
            unsigned hi, lo;
            split2(x0, x1, hi, lo);
            *(unsigned*)(Ah + R0 * ASTRIDE + col * 2) = hi;
            *(unsigned*)(Al + R0 * ASTRIDE + col * 2) = lo;
            split2(x2, x3, hi, lo);
            *(unsigned*)(Ah + R1 * ASTRIDE + col * 2) = hi;
            *(unsigned*)(Al + R1 * ASTRIDE + col * 2) = lo;
        }
        __syncthreads();
    }

    // ---- GEMM3: gate hidden = hidden @ gw1 + gb1 -> gelu -> dot gw2 ----
    {
        float acc[8][4];
#pragma unroll
        for (int j = 0; j < 8; j++)
#pragma unroll
            for (int q = 0; q < 4; q++) acc[j][q] = 0.f;
        mma_passg<8, 16>(Ah, Al, ASTRIDE, g_wfrag[2], acc, wid, lane);
        float p0 = 0.f, p1 = 0.f;
#pragma unroll
        for (int j = 0; j < 8; j++) {
            int col = ch * 64 + j * 8 + 2 * t;
            p0 += gw2s[col] * gelu_exact(acc[j][0] + gb1s[col])
                + gw2s[col + 1] * gelu_exact(acc[j][1] + gb1s[col + 1]);
            p1 += gw2s[col] * gelu_exact(acc[j][2] + gb1s[col])
                + gw2s[col + 1] * gelu_exact(acc[j][3] + gb1s[col + 1]);
        }
        p0 += __shfl_xor_sync(~0u, p0, 1);
        p0 += __shfl_xor_sync(~0u, p0, 2);
        p1 += __shfl_xor_sync(~0u, p1, 1);
        p1 += __shfl_xor_sync(~0u, p1, 2);
        if (t == 0) {
            gp[ch * 64 + R0] = p0;
            gp[ch * 64 + R1] = p1;
        }
        __syncthreads();
        if (tid < 64) {
            float a = gp[tid] + gp[64 + tid] + gb2[0];
            gateS[tid] = 1.f / (1.f + expf(-a));
        }
        __syncthreads();
    }

    // ---- scatter msg = gate * (hi + lo), vector red.add.v4.f32 ----
    for (int idx = tid; idx < 64 * 32; idx += 256) {
        int e = idx >> 5, c = (idx & 31) * 4;
        uint2 hu = *(const uint2*)(Ah + e * ASTRIDE + c * 2);
        uint2 lu = *(const uint2*)(Al + e * ASTRIDE + c * 2);
        float2 h0 = __bfloat1622float2(*(__nv_bfloat162*)&hu.x);
        float2 h1 = __bfloat1622float2(*(__nv_bfloat162*)&hu.y);
        float2 l0 = __bfloat1622float2(*(__nv_bfloat162*)&lu.x);
        float2 l1 = __bfloat1622float2(*(__nv_bfloat162*)&lu.y);
        float gt = gateS[e];
        float v0 = gt * (h0.x + l0.x);
        float v1 = gt * (h0.y + l0.y);
        float v2 = gt * (h1.x + l1.x);
        float v3 = gt * (h1.y + l1.y);
        float* dst = g_agg + (size_t)rs[e] * MCC + c;
        asm volatile("red.global.add.v4.f32 [%0], {%1, %2, %3, %4};"
                     :: "l"(dst), "f"(v0), "f"(v1), "f"(v2), "f"(v3) : "memory");
    }
    if (tid < 64) atomicAdd(&g_deg[rs[tid]], 1.f);
}

// ---------------- node update kernel: mma.sync bf16-split ----------------
// input K=192 rows stride 400B; intermediate K=128 stride 272B
#define USTRIDE 400
#define SU_UH   0
#define SU_UL   25600
#define SU_BH   51200
#define SU_BL   68608
#define SU_B1   86016
#define SU_B2   86528
#define SU_B3   87040
#define SU_DG   87296
#define SU_BYTES 87552

__global__ void __launch_bounds__(256, 2) k_update(
    const float* __restrict__ ub2, const float* __restrict__ ub3,
    float* __restrict__ out) {
    extern __shared__ char smu[];
    char* UH = smu + SU_UH;
    char* UL = smu + SU_UL;
    char* BH = smu + SU_BH;
    char* BL = smu + SU_BL;
    float* b1s = (float*)(smu + SU_B1);
    float* b2s = (float*)(smu + SU_B2);
    float* b3s = (float*)(smu + SU_B3);
    float* dg  = (float*)(smu + SU_DG);
    const int tid = threadIdx.x;
    const int wid = tid >> 5, lane = tid & 31;
    const int n0 = blockIdx.x * 64;

    if (tid < 128) { b1s[tid] = g_ub1eff[tid]; b2s[tid] = ub2[tid]; }
    if (tid < 64) {
        b3s[tid] = ub3[tid];
        int n = n0 + tid; if (n >= NN) n = NN - 1;
        float d = g_deg[n]; if (d < 1.f) d = 1.f;
        dg[tid] = 1.f / d;
    }
    __syncthreads();

    // build input: cols 0..63 feat, 64..191 agg/deg -> bf16 hi/lo
    for (int idx = tid; idx < 64 * 8; idx += 256) {
        int e = idx >> 3, c0 = (idx & 7) * 8;
        int n = n0 + e; if (n >= NN) n = NN - 1;
        const float* fr = g_feat + n * 64 + c0;
        unsigned hi[4], lo[4];
#pragma unroll
        for (int j = 0; j < 4; j++) split2(fr[2 * j], fr[2 * j + 1], hi[j], lo[j]);
        *(uint4*)(UH + e * USTRIDE + c0 * 2) = make_uint4(hi[0], hi[1], hi[2], hi[3]);
        *(uint4*)(UL + e * USTRIDE + c0 * 2) = make_uint4(lo[0], lo[1], lo[2], lo[3]);
    }
    for (int idx = tid; idx < 64 * 16; idx += 256) {
        int e = idx >> 4, cc = (idx & 15) * 8;
        int n = n0 + e; if (n >= NN) n = NN - 1;
        const float* ar = g_agg + (size_t)n * 128 + cc;
        float sc = dg[e];
        unsigned hi[4], lo[4];
#pragma unroll
        for (int j = 0; j < 4; j++)
            split2(ar[2 * j] * sc, ar[2 * j + 1] * sc, hi[j], lo[j]);
        int boff = (64 + cc) * 2;
        *(uint4*)(UH + e * USTRIDE + boff) = make_uint4(hi[0], hi[1], hi[2], hi[3]);
        *(uint4*)(UL + e * USTRIDE + boff) = make_uint4(lo[0], lo[1], lo[2], lo[3]);
    }
    __syncthreads();

    const int r = wid & 3, ch = wid >> 2;
    const int g = lane >> 2, t = lane & 3;
    const int R0 = r * 16 + g, R1 = R0 + 8;

    // ---- GEMM1: h1 = gelu(U @ uw1 + ub1eff) -> BH/BL ----
    {
        float acc[8][4];
#pragma unroll
        for (int j = 0; j < 8; j++)
#pragma unroll
            for (int q = 0; q < 4; q++) acc[j][q] = 0.f;
        mma_passg<12, 16>(UH, UL, USTRIDE, g_wfu1, acc, wid, lane);
#pragma unroll
        for (int j = 0; j < 8; j++) {
            int col = ch * 64 + j * 8 + 2 * t;
            float x0 = gelu_exact(acc[j][0] + b1s[col]);
            float x1 = gelu_exact(acc[j][1] + b1s[col + 1]);
            float x2 = gelu_exact(acc[j][2] + b1s[col]);
            float x3 = gelu_exact(acc[j][3] + b1s[col + 1]);
            unsigned hi, lo;
            split2(x0, x1, hi, lo);
            *(unsigned*)(BH + R0 * ASTRIDE + col * 2) = hi;
            *(unsigned*)(BL + R0 * ASTRIDE + col * 2) = lo;
            split2(x2, x3, hi, lo);
            *(unsigned*)(BH + R1 * ASTRIDE + col * 2) = hi;
            *(unsigned*)(BL + R1 * ASTRIDE + col * 2) = lo;
        }
        __syncthreads();
    }

    // ---- GEMM2: h2 = gelu(h1 @ uw2 + ub2) -> UH/UL (cols 0..127) ----
    {
        float acc[8][4];
#pragma unroll
        for (int j = 0; j < 8; j++)
#pragma unroll
            for (int q = 0; q < 4; q++) acc[j][q] = 0.f;
        mma_passg<8, 16>(BH, BL, ASTRIDE, g_wfu2, acc, wid, lane);
        __syncthreads();
#pragma unroll
        for (int j = 0; j < 8; j++) {
            int col = ch * 64 + j * 8 + 2 * t;
            float x0 = gelu_exact(acc[j][0] + b2s[col]);
            float x1 = gelu_exact(acc[j][1] + b2s[col + 1]);
            float x2 = gelu_exact(acc[j][2] + b2s[col]);
            float x3 = gelu_exact(acc[j][3] + b2s[col + 1]);
            unsigned hi, lo;
            split2(x0, x1, hi, lo);
            *(unsigned*)(UH + R0 * USTRIDE + col * 2) = hi;
            *(unsigned*)(UL + R0 * USTRIDE + col * 2) = lo;
            split2(x2, x3, hi, lo);
            *(unsigned*)(UH + R1 * USTRIDE + col * 2) = hi;
            *(unsigned*)(UL + R1 * USTRIDE + col * 2) = lo;
        }
        __syncthreads();
    }

    // ---- GEMM3: dh = h2 @ uw3 + ub3 -> out (direct from accumulators) ----
    {
        float acc[4][4];
#pragma unroll
        for (int j = 0; j < 4; j++)
#pragma unroll
            for (int q = 0; q < 4; q++) acc[j][q] = 0.f;
        mma_passg<8, 8>(UH, UL, USTRIDE, g_wfu3, acc, wid, lane);
        float ts = g_misc[3];
        int nA = n0 + R0, nB = n0 + R1;
#pragma unroll
        for (int j = 0; j < 4; j++) {
            int col = ch * 32 + j * 8 + 2 * t;
            if (nA < NN) {
                float2 v = make_float2(ts * (acc[j][0] + b3s[col]),
                                       ts * (acc[j][1] + b3s[col + 1]));
                *(float2*)(out + nA * 64 + col) = v;
            }
            if (nB < NN) {
                float2 v = make_float2(ts * (acc[j][2] + b3s[col]),
                                       ts * (acc[j][3] + b3s[col + 1]));
                *(float2*)(out + nB * 64 + col) = v;
            }
        }
    }
}

// ---------------- launch ----------------
extern "C" void kernel_launch(void* const* d_in, const int* in_sizes, int n_in,
                              void* d_out, int out_size) {
    const float* coords   = (const float*)d_in[0];
    const float* h        = (const float*)d_in[1];
    const float* fdir     = (const float*)d_in[2];
    const int*   ei       = (const int*)d_in[3];
    const float* ln_g     = (const float*)d_in[4];
    const float* ln_b     = (const float*)d_in[5];
    const float* ew1      = (const float*)d_in[6];
    const float* eb1      = (const float*)d_in[7];
    const float* ew2      = (const float*)d_in[8];
    const float* eb2      = (const float*)d_in[9];
    const float* ew3      = (const float*)d_in[10];
    const float* eb3      = (const float*)d_in[11];
    const float* gw1      = (const float*)d_in[12];
    const float* gb1      = (const float*)d_in[13];
    const float* gw2      = (const float*)d_in[14];
    const float* gb2      = (const float*)d_in[15];
    const float* glw1     = (const float*)d_in[16];
    const float* glb1     = (const float*)d_in[17];
    const float* glw2     = (const float*)d_in[18];
    const float* glb2     = (const float*)d_in[19];
    const float* glw3     = (const float*)d_in[20];
    const float* glb3     = (const float*)d_in[21];
    const float* uw1      = (const float*)d_in[22];
    const float* ub1      = (const float*)d_in[23];
    const float* uw2      = (const float*)d_in[24];
    const float* ub2      = (const float*)d_in[25];
    const float* uw3      = (const float*)d_in[26];
    const float* ub3      = (const float*)d_in[27];
    const float* rscale   = (const float*)d_in[28];
    float* out = (float*)d_out;

    cudaFuncSetAttribute(k_edge, cudaFuncAttributeMaxDynamicSharedMemorySize,
                         SB_EDGE_BYTES);
    cudaFuncSetAttribute(k_update, cudaFuncAttributeMaxDynamicSharedMemorySize,
                         SU_BYTES);

    k_zero<<<2048, 256>>>();
    k_prep<<<32, 256>>>(ew1);
    {
        dim3 gdim(16, 3);
        k_prep_w<<<gdim, 256>>>(ew2, ew3, gw1);
    }
    k_prep_wu<<<48, 256>>>(uw1, uw2, uw3);
    k_prep_wpq<<<16, 256>>>();
    k_lnorm<<<NN / 8, 128>>>(h, ln_g, ln_b);
    k_global<<<1, 64>>>(fdir, glw1, glb1, glw2, glb2, glw3, glb3, rscale, ub1, uw1);
    k_pq<<<NPAD / 64, 256>>>();
    k_edge<<<EE / 64, 256, SB_EDGE_BYTES>>>(ei, coords,
        ew1, eb1, eb2, eb3, gb1, gw2, gb2);
    k_update<<<(NN + 63) / 64, 256, SU_BYTES>>>(ub2, ub3, out);
}

// round 12
// speedup vs baseline: 1.4245x; 1.0498x over previous
#include <cuda_runtime.h>
#include <cuda_bf16.h>

#define NN 50000
#define EE 800000
#define CC 64
#define MCC 128
#define NPAD 50048

typedef unsigned long long ull;

// ---------------- device scratch ----------------
__device__ __align__(16) float g_feat[NN * CC];
__device__ __align__(16) float g_agg[NN * MCC];
__device__ __align__(16) float g_deg[NN];
__device__ __align__(16) float g_gsum[CC];
__device__ __align__(16) float g_gctx[CC];
__device__ __align__(16) float g_misc[4];          // u0,u1,u2, tanh(res_scale)
__device__ __align__(16) float g_W1a[CC * MCC];
__device__ __align__(16) float g_W1b[CC * MCC];
__device__ __align__(16) float g_P[NPAD * MCC];
__device__ __align__(16) float g_Q[NPAD * MCC];
__device__ __align__(16) float g_ub1eff[MCC];
// mma.sync B fragments: [mat][ (s*16 + jg)*32 + lane ] = {bh0, bh1, bl0, bl1}
__device__ __align__(16) uint4 g_wfrag[3][4096];
// update-MLP weight fragments: uw1 (K=192,N=128), uw2 (128,128), uw3 (128,64)
__device__ __align__(16) uint4 g_wfu1[6144];
__device__ __align__(16) uint4 g_wfu2[4096];
__device__ __align__(16) uint4 g_wfu3[2048];
// P/Q weight fragments: W1a, W1b (K=64, N=128) -> 2048 each
__device__ __align__(16) uint4 g_wfpq[2][2048];

// ---------------- helpers ----------------
__device__ __forceinline__ float gelu_exact(float x) {
    return 0.5f * x * (1.0f + erff(x * 0.7071067811865476f));
}
__device__ __forceinline__ void split2(float a, float b, unsigned& hi, unsigned& lo) {
    __nv_bfloat162 h = __floats2bfloat162_rn(a, b);
    float ra = a - __bfloat162float(h.x);
    float rb = b - __bfloat162float(h.y);
    __nv_bfloat162 l = __floats2bfloat162_rn(ra, rb);
    hi = *(unsigned*)&h;
    lo = *(unsigned*)&l;
}

#define MMA_BF16(c, a0, a1, a2, a3, b0, b1) \
    asm volatile( \
        "mma.sync.aligned.m16n8k16.row.col.f32.bf16.bf16.f32 " \
        "{%0,%1,%2,%3}, {%4,%5,%6,%7}, {%8,%9}, {%0,%1,%2,%3};" \
        : "+f"((c)[0]), "+f"((c)[1]), "+f"((c)[2]), "+f"((c)[3]) \
        : "r"(a0), "r"(a1), "r"(a2), "r"(a3), "r"(b0), "r"(b1))

// ---------------- zero scratch ----------------
__global__ void k_zero() {
    int i = blockIdx.x * blockDim.x + threadIdx.x;
    int stride = gridDim.x * blockDim.x;
    float4 z = make_float4(0.f, 0.f, 0.f, 0.f);
    for (int j = i; j < NN * MCC / 4; j += stride) ((float4*)g_agg)[j] = z;
    for (int j = i; j < NN; j += stride) g_deg[j] = 0.f;
    if (i < CC) g_gsum[i] = 0.f;
}

// ---------------- weight prep ----------------
__global__ void k_prep(const float* __restrict__ ew1) {
    int i = blockIdx.x * blockDim.x + threadIdx.x;
    int stride = gridDim.x * blockDim.x;
    for (int j = i; j < CC * MCC; j += stride) {
        float wc = ew1[2 * CC * MCC + j];
        g_W1a[j] = ew1[j] + wc;
        g_W1b[j] = ew1[CC * MCC + j] - wc;
    }
}

// mma B-fragment pack for ew2, ew3, gw1 (bf16 hi/lo split)
__global__ void k_prep_w(const float* __restrict__ ew2,
                         const float* __restrict__ ew3,
                         const float* __restrict__ gw1) {
    int m = blockIdx.y;
    const float* W = (m == 0) ? ew2 : (m == 1) ? ew3 : gw1;
    int idx = blockIdx.x * blockDim.x + threadIdx.x;
    if (idx >= 4096) return;
    int lane = idx & 31;
    int jg = (idx >> 5) & 15;
    int s = idx >> 9;
    int n = jg * 8 + (lane >> 2);
    int k = s * 16 + (lane & 3) * 2;
    float w00 = W[k * 128 + n],       w01 = W[(k + 1) * 128 + n];
    float w80 = W[(k + 8) * 128 + n], w81 = W[(k + 9) * 128 + n];
    unsigned h0, l0, h8, l8;
    split2(w00, w01, h0, l0);
    split2(w80, w81, h8, l8);
    g_wfrag[m][idx] = make_uint4(h0, h8, l0, l8);
}

// fragment pack for update weights uw1/uw2/uw3
__global__ void k_prep_wu(const float* __restrict__ uw1,
                          const float* __restrict__ uw2,
                          const float* __restrict__ uw3) {
    int gidx = blockIdx.x * blockDim.x + threadIdx.x;
    if (gidx >= 12288) return;
    const float* W; uint4* dst; int idx, ldW, jgTot;
    if (gidx < 6144)       { W = uw1; dst = g_wfu1; idx = gidx;          ldW = 128; jgTot = 16; }
    else if (gidx < 10240) { W = uw2; dst = g_wfu2; idx = gidx - 6144;   ldW = 128; jgTot = 16; }
    else                   { W = uw3; dst = g_wfu3; idx = gidx - 10240;  ldW = 64;  jgTot = 8; }
    int lane = idx & 31;
    int jg = (idx >> 5) % jgTot;
    int s  = (idx >> 5) / jgTot;
    int n = jg * 8 + (lane >> 2);
    int k = s * 16 + (lane & 3) * 2;
    float w00 = W[k * ldW + n],       w01 = W[(k + 1) * ldW + n];
    float w80 = W[(k + 8) * ldW + n], w81 = W[(k + 9) * ldW + n];
    unsigned h0, l0, h8, l8;
    split2(w00, w01, h0, l0);
    split2(w80, w81, h8, l8);
    dst[idx] = make_uint4(h0, h8, l0, l8);
}

// fragment pack for P/Q weights (device-resident g_W1a/g_W1b, K=64, N=128)
__global__ void k_prep_wpq() {
    int gidx = blockIdx.x * blockDim.x + threadIdx.x;
    if (gidx >= 4096) return;
    int m = gidx >> 11;
    int idx = gidx & 2047;
    const float* W = m ? g_W1b : g_W1a;
    int lane = idx & 31;
    int jg = (idx >> 5) & 15;
    int s = idx >> 9;                 // 0..3  (K=64)
    int n = jg * 8 + (lane >> 2);
    int k = s * 16 + (lane & 3) * 2;
    float w00 = W[k * 128 + n],       w01 = W[(k + 1) * 128 + n];
    float w80 = W[(k + 8) * 128 + n], w81 = W[(k + 9) * 128 + n];
    unsigned h0, l0, h8, l8;
    split2(w00, w01, h0, l0);
    split2(w80, w81, h8, l8);
    g_wfpq[m][idx] = make_uint4(h0, h8, l0, l8);
}

// ---------------- tiny global MLP + misc + effective update bias ----------------
__global__ void k_global(const float* __restrict__ fdir,
                         const float* glw1, const float* glb1,
                         const float* glw2, const float* glb2,
                         const float* glw3, const float* glb3,
                         const float* res_scale,
                         const float* ub1, const float* uw1) {
    __shared__ float a0[CC], a1[CC], a2[CC];
    int t = threadIdx.x;
    if (t < CC) a0[t] = g_gsum[t] * (1.f / (float)NN);
    __syncthreads();
    if (t < CC) {
        float acc = glb1[t];
        for (int k = 0; k < CC; k++) acc += a0[k] * glw1[k * CC + t];
        a1[t] = gelu_exact(acc);
    }
    __syncthreads();
    if (t < CC) {
        float acc = glb2[t];
        for (int k = 0; k < CC; k++) acc += a1[k] * glw2[k * CC + t];
        a2[t] = gelu_exact(acc);
    }
    __syncthreads();
    if (t < CC) {
        float acc = glb3[t];
        for (int k = 0; k < CC; k++) acc += a2[k] * glw3[k * CC + t];
        g_gctx[t] = acc;
        a0[t] = acc;
    }
    __syncthreads();
    for (int c = t; c < MCC; c += CC) {
        float acc = ub1[c];
        for (int k = 0; k < CC; k++) acc += a0[k] * uw1[(192 + k) * MCC + c];
        g_ub1eff[c] = acc;
    }
    if (t == 0) {
        float u0 = fdir[0], u1 = fdir[1], u2 = fdir[2];
        float inv = 1.f / (sqrtf(u0 * u0 + u1 * u1 + u2 * u2) + 1e-8f);
        g_misc[0] = u0 * inv; g_misc[1] = u1 * inv; g_misc[2] = u2 * inv;
        g_misc[3] = tanhf(res_scale[0]);
    }
}

// ---------------- generic mma pass (64 rows, variable K / N) ----------------
// SS = K/16 s-steps; JGT = N/8 fragment groups total (split over 2 warp-halves).
// LO = include the input-lo correction pass (Al*Wh).
template <int SS, int JGT, bool LO = true>
__device__ __forceinline__ void mma_passg(const char* Ah, const char* Al, int ast,
                                          const uint4* __restrict__ Wf,
                                          float acc[][4], int wid, int lane) {
    const int r = wid & 3, ch = wid >> 2;
    const int g = lane >> 2, t = lane & 3;
    const int ro0 = (r * 16 + g) * ast;
    const int ro1 = ro0 + 8 * ast;
    constexpr int JC = JGT / 2;
#pragma unroll
    for (int s = 0; s < SS; s++) {
        const int cb = s * 32 + 4 * t;
        unsigned ah0 = *(const unsigned*)(Ah + ro0 + cb);
        unsigned ah1 = *(const unsigned*)(Ah + ro1 + cb);
        unsigned ah2 = *(const unsigned*)(Ah + ro0 + cb + 16);
        unsigned ah3 = *(const unsigned*)(Ah + ro1 + cb + 16);
        unsigned al0 = 0, al1 = 0, al2 = 0, al3 = 0;
        if (LO) {
            al0 = *(const unsigned*)(Al + ro0 + cb);
            al1 = *(const unsigned*)(Al + ro1 + cb);
            al2 = *(const unsigned*)(Al + ro0 + cb + 16);
            al3 = *(const unsigned*)(Al + ro1 + cb + 16);
        }
        const uint4* wp = Wf + (s * JGT + ch * JC) * 32 + lane;
#pragma unroll
        for (int j = 0; j < JC; j++) {
            uint4 w = __ldg(wp + j * 32);
            MMA_BF16(acc[j], ah0, ah1, ah2, ah3, w.x, w.y);
            MMA_BF16(acc[j], ah0, ah1, ah2, ah3, w.z, w.w);
            if (LO) MMA_BF16(acc[j], al0, al1, al2, al3, w.x, w.y);
        }
    }
}

// ---------------- fused layernorm + P/Q node GEMMs ----------------
#define PSTRIDE 144

__global__ void __launch_bounds__(256) k_pq(const float* __restrict__ h,
                                            const float* __restrict__ lng,
                                            const float* __restrict__ lnb) {
    __shared__ __align__(16) char PH[64 * PSTRIDE];
    __shared__ __align__(16) char PL[64 * PSTRIDE];
    __shared__ float cs[CC];
    const int tid = threadIdx.x;
    const int wid = tid >> 5, lane = tid & 31;
    const int n0 = blockIdx.x * 64;

    if (tid < CC) cs[tid] = 0.f;
    __syncthreads();

    const float lg0 = lng[2 * lane], lg1 = lng[2 * lane + 1];
    const float lb0 = lnb[2 * lane], lb1 = lnb[2 * lane + 1];
    float ca = 0.f, cb = 0.f;

#pragma unroll
    for (int i = 0; i < 4; i++) {
        int e = wid * 8 + i * 2;
        int nA = n0 + e, nB = nA + 1;
        int rA = (nA < NN) ? nA : NN - 1;
        int rB = (nB < NN) ? nB : NN - 1;
        float2 va = ((const float2*)h)[rA * 32 + lane];
        float2 vb = ((const float2*)h)[rB * 32 + lane];
        float sa = va.x + va.y, qa = va.x * va.x + va.y * va.y;
        float sb = vb.x + vb.y, qb = vb.x * vb.x + vb.y * vb.y;
#pragma unroll
        for (int o = 16; o; o >>= 1) {
            sa += __shfl_xor_sync(~0u, sa, o);
            qa += __shfl_xor_sync(~0u, qa, o);
            sb += __shfl_xor_sync(~0u, sb, o);
            qb += __shfl_xor_sync(~0u, qb, o);
        }
        float muA = sa * (1.f / 64.f);
        float rsA = rsqrtf(qa * (1.f / 64.f) - muA * muA + 1e-5f);
        float muB = sb * (1.f / 64.f);
        float rsB = rsqrtf(qb * (1.f / 64.f) - muB * muB + 1e-5f);
        float f0a = (va.x - muA) * rsA * lg0 + lb0;
        float f1a = (va.y - muA) * rsA * lg1 + lb1;
        float f0b = (vb.x - muB) * rsB * lg0 + lb0;
        float f1b = (vb.y - muB) * rsB * lg1 + lb1;
        ((float2*)g_feat)[rA * 32 + lane] = make_float2(f0a, f1a);
        ((float2*)g_feat)[rB * 32 + lane] = make_float2(f0b, f1b);
        if (nA < NN) { ca += f0a; cb += f1a; }
        if (nB < NN) { ca += f0b; cb += f1b; }
        unsigned hi, lo;
        split2(f0a, f1a, hi, lo);
        *(unsigned*)(PH + e * PSTRIDE + lane * 4) = hi;
        *(unsigned*)(PL + e * PSTRIDE + lane * 4) = lo;
        split2(f0b, f1b, hi, lo);
        *(unsigned*)(PH + (e + 1) * PSTRIDE + lane * 4) = hi;
        *(unsigned*)(PL + (e + 1) * PSTRIDE + lane * 4) = lo;
    }
    atomicAdd(&cs[2 * lane], ca);
    atomicAdd(&cs[2 * lane + 1], cb);
    __syncthreads();
    if (tid < CC) atomicAdd(&g_gsum[tid], cs[tid]);

    const int r = wid & 3, ch = wid >> 2;
    const int g = lane >> 2, t = lane & 3;
    const int R0 = r * 16 + g, R1 = R0 + 8;
    const int nA = n0 + R0, nB = n0 + R1;   // < NPAD always

    // P = feat @ W1a
    {
        float acc[8][4];
#pragma unroll
        for (int j = 0; j < 8; j++)
#pragma unroll
            for (int q = 0; q < 4; q++) acc[j][q] = 0.f;
        mma_passg<4, 16>(PH, PL, PSTRIDE, g_wfpq[0], acc, wid, lane);
#pragma unroll
        for (int j = 0; j < 8; j++) {
            int col = ch * 64 + j * 8 + 2 * t;
            *(float2*)(g_P + (size_t)nA * MCC + col) = make_float2(acc[j][0], acc[j][1]);
            *(float2*)(g_P + (size_t)nB * MCC + col) = make_float2(acc[j][2], acc[j][3]);
        }
    }
    // Q = feat @ W1b
    {
        float acc[8][4];
#pragma unroll
        for (int j = 0; j < 8; j++)
#pragma unroll
            for (int q = 0; q < 4; q++) acc[j][q] = 0.f;
        mma_passg<4, 16>(PH, PL, PSTRIDE, g_wfpq[1], acc, wid, lane);
#pragma unroll
        for (int j = 0; j < 8; j++) {
            int col = ch * 64 + j * 8 + 2 * t;
            *(float2*)(g_Q + (size_t)nA * MCC + col) = make_float2(acc[j][0], acc[j][1]);
            *(float2*)(g_Q + (size_t)nB * MCC + col) = make_float2(acc[j][2], acc[j][3]);
        }
    }
}

// ---------------- edge kernel: mma.sync bf16-split, 64-edge tiles ----------------
#define ASTRIDE 272
#define SB_AH   0
#define SB_AL   17408
#define SB_GEO  34816
#define SB_GP   35840
#define SB_GATE 36352
#define SB_EB2  36608
#define SB_EB3  37120
#define SB_GB1  37632
#define SB_GW2  38144
#define SB_EB1  38656
#define SB_WD   39168
#define SB_RS   41216
#define SB_CS   41472
#define SB_EDGE_BYTES 41728

__global__ void __launch_bounds__(256, 3) k_edge(
    const int* __restrict__ ei, const float* __restrict__ coords,
    const float* __restrict__ ew1, const float* __restrict__ eb1,
    const float* __restrict__ eb2, const float* __restrict__ eb3,
    const float* __restrict__ gb1, const float* __restrict__ gw2,
    const float* __restrict__ gb2) {
    extern __shared__ char sm[];
    char* Ah    = sm + SB_AH;
    char* Al    = sm + SB_AL;
    float* geo  = (float*)(sm + SB_GEO);
    float* gp   = (float*)(sm + SB_GP);
    float* gateS = (float*)(sm + SB_GATE);
    float* eb2s = (float*)(sm + SB_EB2);
    float* eb3s = (float*)(sm + SB_EB3);
    float* gb1s = (float*)(sm + SB_GB1);
    float* gw2s = (float*)(sm + SB_GW2);
    float* eb1s = (float*)(sm + SB_EB1);
    float* Wd   = (float*)(sm + SB_WD);
    int* rs = (int*)(sm + SB_RS);
    int* cs = (int*)(sm + SB_CS);

    const int tid = threadIdx.x;
    const int wid = tid >> 5, lane = tid & 31;
    const int e0 = blockIdx.x * 64;

    if (tid < 64) {
        rs[tid] = ei[e0 + tid];
        cs[tid] = ei[EE + e0 + tid];
    }
    if (tid < 128) {
        eb2s[tid] = eb2[tid];
        eb3s[tid] = eb3[tid];
        gb1s[tid] = gb1[tid];
        gw2s[tid] = gw2[tid];
        eb1s[tid] = eb1[tid];
    }
    for (int i = tid; i < 4 * 128; i += 256) Wd[i] = ew1[192 * 128 + i];
    __syncthreads();

    if (tid < 64) {
        int e = tid, r = rs[e], c = cs[e];
        float xi0 = coords[r * 3], xi1 = coords[r * 3 + 1], xi2 = coords[r * 3 + 2];
        float xj0 = coords[c * 3], xj1 = coords[c * 3 + 1], xj2 = coords[c * 3 + 2];
        float r0 = xi0 - xj0, r1 = xi1 - xj1, r2 = xi2 - xj2;
        float u0 = g_misc[0], u1 = g_misc[1], u2 = g_misc[2];
        geo[e * 4 + 0] = r0 * r0 + r1 * r1 + r2 * r2;
        geo[e * 4 + 1] = xi0 * u0 + xi1 * u1 + xi2 * u2;
        geo[e * 4 + 2] = xj0 * u0 + xj1 * u1 + xj2 * u2;
        geo[e * 4 + 3] = r0 * u0 + r1 * u1 + r2 * u2;
    }
    __syncthreads();

    // ---- build H1 = gelu(P[row] + Q[col] + geo@Wd + eb1) -> Ah/Al ----
    for (int idx = tid; idx < 64 * 16; idx += 256) {
        int e = idx >> 4, c0 = (idx & 15) * 8;
        const float* Pr = g_P + rs[e] * MCC + c0;
        const float* Qr = g_Q + cs[e] * MCC + c0;
        float4 p0 = *(const float4*)Pr, p1 = *(const float4*)(Pr + 4);
        float4 q0 = *(const float4*)Qr, q1 = *(const float4*)(Qr + 4);
        float ge0 = geo[e * 4], ge1 = geo[e * 4 + 1], ge2 = geo[e * 4 + 2], ge3 = geo[e * 4 + 3];
        float h[8];
#pragma unroll
        for (int j = 0; j < 8; j++) {
            int c = c0 + j;
            float pq = (j < 4) ? ((const float*)&p0)[j] + ((const float*)&q0)[j]
                               : ((const float*)&p1)[j - 4] + ((const float*)&q1)[j - 4];
            float v = pq + ge0 * Wd[c] + ge1 * Wd[128 + c] + ge2 * Wd[256 + c]
                    + ge3 * Wd[384 + c] + eb1s[c];
            h[j] = gelu_exact(v);
        }
        unsigned hi[4], lo[4];
#pragma unroll
        for (int j = 0; j < 4; j++) split2(h[2 * j], h[2 * j + 1], hi[j], lo[j]);
        *(uint4*)(Ah + e * ASTRIDE + c0 * 2) = make_uint4(hi[0], hi[1], hi[2], hi[3]);
        *(uint4*)(Al + e * ASTRIDE + c0 * 2) = make_uint4(lo[0], lo[1], lo[2], lo[3]);
    }
    __syncthreads();

    const int r = wid & 3, ch = wid >> 2;
    const int g = lane >> 2, t = lane & 3;
    const int R0 = r * 16 + g, R1 = R0 + 8;

    // ---- GEMM1: H2 = gelu(H1 @ ew2 + eb2) ----
    {
        float acc[8][4];
#pragma unroll
        for (int j = 0; j < 8; j++)
#pragma unroll
            for (int q = 0; q < 4; q++) acc[j][q] = 0.f;
        mma_passg<8, 16>(Ah, Al, ASTRIDE, g_wfrag[0], acc, wid, lane);
        __syncthreads();
#pragma unroll
        for (int j = 0; j < 8; j++) {
            int col = ch * 64 + j * 8 + 2 * t;
            float x0 = gelu_exact(acc[j][0] + eb2s[col]);
            float x1 = gelu_exact(acc[j][1] + eb2s[col + 1]);
            float x2 = gelu_exact(acc[j][2] + eb2s[col]);
            float x3 = gelu_exact(acc[j][3] + eb2s[col + 1]);
            unsigned hi, lo;
            split2(x0, x1, hi, lo);
            *(unsigned*)(Ah + R0 * ASTRIDE + col * 2) = hi;
            *(unsigned*)(Al + R0 * ASTRIDE + col * 2) = lo;
            split2(x2, x3, hi, lo);
            *(unsigned*)(Ah + R1 * ASTRIDE + col * 2) = hi;
            *(unsigned*)(Al + R1 * ASTRIDE + col * 2) = lo;
        }
        __syncthreads();
    }

    // ---- GEMM2: hidden = H2 @ ew3 + eb3 -> split to Ah/Al ----
    {
        float acc[8][4];
#pragma unroll
        for (int j = 0; j < 8; j++)
#pragma unroll
            for (int q = 0; q < 4; q++) acc[j][q] = 0.f;
        mma_passg<8, 16>(Ah, Al, ASTRIDE, g_wfrag[1], acc, wid, lane);
        __syncthreads();
#pragma unroll
        for (int j = 0; j < 8; j++) {
            int col = ch * 64 + j * 8 + 2 * t;
            float x0 = acc[j][0] + eb3s[col];
            float x1 = acc[j][1] + eb3s[col + 1];
            float x2 = acc[j][2] + eb3s[col];
            float x3 = acc[j][3] + eb3s[col + 1];
            unsigned hi, lo;
            split2(x0, x1, hi, lo);
            *(unsigned*)(Ah + R0 * ASTRIDE + col * 2) = hi;
            *(unsigned*)(Al + R0 * ASTRIDE + col * 2) = lo;
            split2(x2, x3, hi, lo);
            *(unsigned*)(Ah + R1 * ASTRIDE + col * 2) = hi;
            *(unsigned*)(Al + R1 * ASTRIDE + col * 2) = lo;
        }
        __syncthreads();
    }

    // ---- GEMM3: gate (hi-only 2-pass: sigmoid tolerates input-lo truncation) ----
    {
        float acc[8][4];
#pragma unroll
        for (int j = 0; j < 8; j++)
#pragma unroll
            for (int q = 0; q < 4; q++) acc[j][q] = 0.f;
        mma_passg<8, 16, false>(Ah, Al, ASTRIDE, g_wfrag[2], acc, wid, lane);
        float p0 = 0.f, p1 = 0.f;
#pragma unroll
        for (int j = 0; j < 8; j++) {
            int col = ch * 64 + j * 8 + 2 * t;
            p0 += gw2s[col] * gelu_exact(acc[j][0] + gb1s[col])
                + gw2s[col + 1] * gelu_exact(acc[j][1] + gb1s[col + 1]);
            p1 += gw2s[col] * gelu_exact(acc[j][2] + gb1s[col])
                + gw2s[col + 1] * gelu_exact(acc[j][3] + gb1s[col + 1]);
        }
        p0 += __shfl_xor_sync(~0u, p0, 1);
        p0 += __shfl_xor_sync(~0u, p0, 2);
        p1 += __shfl_xor_sync(~0u, p1, 1);
        p1 += __shfl_xor_sync(~0u, p1, 2);
        if (t == 0) {
            gp[ch * 64 + R0] = p0;
            gp[ch * 64 + R1] = p1;
        }
        __syncthreads();
        if (tid < 64) {
            float a = gp[tid] + gp[64 + tid] + gb2[0];
            gateS[tid] = 1.f / (1.f + expf(-a));
        }
        __syncthreads();
    }

    // ---- scatter msg = gate * (hi + lo), vector red.add.v4.f32 ----
    for (int idx = tid; idx < 64 * 32; idx += 256) {
        int e = idx >> 5, c = (idx & 31) * 4;
        uint2 hu = *(const uint2*)(Ah + e * ASTRIDE + c * 2);
        uint2 lu = *(const uint2*)(Al + e * ASTRIDE + c * 2);
        float2 h0 = __bfloat1622float2(*(__nv_bfloat162*)&hu.x);
        float2 h1 = __bfloat1622float2(*(__nv_bfloat162*)&hu.y);
        float2 l0 = __bfloat1622float2(*(__nv_bfloat162*)&lu.x);
        float2 l1 = __bfloat1622float2(*(__nv_bfloat162*)&lu.y);
        float gt = gateS[e];
        float v0 = gt * (h0.x + l0.x);
        float v1 = gt * (h0.y + l0.y);
        float v2 = gt * (h1.x + l1.x);
        float v3 = gt * (h1.y + l1.y);
        float* dst = g_agg + (size_t)rs[e] * MCC + c;
        asm volatile("red.global.add.v4.f32 [%0], {%1, %2, %3, %4};"
                     :: "l"(dst), "f"(v0), "f"(v1), "f"(v2), "f"(v3) : "memory");
    }
    if (tid < 64) atomicAdd(&g_deg[rs[tid]], 1.f);
}

// ---------------- node update kernel: mma.sync bf16-split ----------------
// input K=192 rows stride 400B; intermediate K=128 stride 272B
#define USTRIDE 400
#define SU_UH   0
#define SU_UL   25600
#define SU_BH   51200
#define SU_BL   68608
#define SU_B1   86016
#define SU_B2   86528
#define SU_B3   87040
#define SU_DG   87296
#define SU_BYTES 87552

__global__ void __launch_bounds__(256, 2) k_update(
    const float* __restrict__ ub2, const float* __restrict__ ub3,
    float* __restrict__ out) {
    extern __shared__ char smu[];
    char* UH = smu + SU_UH;
    char* UL = smu + SU_UL;
    char* BH = smu + SU_BH;
    char* BL = smu + SU_BL;
    float* b1s = (float*)(smu + SU_B1);
    float* b2s = (float*)(smu + SU_B2);
    float* b3s = (float*)(smu + SU_B3);
    float* dg  = (float*)(smu + SU_DG);
    const int tid = threadIdx.x;
    const int wid = tid >> 5, lane = tid & 31;
    const int n0 = blockIdx.x * 64;

    if (tid < 128) { b1s[tid] = g_ub1eff[tid]; b2s[tid] = ub2[tid]; }
    if (tid < 64) {
        b3s[tid] = ub3[tid];
        int n = n0 + tid; if (n >= NN) n = NN - 1;
        float d = g_deg[n]; if (d < 1.f) d = 1.f;
        dg[tid] = 1.f / d;
    }
    __syncthreads();

    // build input: cols 0..63 feat, 64..191 agg/deg -> bf16 hi/lo
    for (int idx = tid; idx < 64 * 8; idx += 256) {
        int e = idx >> 3, c0 = (idx & 7) * 8;
        int n = n0 + e; if (n >= NN) n = NN - 1;
        const float* fr = g_feat + n * 64 + c0;
        unsigned hi[4], lo[4];
#pragma unroll
        for (int j = 0; j < 4; j++) split2(fr[2 * j], fr[2 * j + 1], hi[j], lo[j]);
        *(uint4*)(UH + e * USTRIDE + c0 * 2) = make_uint4(hi[0], hi[1], hi[2], hi[3]);
        *(uint4*)(UL + e * USTRIDE + c0 * 2) = make_uint4(lo[0], lo[1], lo[2], lo[3]);
    }
    for (int idx = tid; idx < 64 * 16; idx += 256) {
        int e = idx >> 4, cc = (idx & 15) * 8;
        int n = n0 + e; if (n >= NN) n = NN - 1;
        const float* ar = g_agg + (size_t)n * 128 + cc;
        float sc = dg[e];
        unsigned hi[4], lo[4];
#pragma unroll
        for (int j = 0; j < 4; j++)
            split2(ar[2 * j] * sc, ar[2 * j + 1] * sc, hi[j], lo[j]);
        int boff = (64 + cc) * 2;
        *(uint4*)(UH + e * USTRIDE + boff) = make_uint4(hi[0], hi[1], hi[2], hi[3]);
        *(uint4*)(UL + e * USTRIDE + boff) = make_uint4(lo[0], lo[1], lo[2], lo[3]);
    }
    __syncthreads();

    const int r = wid & 3, ch = wid >> 2;
    const int g = lane >> 2, t = lane & 3;
    const int R0 = r * 16 + g, R1 = R0 + 8;

    // ---- GEMM1: h1 = gelu(U @ uw1 + ub1eff) -> BH/BL ----
    {
        float acc[8][4];
#pragma unroll
        for (int j = 0; j < 8; j++)
#pragma unroll
            for (int q = 0; q < 4; q++) acc[j][q] = 0.f;
        mma_passg<12, 16>(UH, UL, USTRIDE, g_wfu1, acc, wid, lane);
#pragma unroll
        for (int j = 0; j < 8; j++) {
            int col = ch * 64 + j * 8 + 2 * t;
            float x0 = gelu_exact(acc[j][0] + b1s[col]);
            float x1 = gelu_exact(acc[j][1] + b1s[col + 1]);
            float x2 = gelu_exact(acc[j][2] + b1s[col]);
            float x3 = gelu_exact(acc[j][3] + b1s[col + 1]);
            unsigned hi, lo;
            split2(x0, x1, hi, lo);
            *(unsigned*)(BH + R0 * ASTRIDE + col * 2) = hi;
            *(unsigned*)(BL + R0 * ASTRIDE + col * 2) = lo;
            split2(x2, x3, hi, lo);
            *(unsigned*)(BH + R1 * ASTRIDE + col * 2) = hi;
            *(unsigned*)(BL + R1 * ASTRIDE + col * 2) = lo;
        }
        __syncthreads();
    }

    // ---- GEMM2: h2 = gelu(h1 @ uw2 + ub2) -> UH/UL (cols 0..127) ----
    {
        float acc[8][4];
#pragma unroll
        for (int j = 0; j < 8; j++)
#pragma unroll
            for (int q = 0; q < 4; q++) acc[j][q] = 0.f;
        mma_passg<8, 16>(BH, BL, ASTRIDE, g_wfu2, acc, wid, lane);
        __syncthreads();
#pragma unroll
        for (int j = 0; j < 8; j++) {
            int col = ch * 64 + j * 8 + 2 * t;
            float x0 = gelu_exact(acc[j][0] + b2s[col]);
            float x1 = gelu_exact(acc[j][1] + b2s[col + 1]);
            float x2 = gelu_exact(acc[j][2] + b2s[col]);
            float x3 = gelu_exact(acc[j][3] + b2s[col + 1]);
            unsigned hi, lo;
            split2(x0, x1, hi, lo);
            *(unsigned*)(UH + R0 * USTRIDE + col * 2) = hi;
            *(unsigned*)(UL + R0 * USTRIDE + col * 2) = lo;
            split2(x2, x3, hi, lo);
            *(unsigned*)(UH + R1 * USTRIDE + col * 2) = hi;
            *(unsigned*)(UL + R1 * USTRIDE + col * 2) = lo;
        }
        __syncthreads();
    }

    // ---- GEMM3: dh = h2 @ uw3 + ub3 -> out (direct from accumulators) ----
    {
        float acc[4][4];
#pragma unroll
        for (int j = 0; j < 4; j++)
#pragma unroll
            for (int q = 0; q < 4; q++) acc[j][q] = 0.f;
        mma_passg<8, 8>(UH, UL, USTRIDE, g_wfu3, acc, wid, lane);
        float ts = g_misc[3];
        int nA = n0 + R0, nB = n0 + R1;
#pragma unroll
        for (int j = 0; j < 4; j++) {
            int col = ch * 32 + j * 8 + 2 * t;
            if (nA < NN) {
                float2 v = make_float2(ts * (acc[j][0] + b3s[col]),
                                       ts * (acc[j][1] + b3s[col + 1]));
                *(float2*)(out + nA * 64 + col) = v;
            }
            if (nB < NN) {
                float2 v = make_float2(ts * (acc[j][2] + b3s[col]),
                                       ts * (acc[j][3] + b3s[col + 1]));
                *(float2*)(out + nB * 64 + col) = v;
            }
        }
    }
}

// ---------------- launch ----------------
extern "C" void kernel_launch(void* const* d_in, const int* in_sizes, int n_in,
                              void* d_out, int out_size) {
    const float* coords   = (const float*)d_in[0];
    const float* h        = (const float*)d_in[1];
    const float* fdir     = (const float*)d_in[2];
    const int*   ei       = (const int*)d_in[3];
    const float* ln_g     = (const float*)d_in[4];
    const float* ln_b     = (const float*)d_in[5];
    const float* ew1      = (const float*)d_in[6];
    const float* eb1      = (const float*)d_in[7];
    const float* ew2      = (const float*)d_in[8];
    const float* eb2      = (const float*)d_in[9];
    const float* ew3      = (const float*)d_in[10];
    const float* eb3      = (const float*)d_in[11];
    const float* gw1      = (const float*)d_in[12];
    const float* gb1      = (const float*)d_in[13];
    const float* gw2      = (const float*)d_in[14];
    const float* gb2      = (const float*)d_in[15];
    const float* glw1     = (const float*)d_in[16];
    const float* glb1     = (const float*)d_in[17];
    const float* glw2     = (const float*)d_in[18];
    const float* glb2     = (const float*)d_in[19];
    const float* glw3     = (const float*)d_in[20];
    const float* glb3     = (const float*)d_in[21];
    const float* uw1      = (const float*)d_in[22];
    const float* ub1      = (const float*)d_in[23];
    const float* uw2      = (const float*)d_in[24];
    const float* ub2      = (const float*)d_in[25];
    const float* uw3      = (const float*)d_in[26];
    const float* ub3      = (const float*)d_in[27];
    const float* rscale   = (const float*)d_in[28];
    float* out = (float*)d_out;

    cudaFuncSetAttribute(k_edge, cudaFuncAttributeMaxDynamicSharedMemorySize,
                         SB_EDGE_BYTES);
    cudaFuncSetAttribute(k_update, cudaFuncAttributeMaxDynamicSharedMemorySize,
                         SU_BYTES);

    k_zero<<<2048, 256>>>();
    k_prep<<<32, 256>>>(ew1);
    {
        dim3 gdim(16, 3);
        k_prep_w<<<gdim, 256>>>(ew2, ew3, gw1);
    }
    k_prep_wu<<<48, 256>>>(uw1, uw2, uw3);
    k_prep_wpq<<<16, 256>>>();
    k_pq<<<NPAD / 64, 256>>>(h, ln_g, ln_b);
    k_global<<<1, 64>>>(fdir, glw1, glb1, glw2, glb2, glw3, glb3, rscale, ub1, uw1);
    k_edge<<<EE / 64, 256, SB_EDGE_BYTES>>>(ei, coords,
        ew1, eb1, eb2, eb3, gb1, gw2, gb2);
    k_update<<<(NN + 63) / 64, 256, SU_BYTES>>>(ub2, ub3, out);
}

// round 16
// speedup vs baseline: 1.4891x; 1.0454x over previous
#include <cuda_runtime.h>
#include <cuda_bf16.h>

#define NN 50000
#define EE 800000
#define CC 64
#define MCC 128
#define NPAD 50048

typedef unsigned long long ull;

// ---------------- device scratch ----------------
__device__ __align__(16) float g_feat[NN * CC];
__device__ __align__(16) float g_agg[NN * MCC];
__device__ __align__(16) float g_deg[NN];
__device__ __align__(16) float g_gsum[CC];
__device__ __align__(16) float g_gctx[CC];
__device__ __align__(16) float g_misc[4];          // u0,u1,u2, tanh(res_scale)
__device__ __align__(16) float g_W1a[CC * MCC];
__device__ __align__(16) float g_W1b[CC * MCC];
__device__ __align__(16) float g_P[NPAD * MCC];
__device__ __align__(16) float g_Q[NPAD * MCC];
__device__ __align__(16) float g_ub1eff[MCC];
// mma.sync B fragments: [mat][ (s*16 + jg)*32 + lane ] = {bh0, bh1, bl0, bl1}
__device__ __align__(16) uint4 g_wfrag[3][4096];
// update-MLP weight fragments: uw1 (K=192,N=128), uw2 (128,128), uw3 (128,64)
__device__ __align__(16) uint4 g_wfu1[6144];
__device__ __align__(16) uint4 g_wfu2[4096];
__device__ __align__(16) uint4 g_wfu3[2048];
// P/Q weight fragments: W1a, W1b (K=64, N=128) -> 2048 each
__device__ __align__(16) uint4 g_wfpq[2][2048];

// ---------------- helpers ----------------
// gelu with branchless A&S 7.1.26 erf (|abs err| <= 1.5e-7)
__device__ __forceinline__ float gelu_exact(float x) {
    float z  = x * 0.7071067811865476f;
    float az = fabsf(z);
    float t  = __fdividef(1.f, fmaf(0.3275911f, az, 1.f));
    float p  = fmaf(t, 1.061405429f, -1.453152027f);
    p = fmaf(t, p, 1.421413741f);
    p = fmaf(t, p, -0.284496736f);
    p = fmaf(t, p, 0.254829592f);
    p = p * t;
    float e    = __expf(-z * z);
    float erfa = fmaf(-p, e, 1.f);
    float erfz = copysignf(erfa, z);
    return 0.5f * x * (1.f + erfz);
}
__device__ __forceinline__ void split2(float a, float b, unsigned& hi, unsigned& lo) {
    __nv_bfloat162 h = __floats2bfloat162_rn(a, b);
    float ra = a - __bfloat162float(h.x);
    float rb = b - __bfloat162float(h.y);
    __nv_bfloat162 l = __floats2bfloat162_rn(ra, rb);
    hi = *(unsigned*)&h;
    lo = *(unsigned*)&l;
}

#define MMA_BF16(c, a0, a1, a2, a3, b0, b1) \
    asm volatile( \
        "mma.sync.aligned.m16n8k16.row.col.f32.bf16.bf16.f32 " \
        "{%0,%1,%2,%3}, {%4,%5,%6,%7}, {%8,%9}, {%0,%1,%2,%3};" \
        : "+f"((c)[0]), "+f"((c)[1]), "+f"((c)[2]), "+f"((c)[3]) \
        : "r"(a0), "r"(a1), "r"(a2), "r"(a3), "r"(b0), "r"(b1))

// ---------------- zero scratch ----------------
__global__ void k_zero() {
    int i = blockIdx.x * blockDim.x + threadIdx.x;
    int stride = gridDim.x * blockDim.x;
    float4 z = make_float4(0.f, 0.f, 0.f, 0.f);
    for (int j = i; j < NN * MCC / 4; j += stride) ((float4*)g_agg)[j] = z;
    for (int j = i; j < NN; j += stride) g_deg[j] = 0.f;
    if (i < CC) g_gsum[i] = 0.f;
}

// ---------------- weight prep ----------------
__global__ void k_prep(const float* __restrict__ ew1) {
    int i = blockIdx.x * blockDim.x + threadIdx.x;
    int stride = gridDim.x * blockDim.x;
    for (int j = i; j < CC * MCC; j += stride) {
        float wc = ew1[2 * CC * MCC + j];
        g_W1a[j] = ew1[j] + wc;
        g_W1b[j] = ew1[CC * MCC + j] - wc;
    }
}

// mma B-fragment pack for ew2, ew3, gw1 (bf16 hi/lo split)
__global__ void k_prep_w(const float* __restrict__ ew2,
                         const float* __restrict__ ew3,
                         const float* __restrict__ gw1) {
    int m = blockIdx.y;
    const float* W = (m == 0) ? ew2 : (m == 1) ? ew3 : gw1;
    int idx = blockIdx.x * blockDim.x + threadIdx.x;
    if (idx >= 4096) return;
    int lane = idx & 31;
    int jg = (idx >> 5) & 15;
    int s = idx >> 9;
    int n = jg * 8 + (lane >> 2);
    int k = s * 16 + (lane & 3) * 2;
    float w00 = W[k * 128 + n],       w01 = W[(k + 1) * 128 + n];
    float w80 = W[(k + 8) * 128 + n], w81 = W[(k + 9) * 128 + n];
    unsigned h0, l0, h8, l8;
    split2(w00, w01, h0, l0);
    split2(w80, w81, h8, l8);
    g_wfrag[m][idx] = make_uint4(h0, h8, l0, l8);
}

// fragment pack for update weights uw1/uw2/uw3
__global__ void k_prep_wu(const float* __restrict__ uw1,
                          const float* __restrict__ uw2,
                          const float* __restrict__ uw3) {
    int gidx = blockIdx.x * blockDim.x + threadIdx.x;
    if (gidx >= 12288) return;
    const float* W; uint4* dst; int idx, ldW, jgTot;
    if (gidx < 6144)       { W = uw1; dst = g_wfu1; idx = gidx;          ldW = 128; jgTot = 16; }
    else if (gidx < 10240) { W = uw2; dst = g_wfu2; idx = gidx - 6144;   ldW = 128; jgTot = 16; }
    else                   { W = uw3; dst = g_wfu3; idx = gidx - 10240;  ldW = 64;  jgTot = 8; }
    int lane = idx & 31;
    int jg = (idx >> 5) % jgTot;
    int s  = (idx >> 5) / jgTot;
    int n = jg * 8 + (lane >> 2);
    int k = s * 16 + (lane & 3) * 2;
    float w00 = W[k * ldW + n],       w01 = W[(k + 1) * ldW + n];
    float w80 = W[(k + 8) * ldW + n], w81 = W[(k + 9) * ldW + n];
    unsigned h0, l0, h8, l8;
    split2(w00, w01, h0, l0);
    split2(w80, w81, h8, l8);
    dst[idx] = make_uint4(h0, h8, l0, l8);
}

// fragment pack for P/Q weights (device-resident g_W1a/g_W1b, K=64, N=128)
__global__ void k_prep_wpq() {
    int gidx = blockIdx.x * blockDim.x + threadIdx.x;
    if (gidx >= 4096) return;
    int m = gidx >> 11;
    int idx = gidx & 2047;
    const float* W = m ? g_W1b : g_W1a;
    int lane = idx & 31;
    int jg = (idx >> 5) & 15;
    int s = idx >> 9;                 // 0..3  (K=64)
    int n = jg * 8 + (lane >> 2);
    int k = s * 16 + (lane & 3) * 2;
    float w00 = W[k * 128 + n],       w01 = W[(k + 1) * 128 + n];
    float w80 = W[(k + 8) * 128 + n], w81 = W[(k + 9) * 128 + n];
    unsigned h0, l0, h8, l8;
    split2(w00, w01, h0, l0);
    split2(w80, w81, h8, l8);
    g_wfpq[m][idx] = make_uint4(h0, h8, l0, l8);
}

// ---------------- tiny global MLP + misc + effective update bias ----------------
__global__ void k_global(const float* __restrict__ fdir,
                         const float* glw1, const float* glb1,
                         const float* glw2, const float* glb2,
                         const float* glw3, const float* glb3,
                         const float* res_scale,
                         const float* ub1, const float* uw1) {
    __shared__ float a0[CC], a1[CC], a2[CC];
    int t = threadIdx.x;
    if (t < CC) a0[t] = g_gsum[t] * (1.f / (float)NN);
    __syncthreads();
    if (t < CC) {
        float acc = glb1[t];
        for (int k = 0; k < CC; k++) acc += a0[k] * glw1[k * CC + t];
        a1[t] = gelu_exact(acc);
    }
    __syncthreads();
    if (t < CC) {
        float acc = glb2[t];
        for (int k = 0; k < CC; k++) acc += a1[k] * glw2[k * CC + t];
        a2[t] = gelu_exact(acc);
    }
    __syncthreads();
    if (t < CC) {
        float acc = glb3[t];
        for (int k = 0; k < CC; k++) acc += a2[k] * glw3[k * CC + t];
        g_gctx[t] = acc;
        a0[t] = acc;
    }
    __syncthreads();
    for (int c = t; c < MCC; c += CC) {
        float acc = ub1[c];
        for (int k = 0; k < CC; k++) acc += a0[k] * uw1[(192 + k) * MCC + c];
        g_ub1eff[c] = acc;
    }
    if (t == 0) {
        float u0 = fdir[0], u1 = fdir[1], u2 = fdir[2];
        float inv = 1.f / (sqrtf(u0 * u0 + u1 * u1 + u2 * u2) + 1e-8f);
        g_misc[0] = u0 * inv; g_misc[1] = u1 * inv; g_misc[2] = u2 * inv;
        g_misc[3] = tanhf(res_scale[0]);
    }
}

// ---------------- generic mma pass (64 rows, variable K / N) ----------------
// SS = K/16 s-steps; JGT = N/8 fragment groups total (split over 2 warp-halves).
// LO = include the input-lo correction pass (Al*Wh).
template <int SS, int JGT, bool LO = true>
__device__ __forceinline__ void mma_passg(const char* Ah, const char* Al, int ast,
                                          const uint4* __restrict__ Wf,
                                          float acc[][4], int wid, int lane) {
    const int r = wid & 3, ch = wid >> 2;
    const int g = lane >> 2, t = lane & 3;
    const int ro0 = (r * 16 + g) * ast;
    const int ro1 = ro0 + 8 * ast;
    constexpr int JC = JGT / 2;
#pragma unroll
    for (int s = 0; s < SS; s++) {
        const int cb = s * 32 + 4 * t;
        unsigned ah0 = *(const unsigned*)(Ah + ro0 + cb);
        unsigned ah1 = *(const unsigned*)(Ah + ro1 + cb);
        unsigned ah2 = *(const unsigned*)(Ah + ro0 + cb + 16);
        unsigned ah3 = *(const unsigned*)(Ah + ro1 + cb + 16);
        unsigned al0 = 0, al1 = 0, al2 = 0, al3 = 0;
        if (LO) {
            al0 = *(const unsigned*)(Al + ro0 + cb);
            al1 = *(const unsigned*)(Al + ro1 + cb);
            al2 = *(const unsigned*)(Al + ro0 + cb + 16);
            al3 = *(const unsigned*)(Al + ro1 + cb + 16);
        }
        const uint4* wp = Wf + (s * JGT + ch * JC) * 32 + lane;
#pragma unroll
        for (int j = 0; j < JC; j++) {
            uint4 w = __ldg(wp + j * 32);
            MMA_BF16(acc[j], ah0, ah1, ah2, ah3, w.x, w.y);
            MMA_BF16(acc[j], ah0, ah1, ah2, ah3, w.z, w.w);
            if (LO) MMA_BF16(acc[j], al0, al1, al2, al3, w.x, w.y);
        }
    }
}

// ---------------- fused layernorm + P/Q node GEMMs ----------------
#define PSTRIDE 144

__global__ void __launch_bounds__(256) k_pq(const float* __restrict__ h,
                                            const float* __restrict__ lng,
                                            const float* __restrict__ lnb) {
    __shared__ __align__(16) char PH[64 * PSTRIDE];
    __shared__ __align__(16) char PL[64 * PSTRIDE];
    __shared__ float cs[CC];
    const int tid = threadIdx.x;
    const int wid = tid >> 5, lane = tid & 31;
    const int n0 = blockIdx.x * 64;

    if (tid < CC) cs[tid] = 0.f;
    __syncthreads();

    const float lg0 = lng[2 * lane], lg1 = lng[2 * lane + 1];
    const float lb0 = lnb[2 * lane], lb1 = lnb[2 * lane + 1];
    float ca = 0.f, cb = 0.f;

#pragma unroll
    for (int i = 0; i < 4; i++) {
        int e = wid * 8 + i * 2;
        int nA = n0 + e, nB = nA + 1;
        int rA = (nA < NN) ? nA : NN - 1;
        int rB = (nB < NN) ? nB : NN - 1;
        float2 va = ((const float2*)h)[rA * 32 + lane];
        float2 vb = ((const float2*)h)[rB * 32 + lane];
        float sa = va.x + va.y, qa = va.x * va.x + va.y * va.y;
        float sb = vb.x + vb.y, qb = vb.x * vb.x + vb.y * vb.y;
#pragma unroll
        for (int o = 16; o; o >>= 1) {
            sa += __shfl_xor_sync(~0u, sa, o);
            qa += __shfl_xor_sync(~0u, qa, o);
            sb += __shfl_xor_sync(~0u, sb, o);
            qb += __shfl_xor_sync(~0u, qb, o);
        }
        float muA = sa * (1.f / 64.f);
        float rsA = rsqrtf(qa * (1.f / 64.f) - muA * muA + 1e-5f);
        float muB = sb * (1.f / 64.f);
        float rsB = rsqrtf(qb * (1.f / 64.f) - muB * muB + 1e-5f);
        float f0a = (va.x - muA) * rsA * lg0 + lb0;
        float f1a = (va.y - muA) * rsA * lg1 + lb1;
        float f0b = (vb.x - muB) * rsB * lg0 + lb0;
        float f1b = (vb.y - muB) * rsB * lg1 + lb1;
        ((float2*)g_feat)[rA * 32 + lane] = make_float2(f0a, f1a);
        ((float2*)g_feat)[rB * 32 + lane] = make_float2(f0b, f1b);
        if (nA < NN) { ca += f0a; cb += f1a; }
        if (nB < NN) { ca += f0b; cb += f1b; }
        unsigned hi, lo;
        split2(f0a, f1a, hi, lo);
        *(unsigned*)(PH + e * PSTRIDE + lane * 4) = hi;
        *(unsigned*)(PL + e * PSTRIDE + lane * 4) = lo;
        split2(f0b, f1b, hi, lo);
        *(unsigned*)(PH + (e + 1) * PSTRIDE + lane * 4) = hi;
        *(unsigned*)(PL + (e + 1) * PSTRIDE + lane * 4) = lo;
    }
    atomicAdd(&cs[2 * lane], ca);
    atomicAdd(&cs[2 * lane + 1], cb);
    __syncthreads();
    if (tid < CC) atomicAdd(&g_gsum[tid], cs[tid]);

    const int r = wid & 3, ch = wid >> 2;
    const int g = lane >> 2, t = lane & 3;
    const int R0 = r * 16 + g, R1 = R0 + 8;
    const int nA = n0 + R0, nB = n0 + R1;   // < NPAD always

    // P = feat @ W1a
    {
        float acc[8][4];
#pragma unroll
        for (int j = 0; j < 8; j++)
#pragma unroll
            for (int q = 0; q < 4; q++) acc[j][q] = 0.f;
        mma_passg<4, 16>(PH, PL, PSTRIDE, g_wfpq[0], acc, wid, lane);
#pragma unroll
        for (int j = 0; j < 8; j++) {
            int col = ch * 64 + j * 8 + 2 * t;
            *(float2*)(g_P + (size_t)nA * MCC + col) = make_float2(acc[j][0], acc[j][1]);
            *(float2*)(g_P + (size_t)nB * MCC + col) = make_float2(acc[j][2], acc[j][3]);
        }
    }
    // Q = feat @ W1b
    {
        float acc[8][4];
#pragma unroll
        for (int j = 0; j < 8; j++)
#pragma unroll
            for (int q = 0; q < 4; q++) acc[j][q] = 0.f;
        mma_passg<4, 16>(PH, PL, PSTRIDE, g_wfpq[1], acc, wid, lane);
#pragma unroll
        for (int j = 0; j < 8; j++) {
            int col = ch * 64 + j * 8 + 2 * t;
            *(float2*)(g_Q + (size_t)nA * MCC + col) = make_float2(acc[j][0], acc[j][1]);
            *(float2*)(g_Q + (size_t)nB * MCC + col) = make_float2(acc[j][2], acc[j][3]);
        }
    }
}

// ---------------- edge kernel: mma.sync bf16-split, 64-edge tiles ----------------
#define ASTRIDE 272
#define SB_AH   0
#define SB_AL   17408
#define SB_GEO  34816
#define SB_GP   35840
#define SB_GATE 36352
#define SB_EB2  36608
#define SB_EB3  37120
#define SB_GB1  37632
#define SB_GW2  38144
#define SB_EB1  38656
#define SB_WD   39168
#define SB_RS   41216
#define SB_CS   41472
#define SB_EDGE_BYTES 41728

__global__ void __launch_bounds__(256, 3) k_edge(
    const int* __restrict__ ei, const float* __restrict__ coords,
    const float* __restrict__ ew1, const float* __restrict__ eb1,
    const float* __restrict__ eb2, const float* __restrict__ eb3,
    const float* __restrict__ gb1, const float* __restrict__ gw2,
    const float* __restrict__ gb2) {
    extern __shared__ char sm[];
    char* Ah    = sm + SB_AH;
    char* Al    = sm + SB_AL;
    float* geo  = (float*)(sm + SB_GEO);
    float* gp   = (float*)(sm + SB_GP);
    float* gateS = (float*)(sm + SB_GATE);
    float* eb2s = (float*)(sm + SB_EB2);
    float* eb3s = (float*)(sm + SB_EB3);
    float* gb1s = (float*)(sm + SB_GB1);
    float* gw2s = (float*)(sm + SB_GW2);
    float* eb1s = (float*)(sm + SB_EB1);
    float* Wd   = (float*)(sm + SB_WD);
    int* rs = (int*)(sm + SB_RS);
    int* cs = (int*)(sm + SB_CS);

    const int tid = threadIdx.x;
    const int wid = tid >> 5, lane = tid & 31;
    const int e0 = blockIdx.x * 64;

    if (tid < 64) {
        rs[tid] = ei[e0 + tid];
        cs[tid] = ei[EE + e0 + tid];
    }
    if (tid < 128) {
        eb2s[tid] = eb2[tid];
        eb3s[tid] = eb3[tid];
        gb1s[tid] = gb1[tid];
        gw2s[tid] = gw2[tid];
        eb1s[tid] = eb1[tid];
    }
    for (int i = tid; i < 4 * 128; i += 256) Wd[i] = ew1[192 * 128 + i];
    __syncthreads();

    if (tid < 64) {
        int e = tid, r = rs[e], c = cs[e];
        float xi0 = coords[r * 3], xi1 = coords[r * 3 + 1], xi2 = coords[r * 3 + 2];
        float xj0 = coords[c * 3], xj1 = coords[c * 3 + 1], xj2 = coords[c * 3 + 2];
        float r0 = xi0 - xj0, r1 = xi1 - xj1, r2 = xi2 - xj2;
        float u0 = g_misc[0], u1 = g_misc[1], u2 = g_misc[2];
        geo[e * 4 + 0] = r0 * r0 + r1 * r1 + r2 * r2;
        geo[e * 4 + 1] = xi0 * u0 + xi1 * u1 + xi2 * u2;
        geo[e * 4 + 2] = xj0 * u0 + xj1 * u1 + xj2 * u2;
        geo[e * 4 + 3] = r0 * u0 + r1 * u1 + r2 * u2;
    }
    __syncthreads();

    // ---- build H1 = gelu(P[row] + Q[col] + geo@Wd + eb1) -> Ah/Al ----
    for (int idx = tid; idx < 64 * 16; idx += 256) {
        int e = idx >> 4, c0 = (idx & 15) * 8;
        const float* Pr = g_P + rs[e] * MCC + c0;
        const float* Qr = g_Q + cs[e] * MCC + c0;
        float4 p0 = *(const float4*)Pr, p1 = *(const float4*)(Pr + 4);
        float4 q0 = *(const float4*)Qr, q1 = *(const float4*)(Qr + 4);
        float ge0 = geo[e * 4], ge1 = geo[e * 4 + 1], ge2 = geo[e * 4 + 2], ge3 = geo[e * 4 + 3];
        float h[8];
#pragma unroll
        for (int j = 0; j < 8; j++) {
            int c = c0 + j;
            float pq = (j < 4) ? ((const float*)&p0)[j] + ((const float*)&q0)[j]
                               : ((const float*)&p1)[j - 4] + ((const float*)&q1)[j - 4];
            float v = pq + ge0 * Wd[c] + ge1 * Wd[128 + c] + ge2 * Wd[256 + c]
                    + ge3 * Wd[384 + c] + eb1s[c];
            h[j] = gelu_exact(v);
        }
        unsigned hi[4], lo[4];
#pragma unroll
        for (int j = 0; j < 4; j++) split2(h[2 * j], h[2 * j + 1], hi[j], lo[j]);
        *(uint4*)(Ah + e * ASTRIDE + c0 * 2) = make_uint4(hi[0], hi[1], hi[2], hi[3]);
        *(uint4*)(Al + e * ASTRIDE + c0 * 2) = make_uint4(lo[0], lo[1], lo[2], lo[3]);
    }
    __syncthreads();

    const int r = wid & 3, ch = wid >> 2;
    const int g = lane >> 2, t = lane & 3;
    const int R0 = r * 16 + g, R1 = R0 + 8;

    // ---- GEMM1: H2 = gelu(H1 @ ew2 + eb2) ----
    {
        float acc[8][4];
#pragma unroll
        for (int j = 0; j < 8; j++)
#pragma unroll
            for (int q = 0; q < 4; q++) acc[j][q] = 0.f;
        mma_passg<8, 16>(Ah, Al, ASTRIDE, g_wfrag[0], acc, wid, lane);
        __syncthreads();
#pragma unroll
        for (int j = 0; j < 8; j++) {
            int col = ch * 64 + j * 8 + 2 * t;
            float x0 = gelu_exact(acc[j][0] + eb2s[col]);
            float x1 = gelu_exact(acc[j][1] + eb2s[col + 1]);
            float x2 = gelu_exact(acc[j][2] + eb2s[col]);
            float x3 = gelu_exact(acc[j][3] + eb2s[col + 1]);
            unsigned hi, lo;
            split2(x0, x1, hi, lo);
            *(unsigned*)(Ah + R0 * ASTRIDE + col * 2) = hi;
            *(unsigned*)(Al + R0 * ASTRIDE + col * 2) = lo;
            split2(x2, x3, hi, lo);
            *(unsigned*)(Ah + R1 * ASTRIDE + col * 2) = hi;
            *(unsigned*)(Al + R1 * ASTRIDE + col * 2) = lo;
        }
        __syncthreads();
    }

    // ---- GEMM2: hidden = H2 @ ew3 + eb3 -> split to Ah/Al ----
    {
        float acc[8][4];
#pragma unroll
        for (int j = 0; j < 8; j++)
#pragma unroll
            for (int q = 0; q < 4; q++) acc[j][q] = 0.f;
        mma_passg<8, 16>(Ah, Al, ASTRIDE, g_wfrag[1], acc, wid, lane);
        __syncthreads();
#pragma unroll
        for (int j = 0; j < 8; j++) {
            int col = ch * 64 + j * 8 + 2 * t;
            float x0 = acc[j][0] + eb3s[col];
            float x1 = acc[j][1] + eb3s[col + 1];
            float x2 = acc[j][2] + eb3s[col];
            float x3 = acc[j][3] + eb3s[col + 1];
            unsigned hi, lo;
            split2(x0, x1, hi, lo);
            *(unsigned*)(Ah + R0 * ASTRIDE + col * 2) = hi;
            *(unsigned*)(Al + R0 * ASTRIDE + col * 2) = lo;
            split2(x2, x3, hi, lo);
            *(unsigned*)(Ah + R1 * ASTRIDE + col * 2) = hi;
            *(unsigned*)(Al + R1 * ASTRIDE + col * 2) = lo;
        }
        __syncthreads();
    }

    // ---- GEMM3: gate (hi-only 2-pass: sigmoid tolerates input-lo truncation) ----
    {
        float acc[8][4];
#pragma unroll
        for (int j = 0; j < 8; j++)
#pragma unroll
            for (int q = 0; q < 4; q++) acc[j][q] = 0.f;
        mma_passg<8, 16, false>(Ah, Al, ASTRIDE, g_wfrag[2], acc, wid, lane);
        float p0 = 0.f, p1 = 0.f;
#pragma unroll
        for (int j = 0; j < 8; j++) {
            int col = ch * 64 + j * 8 + 2 * t;
            p0 += gw2s[col] * gelu_exact(acc[j][0] + gb1s[col])
                + gw2s[col + 1] * gelu_exact(acc[j][1] + gb1s[col + 1]);
            p1 += gw2s[col] * gelu_exact(acc[j][2] + gb1s[col])
                + gw2s[col + 1] * gelu_exact(acc[j][3] + gb1s[col + 1]);
        }
        p0 += __shfl_xor_sync(~0u, p0, 1);
        p0 += __shfl_xor_sync(~0u, p0, 2);
        p1 += __shfl_xor_sync(~0u, p1, 1);
        p1 += __shfl_xor_sync(~0u, p1, 2);
        if (t == 0) {
            gp[ch * 64 + R0] = p0;
            gp[ch * 64 + R1] = p1;
        }
        __syncthreads();
        if (tid < 64) {
            float a = gp[tid] + gp[64 + tid] + gb2[0];
            gateS[tid] = __fdividef(1.f, 1.f + __expf(-a));
        }
        __syncthreads();
    }

    // ---- scatter msg = gate * (hi + lo), vector red.add.v4.f32 ----
    for (int idx = tid; idx < 64 * 32; idx += 256) {
        int e = idx >> 5, c = (idx & 31) * 4;
        uint2 hu = *(const uint2*)(Ah + e * ASTRIDE + c * 2);
        uint2 lu = *(const uint2*)(Al + e * ASTRIDE + c * 2);
        float2 h0 = __bfloat1622float2(*(__nv_bfloat162*)&hu.x);
        float2 h1 = __bfloat1622float2(*(__nv_bfloat162*)&hu.y);
        float2 l0 = __bfloat1622float2(*(__nv_bfloat162*)&lu.x);
        float2 l1 = __bfloat1622float2(*(__nv_bfloat162*)&lu.y);
        float gt = gateS[e];
        float v0 = gt * (h0.x + l0.x);
        float v1 = gt * (h0.y + l0.y);
        float v2 = gt * (h1.x + l1.x);
        float v3 = gt * (h1.y + l1.y);
        float* dst = g_agg + (size_t)rs[e] * MCC + c;
        asm volatile("red.global.add.v4.f32 [%0], {%1, %2, %3, %4};"
                     :: "l"(dst), "f"(v0), "f"(v1), "f"(v2), "f"(v3) : "memory");
    }
    if (tid < 64) atomicAdd(&g_deg[rs[tid]], 1.f);
}

// ---------------- node update kernel: mma.sync bf16-split ----------------
// input K=192 rows stride 400B; intermediate K=128 stride 272B
#define USTRIDE 400
#define SU_UH   0
#define SU_UL   25600
#define SU_BH   51200
#define SU_BL   68608
#define SU_B1   86016
#define SU_B2   86528
#define SU_B3   87040
#define SU_DG   87296
#define SU_BYTES 87552

__global__ void __launch_bounds__(256, 2) k_update(
    const float* __restrict__ ub2, const float* __restrict__ ub3,
    float* __restrict__ out) {
    extern __shared__ char smu[];
    char* UH = smu + SU_UH;
    char* UL = smu + SU_UL;
    char* BH = smu + SU_BH;
    char* BL = smu + SU_BL;
    float* b1s = (float*)(smu + SU_B1);
    float* b2s = (float*)(smu + SU_B2);
    float* b3s = (float*)(smu + SU_B3);
    float* dg  = (float*)(smu + SU_DG);
    const int tid = threadIdx.x;
    const int wid = tid >> 5, lane = tid & 31;
    const int n0 = blockIdx.x * 64;

    if (tid < 128) { b1s[tid] = g_ub1eff[tid]; b2s[tid] = ub2[tid]; }
    if (tid < 64) {
        b3s[tid] = ub3[tid];
        int n = n0 + tid; if (n >= NN) n = NN - 1;
        float d = g_deg[n]; if (d < 1.f) d = 1.f;
        dg[tid] = 1.f / d;
    }
    __syncthreads();

    // build input: cols 0..63 feat, 64..191 agg/deg -> bf16 hi/lo
    for (int idx = tid; idx < 64 * 8; idx += 256) {
        int e = idx >> 3, c0 = (idx & 7) * 8;
        int n = n0 + e; if (n >= NN) n = NN - 1;
        const float* fr = g_feat + n * 64 + c0;
        unsigned hi[4], lo[4];
#pragma unroll
        for (int j = 0; j < 4; j++) split2(fr[2 * j], fr[2 * j + 1], hi[j], lo[j]);
        *(uint4*)(UH + e * USTRIDE + c0 * 2) = make_uint4(hi[0], hi[1], hi[2], hi[3]);
        *(uint4*)(UL + e * USTRIDE + c0 * 2) = make_uint4(lo[0], lo[1], lo[2], lo[3]);
    }
    for (int idx = tid; idx < 64 * 16; idx += 256) {
        int e = idx >> 4, cc = (idx & 15) * 8;
        int n = n0 + e; if (n >= NN) n = NN - 1;
        const float* ar = g_agg + (size_t)n * 128 + cc;
        float sc = dg[e];
        unsigned hi[4], lo[4];
#pragma unroll
        for (int j = 0; j < 4; j++)
            split2(ar[2 * j] * sc, ar[2 * j + 1] * sc, hi[j], lo[j]);
        int boff = (64 + cc) * 2;
        *(uint4*)(UH + e * USTRIDE + boff) = make_uint4(hi[0], hi[1], hi[2], hi[3]);
        *(uint4*)(UL + e * USTRIDE + boff) = make_uint4(lo[0], lo[1], lo[2], lo[3]);
    }
    __syncthreads();

    const int r = wid & 3, ch = wid >> 2;
    const int g = lane >> 2, t = lane & 3;
    const int R0 = r * 16 + g, R1 = R0 + 8;

    // ---- GEMM1: h1 = gelu(U @ uw1 + ub1eff) -> BH/BL ----
    {
        float acc[8][4];
#pragma unroll
        for (int j = 0; j < 8; j++)
#pragma unroll
            for (int q = 0; q < 4; q++) acc[j][q] = 0.f;
        mma_passg<12, 16>(UH, UL, USTRIDE, g_wfu1, acc, wid, lane);
#pragma unroll
        for (int j = 0; j < 8; j++) {
            int col = ch * 64 + j * 8 + 2 * t;
            float x0 = gelu_exact(acc[j][0] + b1s[col]);
            float x1 = gelu_exact(acc[j][1] + b1s[col + 1]);
            float x2 = gelu_exact(acc[j][2] + b1s[col]);
            float x3 = gelu_exact(acc[j][3] + b1s[col + 1]);
            unsigned hi, lo;
            split2(x0, x1, hi, lo);
            *(unsigned*)(BH + R0 * ASTRIDE + col * 2) = hi;
            *(unsigned*)(BL + R0 * ASTRIDE + col * 2) = lo;
            split2(x2, x3, hi, lo);
            *(unsigned*)(BH + R1 * ASTRIDE + col * 2) = hi;
            *(unsigned*)(BL + R1 * ASTRIDE + col * 2) = lo;
        }
        __syncthreads();
    }

    // ---- GEMM2: h2 = gelu(h1 @ uw2 + ub2) -> UH/UL (cols 0..127) ----
    {
        float acc[8][4];
#pragma unroll
        for (int j = 0; j < 8; j++)
#pragma unroll
            for (int q = 0; q < 4; q++) acc[j][q] = 0.f;
        mma_passg<8, 16>(BH, BL, ASTRIDE, g_wfu2, acc, wid, lane);
        __syncthreads();
#pragma unroll
        for (int j = 0; j < 8; j++) {
            int col = ch * 64 + j * 8 + 2 * t;
            float x0 = gelu_exact(acc[j][0] + b2s[col]);
            float x1 = gelu_exact(acc[j][1] + b2s[col + 1]);
            float x2 = gelu_exact(acc[j][2] + b2s[col]);
            float x3 = gelu_exact(acc[j][3] + b2s[col + 1]);
            unsigned hi, lo;
            split2(x0, x1, hi, lo);
            *(unsigned*)(UH + R0 * USTRIDE + col * 2) = hi;
            *(unsigned*)(UL + R0 * USTRIDE + col * 2) = lo;
            split2(x2, x3, hi, lo);
            *(unsigned*)(UH + R1 * USTRIDE + col * 2) = hi;
            *(unsigned*)(UL + R1 * USTRIDE + col * 2) = lo;
        }
        __syncthreads();
    }

    // ---- GEMM3: dh = h2 @ uw3 + ub3 -> out (direct from accumulators) ----
    {
        float acc[4][4];
#pragma unroll
        for (int j = 0; j < 4; j++)
#pragma unroll
            for (int q = 0; q < 4; q++) acc[j][q] = 0.f;
        mma_passg<8, 8>(UH, UL, USTRIDE, g_wfu3, acc, wid, lane);
        float ts = g_misc[3];
        int nA = n0 + R0, nB = n0 + R1;
#pragma unroll
        for (int j = 0; j < 4; j++) {
            int col = ch * 32 + j * 8 + 2 * t;
            if (nA < NN) {
                float2 v = make_float2(ts * (acc[j][0] + b3s[col]),
                                       ts * (acc[j][1] + b3s[col + 1]));
                *(float2*)(out + nA * 64 + col) = v;
            }
            if (nB < NN) {
                float2 v = make_float2(ts * (acc[j][2] + b3s[col]),
                                       ts * (acc[j][3] + b3s[col + 1]));
                *(float2*)(out + nB * 64 + col) = v;
            }
        }
    }
}

// ---------------- launch ----------------
extern "C" void kernel_launch(void* const* d_in, const int* in_sizes, int n_in,
                              void* d_out, int out_size) {
    const float* coords   = (const float*)d_in[0];
    const float* h        = (const float*)d_in[1];
    const float* fdir     = (const float*)d_in[2];
    const int*   ei       = (const int*)d_in[3];
    const float* ln_g     = (const float*)d_in[4];
    const float* ln_b     = (const float*)d_in[5];
    const float* ew1      = (const float*)d_in[6];
    const float* eb1      = (const float*)d_in[7];
    const float* ew2      = (const float*)d_in[8];
    const float* eb2      = (const float*)d_in[9];
    const float* ew3      = (const float*)d_in[10];
    const float* eb3      = (const float*)d_in[11];
    const float* gw1      = (const float*)d_in[12];
    const float* gb1      = (const float*)d_in[13];
    const float* gw2      = (const float*)d_in[14];
    const float* gb2      = (const float*)d_in[15];
    const float* glw1     = (const float*)d_in[16];
    const float* glb1     = (const float*)d_in[17];
    const float* glw2     = (const float*)d_in[18];
    const float* glb2     = (const float*)d_in[19];
    const float* glw3     = (const float*)d_in[20];
    const float* glb3     = (const float*)d_in[21];
    const float* uw1      = (const float*)d_in[22];
    const float* ub1      = (const float*)d_in[23];
    const float* uw2      = (const float*)d_in[24];
    const float* ub2      = (const float*)d_in[25];
    const float* uw3      = (const float*)d_in[26];
    const float* ub3      = (const float*)d_in[27];
    const float* rscale   = (const float*)d_in[28];
    float* out = (float*)d_out;

    cudaFuncSetAttribute(k_edge, cudaFuncAttributeMaxDynamicSharedMemorySize,
                         SB_EDGE_BYTES);
    cudaFuncSetAttribute(k_update, cudaFuncAttributeMaxDynamicSharedMemorySize,
                         SU_BYTES);

    k_zero<<<2048, 256>>>();
    k_prep<<<32, 256>>>(ew1);
    {
        dim3 gdim(16, 3);
        k_prep_w<<<gdim, 256>>>(ew2, ew3, gw1);
    }
    k_prep_wu<<<48, 256>>>(uw1, uw2, uw3);
    k_prep_wpq<<<16, 256>>>();
    k_pq<<<NPAD / 64, 256>>>(h, ln_g, ln_b);
    k_global<<<1, 64>>>(fdir, glw1, glb1, glw2, glb2, glw3, glb3, rscale, ub1, uw1);
    k_edge<<<EE / 64, 256, SB_EDGE_BYTES>>>(ei, coords,
        ew1, eb1, eb2, eb3, gb1, gw2, gb2);
    k_update<<<(NN + 63) / 64, 256, SU_BYTES>>>(ub2, ub3, out);
}